// round 11
// baseline (speedup 1.0000x reference)
#include <cuda_runtime.h>
#include <cuda_fp16.h>
#include <cstdint>
#include <math.h>

// Problem constants
#define B_   64
#define A_   8
#define S_   512
#define F_   256
#define T_   256
#define HID  512
#define OC3  1536
#define HEADS 4
#define C_   128

// ---------------------------------------------------------------------------
// Scratch
// ---------------------------------------------------------------------------
__device__ float  g_temb [(size_t)S_ * OC3];
__device__ __half g_q16  [(size_t)S_ * HID * T_];          // q fp16 [s][d][t]
__device__ __half g_v16  [(size_t)S_ * HEADS * C_ * T_];   // v fp16 [sb][e][t]
__device__ __half g_k16hi[(size_t)S_ * HEADS * C_ * T_];   // softmax(k) hi
__device__ __half g_k16lo[(size_t)S_ * HEADS * C_ * T_];   // softmax(k) lo
__device__ uint2  g_ctxp [(size_t)S_ * HEADS * 8192];      // ctx packed B-frags

// prepacked operands
__device__ uint4 gA_qkv[(size_t)12 * 16 * 8 * 32];         // weights hi [band128][ks][mf8][32]
__device__ uint4 gA_out[(size_t)4 * 32 * 4 * 32];          // [band64][ks][mf4][32]
__device__ uint2 gB_x  [(size_t)S_ * 16 * 32 * 2 * 32];    // [s][ks][nf32][plane][32]
__device__ uint2 gB_att[(size_t)S_ * 32 * 32 * 2 * 32];    // written by applyT

#define BX_SLICE4   ((size_t)16 * 1024)
#define BATT_SLICE4 ((size_t)32 * 1024)
#define BATT_SLICE2 ((size_t)32 * 2048)

// ---------------------------------------------------------------------------
// helpers (fp16 split)
// ---------------------------------------------------------------------------
__device__ __forceinline__ unsigned hpack(float x, float y) {
    __half2 h = __floats2half2_rn(x, y);
    return *reinterpret_cast<unsigned*>(&h);
}
__device__ __forceinline__ unsigned hpack_hh(__half a, __half b) {
    __half2 h = __halves2half2(a, b);
    return *reinterpret_cast<unsigned*>(&h);
}
__device__ __forceinline__ void hsplit(float v, float& hi, float& lo) {
    __half h = __float2half_rn(v);
    hi = __half2float(h);
    lo = v - hi;
}
__device__ __forceinline__ void hpack2(float x, float y, unsigned& hi, unsigned& lo) {
    float hx, lx, hy, ly;
    hsplit(x, hx, lx); hsplit(y, hy, ly);
    hi = hpack(hx, hy); lo = hpack(lx, ly);
}
__device__ __forceinline__ void mma_f16(float* c, const uint4& a, const uint2& b) {
    asm volatile(
        "mma.sync.aligned.m16n8k16.row.col.f32.f16.f16.f32 "
        "{%0,%1,%2,%3}, {%4,%5,%6,%7}, {%8,%9}, {%0,%1,%2,%3};\n"
        : "+f"(c[0]), "+f"(c[1]), "+f"(c[2]), "+f"(c[3])
        : "r"(a.x), "r"(a.y), "r"(a.z), "r"(a.w), "r"(b.x), "r"(b.y));
}

// cp.async
__device__ __forceinline__ void cp16(uint4* smem, const uint4* gmem) {
    unsigned sa = (unsigned)__cvta_generic_to_shared(smem);
    asm volatile("cp.async.cg.shared.global [%0], [%1], 16;\n" :: "r"(sa), "l"(gmem));
}
__device__ __forceinline__ void cp_commit() { asm volatile("cp.async.commit_group;\n" ::); }
__device__ __forceinline__ void cp_wait1()  { asm volatile("cp.async.wait_group 1;\n" ::: "memory"); }
__device__ __forceinline__ void cp_wait0()  { asm volatile("cp.async.wait_group 0;\n" ::: "memory"); }

// store a 16(row)x16(k-pairs) accumulator block as hi/lo B-frags
__device__ __forceinline__ void store_hfrag(uint2* dst, size_t cb, int nf0, int lane,
                                            const float* a0, const float* a1) {
    unsigned h00,l00,h01,l01,h10,l10,h11,l11;
    hpack2(a0[0], a0[1], h00, l00); hpack2(a1[0], a1[1], h01, l01);
    hpack2(a0[2], a0[3], h10, l10); hpack2(a1[2], a1[3], h11, l11);
    dst[cb + (size_t)(nf0 * 2 + 0) * 32 + lane] = make_uint2(h00, h01);
    dst[cb + (size_t)(nf0 * 2 + 1) * 32 + lane] = make_uint2(l00, l01);
    dst[cb + (size_t)((nf0 + 1) * 2 + 0) * 32 + lane] = make_uint2(h10, h11);
    dst[cb + (size_t)((nf0 + 1) * 2 + 1) * 32 + lane] = make_uint2(l10, l11);
}

// ---------------------------------------------------------------------------
// conv_Aq: w_qkv fp32 [1536,256] -> A-frags hi, layout [band128][ks][mf8][32]
// ---------------------------------------------------------------------------
__global__ void conv_Aq(const float* __restrict__ src) {
    int wg   = blockIdx.x * 8 + (threadIdx.x >> 5);
    int lane = threadIdx.x & 31;
    int ks    = wg & 15;
    int row16 = wg >> 4;                 // 0..95
    int band  = row16 >> 3, mf = row16 & 7;
    int g = lane >> 2, tc = (lane & 3) * 2;

    const float* p = src + (size_t)(row16 * 16 + g) * 256 + ks * 16 + tc;
    float2 p00 = *(const float2*)p;
    float2 p01 = *(const float2*)(p + 8);
    float2 p10 = *(const float2*)(p + (size_t)8 * 256);
    float2 p11 = *(const float2*)(p + (size_t)8 * 256 + 8);

    uint4 hi;
    hi.x = hpack(p00.x, p00.y);
    hi.y = hpack(p10.x, p10.y);
    hi.z = hpack(p01.x, p01.y);
    hi.w = hpack(p11.x, p11.y);
    gA_qkv[(((size_t)band * 16 + ks) * 8 + mf) * 32 + lane] = hi;
}

// ---------------------------------------------------------------------------
// conv_A (w_out): fp32 [M,K] -> A-frags hi, [band64][ks][mf4][32]
// ---------------------------------------------------------------------------
__global__ void conv_A(const float* __restrict__ src, int lda, int Ksteps,
                       uint4* __restrict__ dst) {
    int wg   = blockIdx.x * 8 + (threadIdx.x >> 5);
    int lane = threadIdx.x & 31;
    int ks    = wg % Ksteps;
    int row16 = wg / Ksteps;
    int band64 = row16 >> 2, mf4 = row16 & 3;
    int g = lane >> 2, tc = (lane & 3) * 2;

    const float* p = src + (size_t)(row16 * 16 + g) * lda + ks * 16 + tc;
    float2 p00 = *(const float2*)p;
    float2 p01 = *(const float2*)(p + 8);
    float2 p10 = *(const float2*)(p + (size_t)8 * lda);
    float2 p11 = *(const float2*)(p + (size_t)8 * lda + 8);

    uint4 hi;
    hi.x = hpack(p00.x, p00.y);
    hi.y = hpack(p10.x, p10.y);
    hi.z = hpack(p01.x, p01.y);
    hi.w = hpack(p11.x, p11.y);
    dst[(((size_t)band64 * Ksteps + ks) * 4 + mf4) * 32 + lane] = hi;
}

// ---------------------------------------------------------------------------
// conv_Bd: fp32 [K,N=256] row-major (per slice) -> B-frags hi+lo [ks][nf32][pl][32]
// ---------------------------------------------------------------------------
__global__ void conv_Bd(const float* __restrict__ srcbase, int ldb, int Ksteps,
                        size_t src_slice_stride,
                        uint2* __restrict__ dstbase, size_t dst_slice_stride) {
    int s = blockIdx.y;
    const float* src = srcbase + (size_t)s * src_slice_stride;
    uint2* dst = dstbase + (size_t)s * dst_slice_stride;

    int wg   = blockIdx.x * 8 + (threadIdx.x >> 5);
    int lane = threadIdx.x & 31;
    int nf   = wg & 15;
    int ks   = (wg >> 4) % Ksteps;
    int band = wg / (16 * Ksteps);
    int g = lane >> 2, tc = (lane & 3) * 2;

    int nfg = band * 16 + nf;
    int n = nfg * 8 + g;
    const float* p = src + (size_t)(ks * 16 + tc) * ldb + n;
    float v0 = p[0];
    float v1 = p[(size_t)ldb];
    float v2 = p[(size_t)8 * ldb];
    float v3 = p[(size_t)9 * ldb];

    unsigned h0, l0, h1, l1;
    hpack2(v0, v1, h0, l0);
    hpack2(v2, v3, h1, l1);

    size_t base = (((size_t)ks * 32 + nfg) * 2) * 32 + lane;
    dst[base]      = make_uint2(h0, h1);
    dst[base + 32] = make_uint2(l0, l1);
}

// ---------------------------------------------------------------------------
// qkv GEMM: CTA tile 128(M) x 256(N), warp tile 64x64, K=256 (16 ksteps)
// 3-stage cp.async pipeline in dynamic smem (A 4KB + B 16KB per stage).
// Epilogue per band: q (0..3) fp16, k (4..7) full-head softmax, v (8..11) fp16
// ---------------------------------------------------------------------------
#define QKV_STAGE 20480
#define QKV_SMEM  (3 * QKV_STAGE)

__global__ __launch_bounds__(256)
void k_qkv_mma() {
    extern __shared__ char dsm[];
    int band = blockIdx.x, s = blockIdx.y;
    int tid = threadIdx.x, wid = tid >> 5, lane = tid & 31;
    int wm = wid >> 2, wn = wid & 3;
    int g = lane >> 2, tc = (lane & 3) * 2;

    const uint4* Ach = gA_qkv + (size_t)band * 16 * 256;
    const uint4* Bch = ((const uint4*)gB_x) + (size_t)s * BX_SLICE4;

    auto issue = [&](int ks) {
        char* st = dsm + (ks % 3) * QKV_STAGE;
        uint4* sA = (uint4*)st;
        uint4* sB = (uint4*)(st + 4096);
        cp16(&sA[tid], Ach + (size_t)ks * 256 + tid);
        const uint4* B = Bch + (size_t)ks * 1024;
        #pragma unroll
        for (int q = 0; q < 4; q++) cp16(&sB[tid + q * 256], B + tid + q * 256);
        cp_commit();
    };
    issue(0); issue(1);

    float acc[4][8][4] = {};
    for (int ks = 0; ks < 16; ks++) {
        if (ks + 1 < 16) cp_wait1(); else cp_wait0();
        __syncthreads();
        if (ks + 2 < 16) issue(ks + 2);
        char* st = dsm + (ks % 3) * QKV_STAGE;
        const uint4* sa  = (const uint4*)st;
        const uint2* sbp = (const uint2*)(st + 4096);
        uint4 a[4];
        #pragma unroll
        for (int i = 0; i < 4; i++) a[i] = sa[(wm * 4 + i) * 32 + lane];
        #pragma unroll
        for (int j = 0; j < 8; j++) {
            int nf = wn * 8 + j;
            uint2 bh = sbp[(nf * 2 + 0) * 32 + lane];
            uint2 bl = sbp[(nf * 2 + 1) * 32 + lane];
            #pragma unroll
            for (int i = 0; i < 4; i++) {
                mma_f16(acc[i][j], a[i], bh);
                mma_f16(acc[i][j], a[i], bl);
            }
        }
    }

    // temb add: rows d = band*128 + wm*64 + i*16 + hh*8 + g
    const float* te = g_temb + (size_t)s * OC3 + band * 128;
    float tv[4][2];
    #pragma unroll
    for (int i = 0; i < 4; i++) {
        tv[i][0] = te[wm * 64 + i * 16 + g];
        tv[i][1] = te[wm * 64 + i * 16 + 8 + g];
    }
    #pragma unroll
    for (int i = 0; i < 4; i++)
        #pragma unroll
        for (int j = 0; j < 8; j++) {
            acc[i][j][0] += tv[i][0]; acc[i][j][1] += tv[i][0];
            acc[i][j][2] += tv[i][1]; acc[i][j][3] += tv[i][1];
        }

    if (band < 4) {
        // ---- q: fp16 plain store ----
        __half* gq = g_q16 + (size_t)s * HID * T_;
        #pragma unroll
        for (int i = 0; i < 4; i++) {
            int d = band * 128 + wm * 64 + i * 16 + g;
            #pragma unroll
            for (int j = 0; j < 8; j++) {
                int t = wn * 64 + j * 8 + tc;
                *(__half2*)(gq + (size_t)d * T_ + t) =
                    __floats2half2_rn(acc[i][j][0], acc[i][j][1]);
                *(__half2*)(gq + (size_t)(d + 8) * T_ + t) =
                    __floats2half2_rn(acc[i][j][2], acc[i][j][3]);
            }
        }
    } else if (band < 8) {
        // ---- k: full-head softmax over t, write fp16 hi/lo rows ----
        int h = band - 4;
        __syncthreads();                 // stage smem now reusable for reduction
        float* red = (float*)dsm;        // red[wn][128]

        float mx[4][2];
        #pragma unroll
        for (int i = 0; i < 4; i++) { mx[i][0] = -1e30f; mx[i][1] = -1e30f; }
        #pragma unroll
        for (int i = 0; i < 4; i++)
            #pragma unroll
            for (int j = 0; j < 8; j++) {
                mx[i][0] = fmaxf(mx[i][0], fmaxf(acc[i][j][0], acc[i][j][1]));
                mx[i][1] = fmaxf(mx[i][1], fmaxf(acc[i][j][2], acc[i][j][3]));
            }
        #pragma unroll
        for (int i = 0; i < 4; i++)
            #pragma unroll
            for (int hh = 0; hh < 2; hh++) {
                mx[i][hh] = fmaxf(mx[i][hh], __shfl_xor_sync(0xffffffffu, mx[i][hh], 1));
                mx[i][hh] = fmaxf(mx[i][hh], __shfl_xor_sync(0xffffffffu, mx[i][hh], 2));
            }
        if ((lane & 3) == 0) {
            #pragma unroll
            for (int i = 0; i < 4; i++) {
                red[wn * 128 + wm * 64 + i * 16 + g]     = mx[i][0];
                red[wn * 128 + wm * 64 + i * 16 + 8 + g] = mx[i][1];
            }
        }
        __syncthreads();
        float MX[4][2];
        #pragma unroll
        for (int i = 0; i < 4; i++)
            #pragma unroll
            for (int hh = 0; hh < 2; hh++) {
                int r = wm * 64 + i * 16 + hh * 8 + g;
                MX[i][hh] = fmaxf(fmaxf(red[r], red[128 + r]),
                                  fmaxf(red[256 + r], red[384 + r]));
            }
        __syncthreads();
        float sm[4][2] = {};
        #pragma unroll
        for (int i = 0; i < 4; i++)
            #pragma unroll
            for (int j = 0; j < 8; j++) {
                acc[i][j][0] = __expf(acc[i][j][0] - MX[i][0]);
                acc[i][j][1] = __expf(acc[i][j][1] - MX[i][0]);
                acc[i][j][2] = __expf(acc[i][j][2] - MX[i][1]);
                acc[i][j][3] = __expf(acc[i][j][3] - MX[i][1]);
                sm[i][0] += acc[i][j][0] + acc[i][j][1];
                sm[i][1] += acc[i][j][2] + acc[i][j][3];
            }
        #pragma unroll
        for (int i = 0; i < 4; i++)
            #pragma unroll
            for (int hh = 0; hh < 2; hh++) {
                sm[i][hh] += __shfl_xor_sync(0xffffffffu, sm[i][hh], 1);
                sm[i][hh] += __shfl_xor_sync(0xffffffffu, sm[i][hh], 2);
            }
        if ((lane & 3) == 0) {
            #pragma unroll
            for (int i = 0; i < 4; i++) {
                red[wn * 128 + wm * 64 + i * 16 + g]     = sm[i][0];
                red[wn * 128 + wm * 64 + i * 16 + 8 + g] = sm[i][1];
            }
        }
        __syncthreads();
        float INV[4][2];
        #pragma unroll
        for (int i = 0; i < 4; i++)
            #pragma unroll
            for (int hh = 0; hh < 2; hh++) {
                int r = wm * 64 + i * 16 + hh * 8 + g;
                INV[i][hh] = 1.f / (red[r] + red[128 + r] + red[256 + r] + red[384 + r]);
            }
        __half* khi = g_k16hi + (size_t)(s * HEADS + h) * C_ * T_;
        __half* klo = g_k16lo + (size_t)(s * HEADS + h) * C_ * T_;
        #pragma unroll
        for (int i = 0; i < 4; i++) {
            int d0 = wm * 64 + i * 16 + g;
            #pragma unroll
            for (int j = 0; j < 8; j++) {
                int t = wn * 64 + j * 8 + tc;
                float e0 = acc[i][j][0] * INV[i][0];
                float e1 = acc[i][j][1] * INV[i][0];
                float e2 = acc[i][j][2] * INV[i][1];
                float e3 = acc[i][j][3] * INV[i][1];
                float h0, l0, h1, l1, h2, l2, h3, l3;
                hsplit(e0, h0, l0); hsplit(e1, h1, l1);
                hsplit(e2, h2, l2); hsplit(e3, h3, l3);
                *(unsigned*)(khi + (size_t)d0 * T_ + t)       = hpack(h0, h1);
                *(unsigned*)(klo + (size_t)d0 * T_ + t)       = hpack(l0, l1);
                *(unsigned*)(khi + (size_t)(d0 + 8) * T_ + t) = hpack(h2, h3);
                *(unsigned*)(klo + (size_t)(d0 + 8) * T_ + t) = hpack(l2, l3);
            }
        }
    } else {
        // ---- v: fp16 plain store ----
        int h = band - 8;
        __half* gv = g_v16 + (size_t)(s * HEADS + h) * C_ * T_;
        #pragma unroll
        for (int i = 0; i < 4; i++) {
            int e = wm * 64 + i * 16 + g;
            #pragma unroll
            for (int j = 0; j < 8; j++) {
                int t = wn * 64 + j * 8 + tc;
                *(__half2*)(gv + (size_t)e * T_ + t) =
                    __floats2half2_rn(acc[i][j][0], acc[i][j][1]);
                *(__half2*)(gv + (size_t)(e + 8) * T_ + t) =
                    __floats2half2_rn(acc[i][j][2], acc[i][j][3]);
            }
        }
    }
}

// ---------------------------------------------------------------------------
// 64(M)x256(N) CTA-tile GEMM core (prepacked A hi + B hi/lo), 3-stage cp.async
// (used by out GEMM)
// ---------------------------------------------------------------------------
__device__ __forceinline__ void gemm64x256(const uint4* __restrict__ Ach,
                                           const uint4* __restrict__ Bch,
                                           int Ksteps, float acc[2][8][4]) {
    __shared__ uint4 sA[3][128];
    __shared__ uint4 sB[3][1024];
    int tid = threadIdx.x, wid = tid >> 5, lane = tid & 31;
    int wm = wid >> 2, wn = wid & 3;

    auto issue = [&](int ks) {
        int st = ks % 3;
        const uint4* A = Ach + (size_t)ks * 128;
        const uint4* B = Bch + (size_t)ks * 1024;
        if (tid < 128) cp16(&sA[st][tid], A + tid);
        #pragma unroll
        for (int q = 0; q < 4; q++) cp16(&sB[st][tid + q * 256], B + tid + q * 256);
        cp_commit();
    };
    issue(0);
    issue(1);

    for (int ks = 0; ks < Ksteps; ks++) {
        if (ks + 1 < Ksteps) cp_wait1(); else cp_wait0();
        __syncthreads();
        if (ks + 2 < Ksteps) issue(ks + 2);
        const uint4* sa  = &sA[ks % 3][0];
        const uint2* sbp = (const uint2*)&sB[ks % 3][0];
        uint4 a0 = sa[(wm * 2 + 0) * 32 + lane];
        uint4 a1 = sa[(wm * 2 + 1) * 32 + lane];
        #pragma unroll
        for (int j = 0; j < 8; j++) {
            int nf = wn * 8 + j;
            uint2 bh = sbp[(nf * 2 + 0) * 32 + lane];
            uint2 bl = sbp[(nf * 2 + 1) * 32 + lane];
            mma_f16(acc[0][j], a0, bh); mma_f16(acc[0][j], a0, bl);
            mma_f16(acc[1][j], a1, bh); mma_f16(acc[1][j], a1, bl);
        }
    }
}

// ---------------------------------------------------------------------------
// frag mma (128x128 core): A hi-only, B hi+lo
// ---------------------------------------------------------------------------
__device__ __forceinline__ void frag_mma2(const uint4* sa, const uint2* sbp,
                                          int wm, int wn, int lane, float acc[4][4][4]) {
    uint4 a[4]; uint2 b[4][2];
    #pragma unroll
    for (int i = 0; i < 4; i++) a[i] = sa[(wm * 4 + i) * 32 + lane];
    #pragma unroll
    for (int j = 0; j < 4; j++) {
        int nf = wn * 4 + j;
        b[j][0] = sbp[(nf * 2 + 0) * 32 + lane];
        b[j][1] = sbp[(nf * 2 + 1) * 32 + lane];
    }
    #pragma unroll
    for (int i = 0; i < 4; i++)
        #pragma unroll
        for (int j = 0; j < 4; j++) {
            mma_f16(acc[i][j], a[i], b[j][0]);
            mma_f16(acc[i][j], a[i], b[j][1]);
        }
}

// ---------------------------------------------------------------------------
// ctx: ctxT[e][d] = sum_t v[e,t]*softmax(k)[d,t]  — staged from fp16, mma.sync
// ---------------------------------------------------------------------------
__global__ __launch_bounds__(256, 2)
void k_ctx_mma() {
    __shared__ uint4 sA[2][256];
    __shared__ uint4 sB[2][512];
    int sb = blockIdx.x;
    int tid = threadIdx.x, wid = tid >> 5, lane = tid & 31;
    int wm = wid >> 2, wn = wid & 3, g = lane >> 2, tc = (lane & 3) * 2;

    const __half* v0  = g_v16   + ((size_t)sb * C_ + wid * 16 + g) * T_;
    const __half* v1  = v0 + (size_t)8 * T_;
    const __half* kh0 = g_k16hi + ((size_t)sb * C_ + (wid * 2 + 0) * 8 + g) * T_;
    const __half* kh1 = g_k16hi + ((size_t)sb * C_ + (wid * 2 + 1) * 8 + g) * T_;
    const __half* kl0 = g_k16lo + ((size_t)sb * C_ + (wid * 2 + 0) * 8 + g) * T_;
    const __half* kl1 = g_k16lo + ((size_t)sb * C_ + (wid * 2 + 1) * 8 + g) * T_;

    uint4 a; uint2 bh0, bl0, bh1, bl1;
    auto gload = [&](int ks) {
        int kb = ks * 16 + tc;
        a.x = *(const unsigned*)(v0 + kb);
        a.y = *(const unsigned*)(v1 + kb);
        a.z = *(const unsigned*)(v0 + kb + 8);
        a.w = *(const unsigned*)(v1 + kb + 8);
        bh0 = make_uint2(*(const unsigned*)(kh0 + kb), *(const unsigned*)(kh0 + kb + 8));
        bl0 = make_uint2(*(const unsigned*)(kl0 + kb), *(const unsigned*)(kl0 + kb + 8));
        bh1 = make_uint2(*(const unsigned*)(kh1 + kb), *(const unsigned*)(kh1 + kb + 8));
        bl1 = make_uint2(*(const unsigned*)(kl1 + kb), *(const unsigned*)(kl1 + kb + 8));
    };
    auto sstore = [&](int buf) {
        sA[buf][wid * 32 + lane] = a;
        uint2* sbp = (uint2*)&sB[buf][0];
        sbp[((wid * 2 + 0) * 2 + 0) * 32 + lane] = bh0;
        sbp[((wid * 2 + 0) * 2 + 1) * 32 + lane] = bl0;
        sbp[((wid * 2 + 1) * 2 + 0) * 32 + lane] = bh1;
        sbp[((wid * 2 + 1) * 2 + 1) * 32 + lane] = bl1;
    };

    gload(0); sstore(0);
    __syncthreads();

    float acc[4][4][4] = {};
    for (int ks = 0; ks < 16; ks++) {
        int cur = ks & 1;
        bool more = ks + 1 < 16;
        if (more) gload(ks + 1);
        frag_mma2(&sA[cur][0], (const uint2*)&sB[cur][0], wm, wn, lane, acc);
        if (more) { sstore(cur ^ 1); __syncthreads(); }
    }

    uint2* dst = g_ctxp + (size_t)sb * 8192;
    #pragma unroll
    for (int i = 0; i < 4; i++) {
        int nf0 = wm * 8 + 2 * i;
        #pragma unroll
        for (int jp = 0; jp < 2; jp++) {
            int ks = wn * 2 + jp;
            store_hfrag(dst, (size_t)ks * 1024, nf0, lane, acc[i][2 * jp], acc[i][2 * jp + 1]);
        }
    }
}

// ---------------------------------------------------------------------------
// applyT: attT[t][e] = sum_d q[d,t]*ctxT[e,d]  -> gB_att packed B-frags
// ---------------------------------------------------------------------------
__global__ __launch_bounds__(256, 2)
void k_applyT_mma() {
    __shared__ uint4 sA[2][256];
    __shared__ uint4 sB[2][512];
    int sb = blockIdx.z, s = sb >> 2, h = sb & 3;
    int mband = blockIdx.x;
    int tid = threadIdx.x, wid = tid >> 5, lane = tid & 31;
    int wm = wid >> 2, wn = wid & 3, g = lane >> 2, tc = (lane & 3) * 2;

    const __half* q = g_q16 + (size_t)s * HID * T_ + (size_t)(h * C_) * T_;
    const uint4* Bch = (const uint4*)(g_ctxp + (size_t)sb * 8192);
    int m = mband * 128 + wid * 16 + g;

    __half av[8];
    auto gloadA = [&](int ks) {
        int k0 = ks * 16 + tc;
        av[0] = q[(size_t)(k0 + 0) * T_ + m];     av[1] = q[(size_t)(k0 + 1) * T_ + m];
        av[2] = q[(size_t)(k0 + 0) * T_ + m + 8]; av[3] = q[(size_t)(k0 + 1) * T_ + m + 8];
        av[4] = q[(size_t)(k0 + 8) * T_ + m];     av[5] = q[(size_t)(k0 + 9) * T_ + m];
        av[6] = q[(size_t)(k0 + 8) * T_ + m + 8]; av[7] = q[(size_t)(k0 + 9) * T_ + m + 8];
    };
    auto sstoreA = [&](int buf) {
        uint4 hi;
        hi.x = hpack_hh(av[0], av[1]);
        hi.y = hpack_hh(av[2], av[3]);
        hi.z = hpack_hh(av[4], av[5]);
        hi.w = hpack_hh(av[6], av[7]);
        sA[buf][wid * 32 + lane] = hi;
    };

    cp16(&sB[0][tid], Bch + tid); cp16(&sB[0][tid + 256], Bch + tid + 256); cp_commit();
    gloadA(0); sstoreA(0);
    cp_wait0();
    __syncthreads();

    float acc[4][4][4] = {};
    for (int ks = 0; ks < 8; ks++) {
        int cur = ks & 1, nxt = cur ^ 1;
        bool more = ks + 1 < 8;
        if (more) {
            const uint4* B = Bch + (size_t)(ks + 1) * 512;
            cp16(&sB[nxt][tid], B + tid); cp16(&sB[nxt][tid + 256], B + tid + 256); cp_commit();
            gloadA(ks + 1);
        }
        frag_mma2(&sA[cur][0], (const uint2*)&sB[cur][0], wm, wn, lane, acc);
        if (more) { sstoreA(nxt); cp_wait0(); __syncthreads(); }
    }

    uint2* dst = gB_att + (size_t)s * BATT_SLICE2;
    #pragma unroll
    for (int i = 0; i < 4; i++) {
        int nf0 = mband * 16 + wm * 8 + 2 * i;
        #pragma unroll
        for (int jp = 0; jp < 2; jp++) {
            int ks = h * 8 + wn * 2 + jp;
            store_hfrag(dst, (size_t)ks * 2048, nf0, lane, acc[i][2 * jp], acc[i][2 * jp + 1]);
        }
    }
}

// ---------------------------------------------------------------------------
// out GEMM: 64x256 core, Ksteps=32, bias epilogue
// ---------------------------------------------------------------------------
__global__ __launch_bounds__(256, 2)
void k_out_mma(const uint4* __restrict__ Ap, const uint4* __restrict__ Bp,
               const float* __restrict__ bias, float* __restrict__ out) {
    int s = blockIdx.z, band = blockIdx.y;
    const uint4* Ach = Ap + (size_t)band * 32 * 128;
    const uint4* Bch = Bp + (size_t)s * BATT_SLICE4;

    float acc[2][8][4] = {};
    gemm64x256(Ach, Bch, 32, acc);

    int tid = threadIdx.x, wid = tid >> 5, lane = tid & 31;
    int wm = wid >> 2, wn = wid & 3;
    int g = lane >> 2, tc = (lane & 3) * 2;
    float* Co = out + (size_t)s * 256 * T_;

    #pragma unroll
    for (int i = 0; i < 2; i++) {
        int m = band * 64 + wm * 32 + i * 16 + g;
        float b0 = bias[m], b1 = bias[m + 8];
        #pragma unroll
        for (int j = 0; j < 8; j++) {
            int n = wn * 64 + j * 8 + tc;
            *(float2*)(Co + (size_t)m * T_ + n) =
                make_float2(acc[i][j][0] + b0, acc[i][j][1] + b0);
            *(float2*)(Co + (size_t)(m + 8) * T_ + n) =
                make_float2(acc[i][j][2] + b1, acc[i][j][3] + b1);
        }
    }
}

// ---------------------------------------------------------------------------
// temb
// ---------------------------------------------------------------------------
__global__ void k_temb(const float* __restrict__ time_in,
                       const float* __restrict__ w_time,
                       const float* __restrict__ b_time) {
    int s = blockIdx.x;
    int t = threadIdx.x;
    __shared__ float m[256];
    float v = time_in[(size_t)s * 256 + t];
    float sp = (v > 20.f) ? v : log1pf(__expf(v));
    m[t] = v * tanhf(sp);
    __syncthreads();

    int warp = t >> 5, lane = t & 31;
    for (int o = warp; o < OC3; o += 8) {
        const float* w = w_time + (size_t)o * 256;
        float acc = 0.f;
        #pragma unroll 4
        for (int e = lane; e < 256; e += 32) acc += m[e] * w[e];
        #pragma unroll
        for (int off = 16; off; off >>= 1) acc += __shfl_down_sync(0xffffffffu, acc, off);
        if (lane == 0) g_temb[(size_t)s * OC3 + o] = acc + b_time[o];
    }
}

// ---------------------------------------------------------------------------
extern "C" void kernel_launch(void* const* d_in, const int* in_sizes, int n_in,
                              void* d_out, int out_size) {
    (void)in_sizes; (void)n_in; (void)out_size;
    const float* x       = (const float*)d_in[0];
    const float* time_in = (const float*)d_in[1];
    const float* w_qkv   = (const float*)d_in[2];
    const float* w_time  = (const float*)d_in[3];
    const float* b_time  = (const float*)d_in[4];
    const float* w_out   = (const float*)d_in[5];
    const float* b_out   = (const float*)d_in[6];
    float* out = (float*)d_out;

    uint4* pA_out; cudaGetSymbolAddress((void**)&pA_out, gA_out);
    uint2* pB_x;   cudaGetSymbolAddress((void**)&pB_x,   gB_x);
    uint2* pB_att; cudaGetSymbolAddress((void**)&pB_att, gB_att);

    cudaFuncSetAttribute(k_qkv_mma, cudaFuncAttributeMaxDynamicSharedMemorySize, QKV_SMEM);

    k_temb<<<S_, 256>>>(time_in, w_time, b_time);

    conv_Aq<<<192, 256>>>(w_qkv);                     // 96 row16-bands x 16 ks
    conv_A<<<64, 256>>>(w_out, HID, 32, pA_out);      // 16 row16-bands x 32 ks
    conv_Bd<<<dim3(64, S_), 256>>>(x, T_, 16, (size_t)F_ * T_, pB_x, (size_t)16 * 2048);

    k_qkv_mma<<<dim3(12, S_), 256, QKV_SMEM>>>();

    k_ctx_mma<<<S_ * HEADS, 256>>>();
    k_applyT_mma<<<dim3(2, 1, S_ * HEADS), 256>>>();

    k_out_mma<<<dim3(1, 4, S_), 256>>>(pA_out, (const uint4*)pB_att, b_out, out);
}

// round 12
// speedup vs baseline: 1.2759x; 1.2759x over previous
#include <cuda_runtime.h>
#include <cuda_fp16.h>
#include <cstdint>
#include <math.h>

// Problem constants
#define B_   64
#define A_   8
#define S_   512
#define F_   256
#define T_   256
#define HID  512
#define OC3  1536
#define HEADS 4
#define C_   128

// ---------------------------------------------------------------------------
// Scratch
// ---------------------------------------------------------------------------
__device__ float  g_temb[(size_t)S_ * OC3];
__device__ __half g_q16 [(size_t)S_ * HID * T_];                 // q fp16 [s][d][t]
__device__ uint4  g_vp  [(size_t)S_ * HEADS * 4096];             // v packed A-frags (hi)
__device__ uint2  g_kp  [(size_t)S_ * HEADS * 16384];            // softmax(k) packed B-frags hi+lo
__device__ uint2  g_ctxp[(size_t)S_ * HEADS * 8192];             // ctx packed B-frags hi+lo

// prepacked operands
__device__ uint4 gA_qkv[(size_t)24 * 16 * 4 * 32];               // weights hi, [band64][ks][mf4][32]
__device__ uint4 gA_out[(size_t)4 * 32 * 4 * 32];
__device__ uint2 gB_x  [(size_t)S_ * 16 * 32 * 2 * 32];          // [s][ks][nf32][plane][32]
__device__ uint2 gB_att[(size_t)S_ * 32 * 32 * 2 * 32];          // written by applyT

#define BX_SLICE4   ((size_t)16 * 1024)    // uint4 per slice (x frags)
#define BATT_SLICE4 ((size_t)32 * 1024)    // uint4 per slice (att frags)
#define BATT_SLICE2 ((size_t)32 * 2048)    // uint2 per slice

// ---------------------------------------------------------------------------
// helpers (fp16 split)
// ---------------------------------------------------------------------------
__device__ __forceinline__ unsigned hpack(float x, float y) {
    __half2 h = __floats2half2_rn(x, y);
    return *reinterpret_cast<unsigned*>(&h);
}
__device__ __forceinline__ void hsplit(float v, float& hi, float& lo) {
    __half h = __float2half_rn(v);
    hi = __half2float(h);
    lo = v - hi;
}
__device__ __forceinline__ void hpack2(float x, float y, unsigned& hi, unsigned& lo) {
    float hx, lx, hy, ly;
    hsplit(x, hx, lx); hsplit(y, hy, ly);
    hi = hpack(hx, hy); lo = hpack(lx, ly);
}
__device__ __forceinline__ void mma_f16(float* c, const uint4& a, const uint2& b) {
    asm volatile(
        "mma.sync.aligned.m16n8k16.row.col.f32.f16.f16.f32 "
        "{%0,%1,%2,%3}, {%4,%5,%6,%7}, {%8,%9}, {%0,%1,%2,%3};\n"
        : "+f"(c[0]), "+f"(c[1]), "+f"(c[2]), "+f"(c[3])
        : "r"(a.x), "r"(a.y), "r"(a.z), "r"(a.w), "r"(b.x), "r"(b.y));
}

// cp.async
__device__ __forceinline__ void cp16(uint4* smem, const uint4* gmem) {
    unsigned sa = (unsigned)__cvta_generic_to_shared(smem);
    asm volatile("cp.async.cg.shared.global [%0], [%1], 16;\n" :: "r"(sa), "l"(gmem));
}
__device__ __forceinline__ void cp16s(uint32_t saddr, const void* gmem) {
    asm volatile("cp.async.cg.shared.global [%0], [%1], 16;\n" :: "r"(saddr), "l"(gmem));
}
__device__ __forceinline__ void cp_commit() { asm volatile("cp.async.commit_group;\n" ::); }
__device__ __forceinline__ void cp_wait1()  { asm volatile("cp.async.wait_group 1;\n" ::: "memory"); }
__device__ __forceinline__ void cp_wait0()  { asm volatile("cp.async.wait_group 0;\n" ::: "memory"); }

__device__ __forceinline__ uint32_t smem_u32(const void* p) {
    return (uint32_t)__cvta_generic_to_shared(p);
}

// ldmatrix x4 transposed (b16): A-frag from [k][m] smem tile
__device__ __forceinline__ void ldsm4t(uint4& a, uint32_t addr) {
    asm volatile("ldmatrix.sync.aligned.m8n8.x4.trans.shared.b16 {%0,%1,%2,%3}, [%4];"
                 : "=r"(a.x), "=r"(a.y), "=r"(a.z), "=r"(a.w) : "r"(addr));
}

// 2-pass frag mma: A hi-only (4 uint4), B hi+lo (8 uint2) — 32 mma per call
__device__ __forceinline__ void frag_mma2(const uint4* sa, const uint2* sbp,
                                          int wm, int wn, int lane, float acc[4][4][4]) {
    uint4 a[4]; uint2 b[4][2];
    #pragma unroll
    for (int i = 0; i < 4; i++) a[i] = sa[(wm * 4 + i) * 32 + lane];
    #pragma unroll
    for (int j = 0; j < 4; j++) {
        int nf = wn * 4 + j;
        b[j][0] = sbp[(nf * 2 + 0) * 32 + lane];
        b[j][1] = sbp[(nf * 2 + 1) * 32 + lane];
    }
    #pragma unroll
    for (int i = 0; i < 4; i++)
        #pragma unroll
        for (int j = 0; j < 4; j++) {
            mma_f16(acc[i][j], a[i], b[j][0]);
            mma_f16(acc[i][j], a[i], b[j][1]);
        }
}

// store a 16(row)x16(k-pairs) accumulator block as hi/lo B-frags
__device__ __forceinline__ void store_hfrag(uint2* dst, size_t cb, int nf0, int lane,
                                            const float* a0, const float* a1) {
    unsigned h00,l00,h01,l01,h10,l10,h11,l11;
    hpack2(a0[0], a0[1], h00, l00); hpack2(a1[0], a1[1], h01, l01);
    hpack2(a0[2], a0[3], h10, l10); hpack2(a1[2], a1[3], h11, l11);
    dst[cb + (size_t)(nf0 * 2 + 0) * 32 + lane] = make_uint2(h00, h01);
    dst[cb + (size_t)(nf0 * 2 + 1) * 32 + lane] = make_uint2(l00, l01);
    dst[cb + (size_t)((nf0 + 1) * 2 + 0) * 32 + lane] = make_uint2(h10, h11);
    dst[cb + (size_t)((nf0 + 1) * 2 + 1) * 32 + lane] = make_uint2(l10, l11);
}

// ---------------------------------------------------------------------------
// conv_A: fp32 [M,K] row-major -> A-frags hi, layout [band64][ks][mf4][32]
// ---------------------------------------------------------------------------
__global__ void conv_A(const float* __restrict__ src, int lda, int Ksteps,
                       uint4* __restrict__ dst) {
    int wg   = blockIdx.x * 8 + (threadIdx.x >> 5);
    int lane = threadIdx.x & 31;
    int ks    = wg % Ksteps;
    int row16 = wg / Ksteps;
    int band64 = row16 >> 2, mf4 = row16 & 3;
    int g = lane >> 2, tc = (lane & 3) * 2;

    const float* p = src + (size_t)(row16 * 16 + g) * lda + ks * 16 + tc;
    float2 p00 = *(const float2*)p;
    float2 p01 = *(const float2*)(p + 8);
    float2 p10 = *(const float2*)(p + (size_t)8 * lda);
    float2 p11 = *(const float2*)(p + (size_t)8 * lda + 8);

    uint4 hi;
    hi.x = hpack(p00.x, p00.y);
    hi.y = hpack(p10.x, p10.y);
    hi.z = hpack(p01.x, p01.y);
    hi.w = hpack(p11.x, p11.y);
    dst[(((size_t)band64 * Ksteps + ks) * 4 + mf4) * 32 + lane] = hi;
}

// ---------------------------------------------------------------------------
// conv_Bd: fp32 [K,N=256] row-major (per slice) -> B-frags hi+lo
// layout [ks][nf32][plane][32]
// ---------------------------------------------------------------------------
__global__ void conv_Bd(const float* __restrict__ srcbase, int ldb, int Ksteps,
                        size_t src_slice_stride,
                        uint2* __restrict__ dstbase, size_t dst_slice_stride) {
    int s = blockIdx.y;
    const float* src = srcbase + (size_t)s * src_slice_stride;
    uint2* dst = dstbase + (size_t)s * dst_slice_stride;

    int wg   = blockIdx.x * 8 + (threadIdx.x >> 5);
    int lane = threadIdx.x & 31;
    int nf   = wg & 15;
    int ks   = (wg >> 4) % Ksteps;
    int band = wg / (16 * Ksteps);
    int g = lane >> 2, tc = (lane & 3) * 2;

    int nfg = band * 16 + nf;
    int n = nfg * 8 + g;
    const float* p = src + (size_t)(ks * 16 + tc) * ldb + n;
    float v0 = p[0];
    float v1 = p[(size_t)ldb];
    float v2 = p[(size_t)8 * ldb];
    float v3 = p[(size_t)9 * ldb];

    unsigned h0, l0, h1, l1;
    hpack2(v0, v1, h0, l0);
    hpack2(v2, v3, h1, l1);

    size_t base = (((size_t)ks * 32 + nfg) * 2) * 32 + lane;
    dst[base]      = make_uint2(h0, h1);
    dst[base + 32] = make_uint2(l0, l1);
}

// ---------------------------------------------------------------------------
// 64(M)x256(N) CTA tile GEMM core, prepacked A (hi) + B (hi/lo), 3-stage cp.async
// ---------------------------------------------------------------------------
__device__ __forceinline__ void gemm64x256(const uint4* __restrict__ Ach,
                                           const uint4* __restrict__ Bch,
                                           int Ksteps, float acc[2][8][4]) {
    __shared__ uint4 sA[3][128];
    __shared__ uint4 sB[3][1024];
    int tid = threadIdx.x, wid = tid >> 5, lane = tid & 31;
    int wm = wid >> 2, wn = wid & 3;

    auto issue = [&](int ks) {
        int st = ks % 3;
        const uint4* A = Ach + (size_t)ks * 128;
        const uint4* B = Bch + (size_t)ks * 1024;
        if (tid < 128) cp16(&sA[st][tid], A + tid);
        #pragma unroll
        for (int q = 0; q < 4; q++) cp16(&sB[st][tid + q * 256], B + tid + q * 256);
        cp_commit();
    };
    issue(0);
    issue(1);

    for (int ks = 0; ks < Ksteps; ks++) {
        if (ks + 1 < Ksteps) cp_wait1(); else cp_wait0();
        __syncthreads();
        if (ks + 2 < Ksteps) issue(ks + 2);
        const uint4* sa  = &sA[ks % 3][0];
        const uint2* sbp = (const uint2*)&sB[ks % 3][0];
        uint4 a0 = sa[(wm * 2 + 0) * 32 + lane];
        uint4 a1 = sa[(wm * 2 + 1) * 32 + lane];
        #pragma unroll
        for (int j = 0; j < 8; j++) {
            int nf = wn * 8 + j;
            uint2 bh = sbp[(nf * 2 + 0) * 32 + lane];
            uint2 bl = sbp[(nf * 2 + 1) * 32 + lane];
            mma_f16(acc[0][j], a0, bh); mma_f16(acc[0][j], a0, bl);
            mma_f16(acc[1][j], a1, bh); mma_f16(acc[1][j], a1, bl);
        }
    }
}

// ---------------------------------------------------------------------------
// qkv GEMM: 24 bands of 64 rows x full t=256. Epilogue per band type:
//   q (0..7):  +temb, write fp16 [d][t]
//   k (8..15): +temb, in-CTA softmax over t, write packed B-frags (ctx)
//   v (16..23):+temb, write packed A-frags (ctx)
// ---------------------------------------------------------------------------
__global__ __launch_bounds__(256, 2)
void k_qkv_mma(const uint4* __restrict__ Ap, const uint4* __restrict__ Bx) {
    __shared__ float red[4][64];
    int s = blockIdx.z, band = blockIdx.y;
    const uint4* Ach = Ap + (size_t)band * 16 * 128;
    const uint4* Bch = Bx + (size_t)s * BX_SLICE4;

    float acc[2][8][4] = {};
    gemm64x256(Ach, Bch, 16, acc);

    int tid = threadIdx.x, wid = tid >> 5, lane = tid & 31;
    int wm = wid >> 2, wn = wid & 3;
    int g = lane >> 2, tc = (lane & 3) * 2;

    const float* te = g_temb + (size_t)s * OC3 + band * 64;
    float tv[2][2];
    #pragma unroll
    for (int i = 0; i < 2; i++) {
        tv[i][0] = te[wm * 32 + i * 16 + g];
        tv[i][1] = te[wm * 32 + i * 16 + 8 + g];
    }
    #pragma unroll
    for (int i = 0; i < 2; i++)
        #pragma unroll
        for (int j = 0; j < 8; j++) {
            acc[i][j][0] += tv[i][0]; acc[i][j][1] += tv[i][0];
            acc[i][j][2] += tv[i][1]; acc[i][j][3] += tv[i][1];
        }

    if (band < 8) {
        // ---- q: fp16 plain store ----
        __half* gq = g_q16 + (size_t)s * HID * T_;
        #pragma unroll
        for (int i = 0; i < 2; i++) {
            int d = band * 64 + wm * 32 + i * 16 + g;
            #pragma unroll
            for (int j = 0; j < 8; j++) {
                int t = wn * 64 + j * 8 + tc;
                *(__half2*)(gq + (size_t)d * T_ + t) =
                    __floats2half2_rn(acc[i][j][0], acc[i][j][1]);
                *(__half2*)(gq + (size_t)(d + 8) * T_ + t) =
                    __floats2half2_rn(acc[i][j][2], acc[i][j][3]);
            }
        }
    } else if (band < 16) {
        // ---- k: softmax over t (full row in CTA), write ctx B-frags ----
        int kb = band - 8, h = kb >> 1, half = kb & 1;
        float mx[2][2];
        #pragma unroll
        for (int i = 0; i < 2; i++) { mx[i][0] = -1e30f; mx[i][1] = -1e30f; }
        #pragma unroll
        for (int i = 0; i < 2; i++)
            #pragma unroll
            for (int j = 0; j < 8; j++) {
                mx[i][0] = fmaxf(mx[i][0], fmaxf(acc[i][j][0], acc[i][j][1]));
                mx[i][1] = fmaxf(mx[i][1], fmaxf(acc[i][j][2], acc[i][j][3]));
            }
        #pragma unroll
        for (int i = 0; i < 2; i++)
            #pragma unroll
            for (int hh = 0; hh < 2; hh++) {
                mx[i][hh] = fmaxf(mx[i][hh], __shfl_xor_sync(0xffffffffu, mx[i][hh], 1));
                mx[i][hh] = fmaxf(mx[i][hh], __shfl_xor_sync(0xffffffffu, mx[i][hh], 2));
            }
        if ((lane & 3) == 0) {
            #pragma unroll
            for (int i = 0; i < 2; i++) {
                red[wn][wm * 32 + i * 16 + g]     = mx[i][0];
                red[wn][wm * 32 + i * 16 + 8 + g] = mx[i][1];
            }
        }
        __syncthreads();
        float MX[2][2];
        #pragma unroll
        for (int i = 0; i < 2; i++)
            #pragma unroll
            for (int hh = 0; hh < 2; hh++) {
                int r = wm * 32 + i * 16 + hh * 8 + g;
                MX[i][hh] = fmaxf(fmaxf(red[0][r], red[1][r]), fmaxf(red[2][r], red[3][r]));
            }
        __syncthreads();
        float sm[2][2] = {};
        #pragma unroll
        for (int i = 0; i < 2; i++)
            #pragma unroll
            for (int j = 0; j < 8; j++) {
                acc[i][j][0] = __expf(acc[i][j][0] - MX[i][0]);
                acc[i][j][1] = __expf(acc[i][j][1] - MX[i][0]);
                acc[i][j][2] = __expf(acc[i][j][2] - MX[i][1]);
                acc[i][j][3] = __expf(acc[i][j][3] - MX[i][1]);
                sm[i][0] += acc[i][j][0] + acc[i][j][1];
                sm[i][1] += acc[i][j][2] + acc[i][j][3];
            }
        #pragma unroll
        for (int i = 0; i < 2; i++)
            #pragma unroll
            for (int hh = 0; hh < 2; hh++) {
                sm[i][hh] += __shfl_xor_sync(0xffffffffu, sm[i][hh], 1);
                sm[i][hh] += __shfl_xor_sync(0xffffffffu, sm[i][hh], 2);
            }
        if ((lane & 3) == 0) {
            #pragma unroll
            for (int i = 0; i < 2; i++) {
                red[wn][wm * 32 + i * 16 + g]     = sm[i][0];
                red[wn][wm * 32 + i * 16 + 8 + g] = sm[i][1];
            }
        }
        __syncthreads();
        float INV[2][2];
        #pragma unroll
        for (int i = 0; i < 2; i++)
            #pragma unroll
            for (int hh = 0; hh < 2; hh++) {
                int r = wm * 32 + i * 16 + hh * 8 + g;
                INV[i][hh] = 1.f / (red[0][r] + red[1][r] + red[2][r] + red[3][r]);
            }
        // pack into ctx B-frags
        uint2* dst = g_kp + ((size_t)s * HEADS + h) * 16384;
        #pragma unroll
        for (int i = 0; i < 2; i++) {
            int nf0 = half * 8 + wm * 4 + i * 2;
            #pragma unroll
            for (int jp = 0; jp < 4; jp++) {
                int ks = wn * 4 + jp;
                float e0[4] = { acc[i][2*jp][0] * INV[i][0], acc[i][2*jp][1] * INV[i][0],
                                acc[i][2*jp][2] * INV[i][1], acc[i][2*jp][3] * INV[i][1] };
                float e1[4] = { acc[i][2*jp+1][0] * INV[i][0], acc[i][2*jp+1][1] * INV[i][0],
                                acc[i][2*jp+1][2] * INV[i][1], acc[i][2*jp+1][3] * INV[i][1] };
                store_hfrag(dst, (size_t)ks * 1024, nf0, lane, e0, e1);
            }
        }
    } else {
        // ---- v: packed A-frags for ctx ----
        int vb = band - 16, h = vb >> 1, half = vb & 1;
        uint4* dst = g_vp + ((size_t)s * HEADS + h) * 4096;
        #pragma unroll
        for (int i = 0; i < 2; i++) {
            int mf = half * 4 + wm * 2 + i;
            #pragma unroll
            for (int jp = 0; jp < 4; jp++) {
                int ks = wn * 4 + jp;
                uint4 hi;
                hi.x = hpack(acc[i][2*jp][0],   acc[i][2*jp][1]);
                hi.y = hpack(acc[i][2*jp][2],   acc[i][2*jp][3]);
                hi.z = hpack(acc[i][2*jp+1][0], acc[i][2*jp+1][1]);
                hi.w = hpack(acc[i][2*jp+1][2], acc[i][2*jp+1][3]);
                dst[(size_t)ks * 256 + mf * 32 + lane] = hi;
            }
        }
    }
}

// ---------------------------------------------------------------------------
// out GEMM: same core, Ksteps=32, epilogue bias + fp32 out
// ---------------------------------------------------------------------------
__global__ __launch_bounds__(256, 2)
void k_out_mma(const uint4* __restrict__ Ap, const uint4* __restrict__ Bp,
               const float* __restrict__ bias, float* __restrict__ out) {
    int s = blockIdx.z, band = blockIdx.y;
    const uint4* Ach = Ap + (size_t)band * 32 * 128;
    const uint4* Bch = Bp + (size_t)s * BATT_SLICE4;

    float acc[2][8][4] = {};
    gemm64x256(Ach, Bch, 32, acc);

    int tid = threadIdx.x, wid = tid >> 5, lane = tid & 31;
    int wm = wid >> 2, wn = wid & 3;
    int g = lane >> 2, tc = (lane & 3) * 2;
    float* Co = out + (size_t)s * 256 * T_;

    #pragma unroll
    for (int i = 0; i < 2; i++) {
        int m = band * 64 + wm * 32 + i * 16 + g;
        float b0 = bias[m], b1 = bias[m + 8];
        #pragma unroll
        for (int j = 0; j < 8; j++) {
            int n = wn * 64 + j * 8 + tc;
            *(float2*)(Co + (size_t)m * T_ + n) =
                make_float2(acc[i][j][0] + b0, acc[i][j][1] + b0);
            *(float2*)(Co + (size_t)(m + 8) * T_ + n) =
                make_float2(acc[i][j][2] + b1, acc[i][j][3] + b1);
        }
    }
}

// ---------------------------------------------------------------------------
// 128x128 prepacked mma core (8 warps 2x4, warp tile 64x32), 3-stage cp.async
// ---------------------------------------------------------------------------
__device__ __forceinline__ void mma_tile3(const uint4* __restrict__ Ach,
                                          const uint4* __restrict__ Bch,
                                          int Ksteps, float acc[4][4][4]) {
    __shared__ uint4 sA[3][256];
    __shared__ uint4 sB[3][512];
    int tid = threadIdx.x, wid = tid >> 5, lane = tid & 31;
    int wm = wid >> 2, wn = wid & 3;

    auto issue = [&](int ks) {
        int st = ks % 3;
        const uint4* A = Ach + (size_t)ks * 256;
        const uint4* B = Bch + (size_t)ks * 512;
        cp16(&sA[st][tid], A + tid);
        cp16(&sB[st][tid], B + tid); cp16(&sB[st][tid + 256], B + tid + 256);
        cp_commit();
    };
    issue(0);
    issue(1);

    for (int ks = 0; ks < Ksteps; ks++) {
        if (ks + 1 < Ksteps) cp_wait1(); else cp_wait0();
        __syncthreads();
        if (ks + 2 < Ksteps) issue(ks + 2);
        frag_mma2(&sA[ks % 3][0], (const uint2*)&sB[ks % 3][0], wm, wn, lane, acc);
    }
}

// ---------------------------------------------------------------------------
// ctx: ctxT[e][d] = sum_t v[e,t]*softmax(k)[d,t] — both operands prepacked
// epilogue -> g_ctxp packed B-frags
// ---------------------------------------------------------------------------
__global__ __launch_bounds__(256, 2)
void k_ctx_mma() {
    int sb = blockIdx.x;
    const uint4* Vch = g_vp + (size_t)sb * 4096;
    const uint4* Kch = (const uint4*)(g_kp + (size_t)sb * 16384);

    float acc[4][4][4] = {};
    mma_tile3(Vch, Kch, 16, acc);

    int tid = threadIdx.x, wid = tid >> 5, lane = tid & 31;
    int wm = wid >> 2, wn = wid & 3;

    uint2* dst = g_ctxp + (size_t)sb * 8192;
    #pragma unroll
    for (int i = 0; i < 4; i++) {
        int nf0 = wm * 8 + 2 * i;
        #pragma unroll
        for (int jp = 0; jp < 2; jp++) {
            int ks = wn * 2 + jp;
            store_hfrag(dst, (size_t)ks * 1024, nf0, lane, acc[i][2 * jp], acc[i][2 * jp + 1]);
        }
    }
}

// ---------------------------------------------------------------------------
// applyT: attT[t][e] = sum_d q[d,t]*ctxT[e,d]
// A = q staged via coalesced cp.async [16k][128m] tiles + swizzled ldmatrix.trans
// B = prepacked ctx frags (cp.async). Epilogue -> gB_att packed B-frags.
// ---------------------------------------------------------------------------
__global__ __launch_bounds__(256, 2)
void k_applyT_mma() {
    __shared__ uint4 sB[3][512];     // ctx frags, 8KB/stage
    __shared__ uint4 sQ[3][256];     // q tiles,   4KB/stage
    int sb = blockIdx.z, s = sb >> 2, h = sb & 3;
    int mband = blockIdx.x;
    int tid = threadIdx.x, wid = tid >> 5, lane = tid & 31;
    int wm = wid >> 2, wn = wid & 3;

    const __half* qb = g_q16 + (size_t)s * HID * T_ + (size_t)(h * C_) * T_
                       + mband * 128;
    const uint4* Bch = (const uint4*)(g_ctxp + (size_t)sb * 8192);

    int qrow = tid >> 4;          // 0..15 (k within tile)
    int qseg = tid & 15;          // 16B segment within 256B row
    uint32_t qdst_off = (uint32_t)(qrow * 256 + ((qseg ^ (qrow & 7)) << 4));

    auto issue = [&](int ks) {
        int st = ks % 3;
        const uint4* B = Bch + (size_t)ks * 512;
        cp16(&sB[st][tid], B + tid);
        cp16(&sB[st][tid + 256], B + tid + 256);
        cp16s(smem_u32(&sQ[st][0]) + qdst_off,
              qb + (size_t)(ks * 16 + qrow) * T_ + qseg * 8);
        cp_commit();
    };
    issue(0); issue(1);

    float acc[4][4][4] = {};
    for (int ks = 0; ks < 8; ks++) {
        if (ks + 1 < 8) cp_wait1(); else cp_wait0();
        __syncthreads();
        if (ks + 2 < 8) issue(ks + 2);

        uint32_t qt = smem_u32(&sQ[ks % 3][0]);
        uint4 a[4];
        #pragma unroll
        for (int i = 0; i < 4; i++) {
            int m0 = (wm * 4 + i) * 16;
            int r = (lane & 7) + ((lane & 16) ? 8 : 0);
            int c = m0 + ((lane & 8) ? 8 : 0);
            ldsm4t(a[i], qt + r * 256 + (((c >> 3) ^ (r & 7)) << 4));
        }
        const uint2* sbp = (const uint2*)&sB[ks % 3][0];
        #pragma unroll
        for (int j = 0; j < 4; j++) {
            int nf = wn * 4 + j;
            uint2 bh = sbp[(nf * 2 + 0) * 32 + lane];
            uint2 bl = sbp[(nf * 2 + 1) * 32 + lane];
            #pragma unroll
            for (int i = 0; i < 4; i++) {
                mma_f16(acc[i][j], a[i], bh);
                mma_f16(acc[i][j], a[i], bl);
            }
        }
    }

    uint2* dst = gB_att + (size_t)s * BATT_SLICE2;
    #pragma unroll
    for (int i = 0; i < 4; i++) {
        int nf0 = mband * 16 + wm * 8 + 2 * i;
        #pragma unroll
        for (int jp = 0; jp < 2; jp++) {
            int ks = h * 8 + wn * 2 + jp;
            store_hfrag(dst, (size_t)ks * 2048, nf0, lane, acc[i][2 * jp], acc[i][2 * jp + 1]);
        }
    }
}

// ---------------------------------------------------------------------------
// temb
// ---------------------------------------------------------------------------
__global__ void k_temb(const float* __restrict__ time_in,
                       const float* __restrict__ w_time,
                       const float* __restrict__ b_time) {
    int s = blockIdx.x;
    int t = threadIdx.x;
    __shared__ float m[256];
    float v = time_in[(size_t)s * 256 + t];
    float sp = (v > 20.f) ? v : log1pf(__expf(v));
    m[t] = v * tanhf(sp);
    __syncthreads();

    int warp = t >> 5, lane = t & 31;
    for (int o = warp; o < OC3; o += 8) {
        const float* w = w_time + (size_t)o * 256;
        float acc = 0.f;
        #pragma unroll 4
        for (int e = lane; e < 256; e += 32) acc += m[e] * w[e];
        #pragma unroll
        for (int off = 16; off; off >>= 1) acc += __shfl_down_sync(0xffffffffu, acc, off);
        if (lane == 0) g_temb[(size_t)s * OC3 + o] = acc + b_time[o];
    }
}

// ---------------------------------------------------------------------------
extern "C" void kernel_launch(void* const* d_in, const int* in_sizes, int n_in,
                              void* d_out, int out_size) {
    (void)in_sizes; (void)n_in; (void)out_size;
    const float* x       = (const float*)d_in[0];
    const float* time_in = (const float*)d_in[1];
    const float* w_qkv   = (const float*)d_in[2];
    const float* w_time  = (const float*)d_in[3];
    const float* b_time  = (const float*)d_in[4];
    const float* w_out   = (const float*)d_in[5];
    const float* b_out   = (const float*)d_in[6];
    float* out = (float*)d_out;

    uint4* pA_qkv; cudaGetSymbolAddress((void**)&pA_qkv, gA_qkv);
    uint4* pA_out; cudaGetSymbolAddress((void**)&pA_out, gA_out);
    uint2* pB_x;   cudaGetSymbolAddress((void**)&pB_x,   gB_x);
    uint2* pB_att; cudaGetSymbolAddress((void**)&pB_att, gB_att);

    k_temb<<<S_, 256>>>(time_in, w_time, b_time);

    conv_A<<<192, 256>>>(w_qkv, F_, 16, pA_qkv);      // 96 row16-bands x 16 ks
    conv_A<<<64, 256>>>(w_out, HID, 32, pA_out);      // 16 row16-bands x 32 ks
    conv_Bd<<<dim3(64, S_), 256>>>(x, T_, 16, (size_t)F_ * T_, pB_x, (size_t)16 * 2048);

    k_qkv_mma<<<dim3(1, 24, S_), 256>>>(pA_qkv, (const uint4*)pB_x);

    k_ctx_mma<<<S_ * HEADS, 256>>>();
    k_applyT_mma<<<dim3(2, 1, S_ * HEADS), 256>>>();

    k_out_mma<<<dim3(1, 4, S_), 256>>>(pA_out, (const uint4*)pB_att, b_out, out);
}

// round 13
// speedup vs baseline: 1.2988x; 1.0179x over previous
#include <cuda_runtime.h>
#include <cuda_fp16.h>
#include <cstdint>
#include <math.h>

// Problem constants
#define B_   64
#define A_   8
#define S_   512
#define F_   256
#define T_   256
#define HID  512
#define OC3  1536
#define HEADS 4
#define C_   128

// ---------------------------------------------------------------------------
// Scratch
// ---------------------------------------------------------------------------
__device__ float  g_temb[(size_t)S_ * OC3];
__device__ __half g_q16 [(size_t)S_ * HID * T_];                 // q fp16 [s][d][t]
__device__ uint4  g_vp  [(size_t)S_ * HEADS * 4096];             // v packed A-frags (hi)
__device__ uint2  g_kp  [(size_t)S_ * HEADS * 16384];            // softmax(k) packed B-frags hi+lo
__device__ uint2  g_ctxp[(size_t)S_ * HEADS * 8192];             // ctx packed B-frags hi+lo

// prepacked operands
__device__ uint4 gA_qkv[(size_t)24 * 16 * 4 * 32];               // weights hi, [band64][ks][mf4][32]
__device__ uint4 gA_out[(size_t)4 * 32 * 4 * 32];
__device__ uint2 gB_x  [(size_t)S_ * 16 * 32 * 2 * 32];          // [s][ks][nf32][plane][32]
__device__ uint2 gB_att[(size_t)S_ * 32 * 32 * 2 * 32];          // written by applyT

#define BX_SLICE4   ((size_t)16 * 1024)    // uint4 per slice (x frags)
#define BATT_SLICE4 ((size_t)32 * 1024)    // uint4 per slice (att frags)
#define BATT_SLICE2 ((size_t)32 * 2048)    // uint2 per slice

// ---------------------------------------------------------------------------
// helpers (fp16 split)
// ---------------------------------------------------------------------------
__device__ __forceinline__ unsigned hpack(float x, float y) {
    __half2 h = __floats2half2_rn(x, y);
    return *reinterpret_cast<unsigned*>(&h);
}
__device__ __forceinline__ void hsplit(float v, float& hi, float& lo) {
    __half h = __float2half_rn(v);
    hi = __half2float(h);
    lo = v - hi;
}
__device__ __forceinline__ void hpack2(float x, float y, unsigned& hi, unsigned& lo) {
    float hx, lx, hy, ly;
    hsplit(x, hx, lx); hsplit(y, hy, ly);
    hi = hpack(hx, hy); lo = hpack(lx, ly);
}
__device__ __forceinline__ void mma_f16(float* c, const uint4& a, const uint2& b) {
    asm volatile(
        "mma.sync.aligned.m16n8k16.row.col.f32.f16.f16.f32 "
        "{%0,%1,%2,%3}, {%4,%5,%6,%7}, {%8,%9}, {%0,%1,%2,%3};\n"
        : "+f"(c[0]), "+f"(c[1]), "+f"(c[2]), "+f"(c[3])
        : "r"(a.x), "r"(a.y), "r"(a.z), "r"(a.w), "r"(b.x), "r"(b.y));
}

// cp.async
__device__ __forceinline__ void cp16(uint4* smem, const uint4* gmem) {
    unsigned sa = (unsigned)__cvta_generic_to_shared(smem);
    asm volatile("cp.async.cg.shared.global [%0], [%1], 16;\n" :: "r"(sa), "l"(gmem));
}
__device__ __forceinline__ void cp16s(uint32_t saddr, const void* gmem) {
    asm volatile("cp.async.cg.shared.global [%0], [%1], 16;\n" :: "r"(saddr), "l"(gmem));
}
__device__ __forceinline__ void cp_commit() { asm volatile("cp.async.commit_group;\n" ::); }
__device__ __forceinline__ void cp_wait1()  { asm volatile("cp.async.wait_group 1;\n" ::: "memory"); }
__device__ __forceinline__ void cp_wait0()  { asm volatile("cp.async.wait_group 0;\n" ::: "memory"); }

__device__ __forceinline__ uint32_t smem_u32(const void* p) {
    return (uint32_t)__cvta_generic_to_shared(p);
}

// ldmatrix x4 transposed (b16): A-frag from [k][m] smem tile
__device__ __forceinline__ void ldsm4t(uint4& a, uint32_t addr) {
    asm volatile("ldmatrix.sync.aligned.m8n8.x4.trans.shared.b16 {%0,%1,%2,%3}, [%4];"
                 : "=r"(a.x), "=r"(a.y), "=r"(a.z), "=r"(a.w) : "r"(addr));
}

// 2-pass frag mma: A hi-only (4 uint4), B hi+lo (8 uint2) — 32 mma per call
__device__ __forceinline__ void frag_mma2(const uint4* sa, const uint2* sbp,
                                          int wm, int wn, int lane, float acc[4][4][4]) {
    uint4 a[4]; uint2 b[4][2];
    #pragma unroll
    for (int i = 0; i < 4; i++) a[i] = sa[(wm * 4 + i) * 32 + lane];
    #pragma unroll
    for (int j = 0; j < 4; j++) {
        int nf = wn * 4 + j;
        b[j][0] = sbp[(nf * 2 + 0) * 32 + lane];
        b[j][1] = sbp[(nf * 2 + 1) * 32 + lane];
    }
    #pragma unroll
    for (int i = 0; i < 4; i++)
        #pragma unroll
        for (int j = 0; j < 4; j++) {
            mma_f16(acc[i][j], a[i], b[j][0]);
            mma_f16(acc[i][j], a[i], b[j][1]);
        }
}

// store a 16(row)x16(k-pairs) accumulator block as hi/lo B-frags
__device__ __forceinline__ void store_hfrag(uint2* dst, size_t cb, int nf0, int lane,
                                            const float* a0, const float* a1) {
    unsigned h00,l00,h01,l01,h10,l10,h11,l11;
    hpack2(a0[0], a0[1], h00, l00); hpack2(a1[0], a1[1], h01, l01);
    hpack2(a0[2], a0[3], h10, l10); hpack2(a1[2], a1[3], h11, l11);
    dst[cb + (size_t)(nf0 * 2 + 0) * 32 + lane] = make_uint2(h00, h01);
    dst[cb + (size_t)(nf0 * 2 + 1) * 32 + lane] = make_uint2(l00, l01);
    dst[cb + (size_t)((nf0 + 1) * 2 + 0) * 32 + lane] = make_uint2(h10, h11);
    dst[cb + (size_t)((nf0 + 1) * 2 + 1) * 32 + lane] = make_uint2(l10, l11);
}

// ---------------------------------------------------------------------------
// conv_A: fp32 [M,K] row-major -> A-frags hi, layout [band64][ks][mf4][32]
// ---------------------------------------------------------------------------
__global__ void conv_A(const float* __restrict__ src, int lda, int Ksteps,
                       uint4* __restrict__ dst) {
    int wg   = blockIdx.x * 8 + (threadIdx.x >> 5);
    int lane = threadIdx.x & 31;
    int ks    = wg % Ksteps;
    int row16 = wg / Ksteps;
    int band64 = row16 >> 2, mf4 = row16 & 3;
    int g = lane >> 2, tc = (lane & 3) * 2;

    const float* p = src + (size_t)(row16 * 16 + g) * lda + ks * 16 + tc;
    float2 p00 = *(const float2*)p;
    float2 p01 = *(const float2*)(p + 8);
    float2 p10 = *(const float2*)(p + (size_t)8 * lda);
    float2 p11 = *(const float2*)(p + (size_t)8 * lda + 8);

    uint4 hi;
    hi.x = hpack(p00.x, p00.y);
    hi.y = hpack(p10.x, p10.y);
    hi.z = hpack(p01.x, p01.y);
    hi.w = hpack(p11.x, p11.y);
    dst[(((size_t)band64 * Ksteps + ks) * 4 + mf4) * 32 + lane] = hi;
}

// ---------------------------------------------------------------------------
// conv_Bd: fp32 [K,N=256] row-major (per slice) -> B-frags hi+lo
// layout [ks][nf32][plane][32]
// ---------------------------------------------------------------------------
__global__ void conv_Bd(const float* __restrict__ srcbase, int ldb, int Ksteps,
                        size_t src_slice_stride,
                        uint2* __restrict__ dstbase, size_t dst_slice_stride) {
    int s = blockIdx.y;
    const float* src = srcbase + (size_t)s * src_slice_stride;
    uint2* dst = dstbase + (size_t)s * dst_slice_stride;

    int wg   = blockIdx.x * 8 + (threadIdx.x >> 5);
    int lane = threadIdx.x & 31;
    int nf   = wg & 15;
    int ks   = (wg >> 4) % Ksteps;
    int band = wg / (16 * Ksteps);
    int g = lane >> 2, tc = (lane & 3) * 2;

    int nfg = band * 16 + nf;
    int n = nfg * 8 + g;
    const float* p = src + (size_t)(ks * 16 + tc) * ldb + n;
    float v0 = p[0];
    float v1 = p[(size_t)ldb];
    float v2 = p[(size_t)8 * ldb];
    float v3 = p[(size_t)9 * ldb];

    unsigned h0, l0, h1, l1;
    hpack2(v0, v1, h0, l0);
    hpack2(v2, v3, h1, l1);

    size_t base = (((size_t)ks * 32 + nfg) * 2) * 32 + lane;
    dst[base]      = make_uint2(h0, h1);
    dst[base + 32] = make_uint2(l0, l1);
}

// ---------------------------------------------------------------------------
// 64(M)x256(N) CTA tile GEMM core, warp tile 64x32 (each warp: all 4 A-frags,
// 4 B nf). Per lane-kstep smem: A 64B + B 64B for 32 mma. 3-stage cp.async.
// acc[4][4][4]: i = M 16-block, j = nf within warp slice.
// ---------------------------------------------------------------------------
__device__ __forceinline__ void gemm64x256(const uint4* __restrict__ Ach,
                                           const uint4* __restrict__ Bch,
                                           int Ksteps, float acc[4][4][4]) {
    __shared__ uint4 sA[3][128];
    __shared__ uint4 sB[3][1024];
    int tid = threadIdx.x, wid = tid >> 5, lane = tid & 31;

    auto issue = [&](int ks) {
        int st = ks % 3;
        const uint4* A = Ach + (size_t)ks * 128;
        const uint4* B = Bch + (size_t)ks * 1024;
        if (tid < 128) cp16(&sA[st][tid], A + tid);
        #pragma unroll
        for (int q = 0; q < 4; q++) cp16(&sB[st][tid + q * 256], B + tid + q * 256);
        cp_commit();
    };
    issue(0);
    issue(1);

    for (int ks = 0; ks < Ksteps; ks++) {
        if (ks + 1 < Ksteps) cp_wait1(); else cp_wait0();
        __syncthreads();
        if (ks + 2 < Ksteps) issue(ks + 2);
        const uint4* sa  = &sA[ks % 3][0];
        const uint2* sbp = (const uint2*)&sB[ks % 3][0];
        uint4 a[4];
        #pragma unroll
        for (int i = 0; i < 4; i++) a[i] = sa[i * 32 + lane];
        #pragma unroll
        for (int j = 0; j < 4; j++) {
            int nf = wid * 4 + j;
            uint2 bh = sbp[(nf * 2 + 0) * 32 + lane];
            uint2 bl = sbp[(nf * 2 + 1) * 32 + lane];
            #pragma unroll
            for (int i = 0; i < 4; i++) {
                mma_f16(acc[i][j], a[i], bh);
                mma_f16(acc[i][j], a[i], bl);
            }
        }
    }
}

// ---------------------------------------------------------------------------
// qkv GEMM: 24 bands of 64 rows x full t=256. Epilogue per band type:
//   q (0..7):  +temb, write fp16 [d][t]
//   k (8..15): +temb, in-CTA softmax over t, write packed B-frags (ctx)
//   v (16..23):+temb, write packed A-frags (ctx)
// Warp tile: all 64 rows x t-slice [wid*32, wid*32+32)
// ---------------------------------------------------------------------------
__global__ __launch_bounds__(256, 2)
void k_qkv_mma(const uint4* __restrict__ Ap, const uint4* __restrict__ Bx) {
    __shared__ float red[8][64];
    int s = blockIdx.z, band = blockIdx.y;
    const uint4* Ach = Ap + (size_t)band * 16 * 128;
    const uint4* Bch = Bx + (size_t)s * BX_SLICE4;

    float acc[4][4][4] = {};
    gemm64x256(Ach, Bch, 16, acc);

    int tid = threadIdx.x, wid = tid >> 5, lane = tid & 31;
    int g = lane >> 2, tc = (lane & 3) * 2;

    const float* te = g_temb + (size_t)s * OC3 + band * 64;
    float tv[4][2];
    #pragma unroll
    for (int i = 0; i < 4; i++) {
        tv[i][0] = te[i * 16 + g];
        tv[i][1] = te[i * 16 + 8 + g];
    }
    #pragma unroll
    for (int i = 0; i < 4; i++)
        #pragma unroll
        for (int j = 0; j < 4; j++) {
            acc[i][j][0] += tv[i][0]; acc[i][j][1] += tv[i][0];
            acc[i][j][2] += tv[i][1]; acc[i][j][3] += tv[i][1];
        }

    if (band < 8) {
        // ---- q: fp16 plain store ----
        __half* gq = g_q16 + (size_t)s * HID * T_;
        #pragma unroll
        for (int i = 0; i < 4; i++) {
            int d = band * 64 + i * 16 + g;
            #pragma unroll
            for (int j = 0; j < 4; j++) {
                int t = wid * 32 + j * 8 + tc;
                *(__half2*)(gq + (size_t)d * T_ + t) =
                    __floats2half2_rn(acc[i][j][0], acc[i][j][1]);
                *(__half2*)(gq + (size_t)(d + 8) * T_ + t) =
                    __floats2half2_rn(acc[i][j][2], acc[i][j][3]);
            }
        }
    } else if (band < 16) {
        // ---- k: softmax over t (full row in CTA), write ctx B-frags ----
        int kb = band - 8, h = kb >> 1, half = kb & 1;
        float mx[4][2];
        #pragma unroll
        for (int i = 0; i < 4; i++) { mx[i][0] = -1e30f; mx[i][1] = -1e30f; }
        #pragma unroll
        for (int i = 0; i < 4; i++)
            #pragma unroll
            for (int j = 0; j < 4; j++) {
                mx[i][0] = fmaxf(mx[i][0], fmaxf(acc[i][j][0], acc[i][j][1]));
                mx[i][1] = fmaxf(mx[i][1], fmaxf(acc[i][j][2], acc[i][j][3]));
            }
        #pragma unroll
        for (int i = 0; i < 4; i++)
            #pragma unroll
            for (int hh = 0; hh < 2; hh++) {
                mx[i][hh] = fmaxf(mx[i][hh], __shfl_xor_sync(0xffffffffu, mx[i][hh], 1));
                mx[i][hh] = fmaxf(mx[i][hh], __shfl_xor_sync(0xffffffffu, mx[i][hh], 2));
            }
        if ((lane & 3) == 0) {
            #pragma unroll
            for (int i = 0; i < 4; i++) {
                red[wid][i * 16 + g]     = mx[i][0];
                red[wid][i * 16 + 8 + g] = mx[i][1];
            }
        }
        __syncthreads();
        float MX[4][2];
        #pragma unroll
        for (int i = 0; i < 4; i++)
            #pragma unroll
            for (int hh = 0; hh < 2; hh++) {
                int r = i * 16 + hh * 8 + g;
                float m0 = fmaxf(fmaxf(red[0][r], red[1][r]), fmaxf(red[2][r], red[3][r]));
                float m1 = fmaxf(fmaxf(red[4][r], red[5][r]), fmaxf(red[6][r], red[7][r]));
                MX[i][hh] = fmaxf(m0, m1);
            }
        __syncthreads();
        float sm[4][2] = {};
        #pragma unroll
        for (int i = 0; i < 4; i++)
            #pragma unroll
            for (int j = 0; j < 4; j++) {
                acc[i][j][0] = __expf(acc[i][j][0] - MX[i][0]);
                acc[i][j][1] = __expf(acc[i][j][1] - MX[i][0]);
                acc[i][j][2] = __expf(acc[i][j][2] - MX[i][1]);
                acc[i][j][3] = __expf(acc[i][j][3] - MX[i][1]);
                sm[i][0] += acc[i][j][0] + acc[i][j][1];
                sm[i][1] += acc[i][j][2] + acc[i][j][3];
            }
        #pragma unroll
        for (int i = 0; i < 4; i++)
            #pragma unroll
            for (int hh = 0; hh < 2; hh++) {
                sm[i][hh] += __shfl_xor_sync(0xffffffffu, sm[i][hh], 1);
                sm[i][hh] += __shfl_xor_sync(0xffffffffu, sm[i][hh], 2);
            }
        if ((lane & 3) == 0) {
            #pragma unroll
            for (int i = 0; i < 4; i++) {
                red[wid][i * 16 + g]     = sm[i][0];
                red[wid][i * 16 + 8 + g] = sm[i][1];
            }
        }
        __syncthreads();
        float INV[4][2];
        #pragma unroll
        for (int i = 0; i < 4; i++)
            #pragma unroll
            for (int hh = 0; hh < 2; hh++) {
                int r = i * 16 + hh * 8 + g;
                INV[i][hh] = 1.f / (red[0][r] + red[1][r] + red[2][r] + red[3][r] +
                                    red[4][r] + red[5][r] + red[6][r] + red[7][r]);
            }
        // pack into ctx B-frags: nf = d-frag (this band covers nf half*8..+7),
        // ks = t-step: warp covers t [wid*32, wid*32+32) = ksteps wid*2, wid*2+1
        uint2* dst = g_kp + ((size_t)s * HEADS + h) * 16384;
        #pragma unroll
        for (int i = 0; i < 4; i++) {
            int nf0 = half * 8 + i * 2;
            #pragma unroll
            for (int jp = 0; jp < 2; jp++) {
                int ks = wid * 2 + jp;
                float e0[4] = { acc[i][2*jp][0] * INV[i][0], acc[i][2*jp][1] * INV[i][0],
                                acc[i][2*jp][2] * INV[i][1], acc[i][2*jp][3] * INV[i][1] };
                float e1[4] = { acc[i][2*jp+1][0] * INV[i][0], acc[i][2*jp+1][1] * INV[i][0],
                                acc[i][2*jp+1][2] * INV[i][1], acc[i][2*jp+1][3] * INV[i][1] };
                store_hfrag(dst, (size_t)ks * 1024, nf0, lane, e0, e1);
            }
        }
    } else {
        // ---- v: packed A-frags for ctx ----
        int vb = band - 16, h = vb >> 1, half = vb & 1;
        uint4* dst = g_vp + ((size_t)s * HEADS + h) * 4096;
        #pragma unroll
        for (int i = 0; i < 4; i++) {
            int mf = half * 4 + i;
            #pragma unroll
            for (int jp = 0; jp < 2; jp++) {
                int ks = wid * 2 + jp;
                uint4 hi;
                hi.x = hpack(acc[i][2*jp][0],   acc[i][2*jp][1]);
                hi.y = hpack(acc[i][2*jp][2],   acc[i][2*jp][3]);
                hi.z = hpack(acc[i][2*jp+1][0], acc[i][2*jp+1][1]);
                hi.w = hpack(acc[i][2*jp+1][2], acc[i][2*jp+1][3]);
                dst[(size_t)ks * 256 + mf * 32 + lane] = hi;
            }
        }
    }
}

// ---------------------------------------------------------------------------
// out GEMM: same core, Ksteps=32, epilogue bias + fp32 out
// ---------------------------------------------------------------------------
__global__ __launch_bounds__(256, 2)
void k_out_mma(const uint4* __restrict__ Ap, const uint4* __restrict__ Bp,
               const float* __restrict__ bias, float* __restrict__ out) {
    int s = blockIdx.z, band = blockIdx.y;
    const uint4* Ach = Ap + (size_t)band * 32 * 128;
    const uint4* Bch = Bp + (size_t)s * BATT_SLICE4;

    float acc[4][4][4] = {};
    gemm64x256(Ach, Bch, 32, acc);

    int tid = threadIdx.x, wid = tid >> 5, lane = tid & 31;
    int g = lane >> 2, tc = (lane & 3) * 2;
    float* Co = out + (size_t)s * 256 * T_;

    #pragma unroll
    for (int i = 0; i < 4; i++) {
        int m = band * 64 + i * 16 + g;
        float b0 = bias[m], b1 = bias[m + 8];
        #pragma unroll
        for (int j = 0; j < 4; j++) {
            int n = wid * 32 + j * 8 + tc;
            *(float2*)(Co + (size_t)m * T_ + n) =
                make_float2(acc[i][j][0] + b0, acc[i][j][1] + b0);
            *(float2*)(Co + (size_t)(m + 8) * T_ + n) =
                make_float2(acc[i][j][2] + b1, acc[i][j][3] + b1);
        }
    }
}

// ---------------------------------------------------------------------------
// 128x128 prepacked mma core (8 warps 2x4, warp tile 64x32), 3-stage cp.async
// ---------------------------------------------------------------------------
__device__ __forceinline__ void mma_tile3(const uint4* __restrict__ Ach,
                                          const uint4* __restrict__ Bch,
                                          int Ksteps, float acc[4][4][4]) {
    __shared__ uint4 sA[3][256];
    __shared__ uint4 sB[3][512];
    int tid = threadIdx.x, wid = tid >> 5, lane = tid & 31;
    int wm = wid >> 2, wn = wid & 3;

    auto issue = [&](int ks) {
        int st = ks % 3;
        const uint4* A = Ach + (size_t)ks * 256;
        const uint4* B = Bch + (size_t)ks * 512;
        cp16(&sA[st][tid], A + tid);
        cp16(&sB[st][tid], B + tid); cp16(&sB[st][tid + 256], B + tid + 256);
        cp_commit();
    };
    issue(0);
    issue(1);

    for (int ks = 0; ks < Ksteps; ks++) {
        if (ks + 1 < Ksteps) cp_wait1(); else cp_wait0();
        __syncthreads();
        if (ks + 2 < Ksteps) issue(ks + 2);
        frag_mma2(&sA[ks % 3][0], (const uint2*)&sB[ks % 3][0], wm, wn, lane, acc);
    }
}

// ---------------------------------------------------------------------------
// ctx: ctxT[e][d] = sum_t v[e,t]*softmax(k)[d,t] — both operands prepacked
// epilogue -> g_ctxp packed B-frags
// ---------------------------------------------------------------------------
__global__ __launch_bounds__(256, 2)
void k_ctx_mma() {
    int sb = blockIdx.x;
    const uint4* Vch = g_vp + (size_t)sb * 4096;
    const uint4* Kch = (const uint4*)(g_kp + (size_t)sb * 16384);

    float acc[4][4][4] = {};
    mma_tile3(Vch, Kch, 16, acc);

    int tid = threadIdx.x, wid = tid >> 5, lane = tid & 31;
    int wm = wid >> 2, wn = wid & 3;

    uint2* dst = g_ctxp + (size_t)sb * 8192;
    #pragma unroll
    for (int i = 0; i < 4; i++) {
        int nf0 = wm * 8 + 2 * i;
        #pragma unroll
        for (int jp = 0; jp < 2; jp++) {
            int ks = wn * 2 + jp;
            store_hfrag(dst, (size_t)ks * 1024, nf0, lane, acc[i][2 * jp], acc[i][2 * jp + 1]);
        }
    }
}

// ---------------------------------------------------------------------------
// applyT: attT[t][e] = sum_d q[d,t]*ctxT[e,d]
// A = q staged via coalesced cp.async [16k][128m] tiles + swizzled ldmatrix.trans
// B = prepacked ctx frags (cp.async). Epilogue -> gB_att packed B-frags.
// ---------------------------------------------------------------------------
__global__ __launch_bounds__(256, 2)
void k_applyT_mma() {
    __shared__ uint4 sB[3][512];     // ctx frags, 8KB/stage
    __shared__ uint4 sQ[3][256];     // q tiles,   4KB/stage
    int sb = blockIdx.z, s = sb >> 2, h = sb & 3;
    int mband = blockIdx.x;
    int tid = threadIdx.x, wid = tid >> 5, lane = tid & 31;
    int wm = wid >> 2, wn = wid & 3;

    const __half* qb = g_q16 + (size_t)s * HID * T_ + (size_t)(h * C_) * T_
                       + mband * 128;
    const uint4* Bch = (const uint4*)(g_ctxp + (size_t)sb * 8192);

    int qrow = tid >> 4;          // 0..15 (k within tile)
    int qseg = tid & 15;          // 16B segment within 256B row
    uint32_t qdst_off = (uint32_t)(qrow * 256 + ((qseg ^ (qrow & 7)) << 4));

    auto issue = [&](int ks) {
        int st = ks % 3;
        const uint4* B = Bch + (size_t)ks * 512;
        cp16(&sB[st][tid], B + tid);
        cp16(&sB[st][tid + 256], B + tid + 256);
        cp16s(smem_u32(&sQ[st][0]) + qdst_off,
              qb + (size_t)(ks * 16 + qrow) * T_ + qseg * 8);
        cp_commit();
    };
    issue(0); issue(1);

    float acc[4][4][4] = {};
    for (int ks = 0; ks < 8; ks++) {
        if (ks + 1 < 8) cp_wait1(); else cp_wait0();
        __syncthreads();
        if (ks + 2 < 8) issue(ks + 2);

        uint32_t qt = smem_u32(&sQ[ks % 3][0]);
        uint4 a[4];
        #pragma unroll
        for (int i = 0; i < 4; i++) {
            int m0 = (wm * 4 + i) * 16;
            int r = (lane & 7) + ((lane & 16) ? 8 : 0);
            int c = m0 + ((lane & 8) ? 8 : 0);
            ldsm4t(a[i], qt + r * 256 + (((c >> 3) ^ (r & 7)) << 4));
        }
        const uint2* sbp = (const uint2*)&sB[ks % 3][0];
        #pragma unroll
        for (int j = 0; j < 4; j++) {
            int nf = wn * 4 + j;
            uint2 bh = sbp[(nf * 2 + 0) * 32 + lane];
            uint2 bl = sbp[(nf * 2 + 1) * 32 + lane];
            #pragma unroll
            for (int i = 0; i < 4; i++) {
                mma_f16(acc[i][j], a[i], bh);
                mma_f16(acc[i][j], a[i], bl);
            }
        }
    }

    uint2* dst = gB_att + (size_t)s * BATT_SLICE2;
    #pragma unroll
    for (int i = 0; i < 4; i++) {
        int nf0 = mband * 16 + wm * 8 + 2 * i;
        #pragma unroll
        for (int jp = 0; jp < 2; jp++) {
            int ks = h * 8 + wn * 2 + jp;
            store_hfrag(dst, (size_t)ks * 2048, nf0, lane, acc[i][2 * jp], acc[i][2 * jp + 1]);
        }
    }
}

// ---------------------------------------------------------------------------
// temb
// ---------------------------------------------------------------------------
__global__ void k_temb(const float* __restrict__ time_in,
                       const float* __restrict__ w_time,
                       const float* __restrict__ b_time) {
    int s = blockIdx.x;
    int t = threadIdx.x;
    __shared__ float m[256];
    float v = time_in[(size_t)s * 256 + t];
    float sp = (v > 20.f) ? v : log1pf(__expf(v));
    m[t] = v * tanhf(sp);
    __syncthreads();

    int warp = t >> 5, lane = t & 31;
    for (int o = warp; o < OC3; o += 8) {
        const float* w = w_time + (size_t)o * 256;
        float acc = 0.f;
        #pragma unroll 4
        for (int e = lane; e < 256; e += 32) acc += m[e] * w[e];
        #pragma unroll
        for (int off = 16; off; off >>= 1) acc += __shfl_down_sync(0xffffffffu, acc, off);
        if (lane == 0) g_temb[(size_t)s * OC3 + o] = acc + b_time[o];
    }
}

// ---------------------------------------------------------------------------
extern "C" void kernel_launch(void* const* d_in, const int* in_sizes, int n_in,
                              void* d_out, int out_size) {
    (void)in_sizes; (void)n_in; (void)out_size;
    const float* x       = (const float*)d_in[0];
    const float* time_in = (const float*)d_in[1];
    const float* w_qkv   = (const float*)d_in[2];
    const float* w_time  = (const float*)d_in[3];
    const float* b_time  = (const float*)d_in[4];
    const float* w_out   = (const float*)d_in[5];
    const float* b_out   = (const float*)d_in[6];
    float* out = (float*)d_out;

    uint4* pA_qkv; cudaGetSymbolAddress((void**)&pA_qkv, gA_qkv);
    uint4* pA_out; cudaGetSymbolAddress((void**)&pA_out, gA_out);
    uint2* pB_x;   cudaGetSymbolAddress((void**)&pB_x,   gB_x);
    uint2* pB_att; cudaGetSymbolAddress((void**)&pB_att, gB_att);

    k_temb<<<S_, 256>>>(time_in, w_time, b_time);

    conv_A<<<192, 256>>>(w_qkv, F_, 16, pA_qkv);      // 96 row16-bands x 16 ks
    conv_A<<<64, 256>>>(w_out, HID, 32, pA_out);      // 16 row16-bands x 32 ks
    conv_Bd<<<dim3(64, S_), 256>>>(x, T_, 16, (size_t)F_ * T_, pB_x, (size_t)16 * 2048);

    k_qkv_mma<<<dim3(1, 24, S_), 256>>>(pA_qkv, (const uint4*)pB_x);

    k_ctx_mma<<<S_ * HEADS, 256>>>();
    k_applyT_mma<<<dim3(2, 1, S_ * HEADS), 256>>>();

    k_out_mma<<<dim3(1, 4, S_), 256>>>(pA_out, (const uint4*)pB_att, b_out, out);
}

// round 14
// speedup vs baseline: 1.4344x; 1.1044x over previous
#include <cuda_runtime.h>
#include <cuda_fp16.h>
#include <cstdint>
#include <math.h>

// Problem constants
#define B_   64
#define A_   8
#define S_   512
#define F_   256
#define T_   256
#define HID  512
#define OC3  1536
#define HEADS 4
#define C_   128

// ---------------------------------------------------------------------------
// Scratch
// ---------------------------------------------------------------------------
__device__ float  g_temb[(size_t)S_ * OC3];
__device__ __half g_q16 [(size_t)S_ * HID * T_];                 // q fp16 [s][d][t]
__device__ uint4  g_vp  [(size_t)S_ * HEADS * 4096];             // v packed A-frags (hi)
__device__ uint2  g_kp  [(size_t)S_ * HEADS * 16384];            // softmax(k) packed B-frags hi+lo
__device__ uint2  g_ctxp[(size_t)S_ * HEADS * 4096];             // ctx packed B-frags (hi only)

// prepacked operands
__device__ uint4 gA_qkv[(size_t)24 * 16 * 4 * 32];               // weights hi, [band64][ks][mf4][32]
__device__ uint4 gA_out[(size_t)4 * 32 * 4 * 32];
__device__ uint2 gB_x  [(size_t)S_ * 16 * 32 * 2 * 32];          // [s][ks][nf32][plane][32]
__device__ uint2 gB_att[(size_t)S_ * 32 * 32 * 32];              // hi only, written by applyT

#define BX_SLICE4   ((size_t)16 * 1024)    // uint4 per slice (x frags)
#define BATT_SLICE4 ((size_t)16384)        // uint4 per slice (att frags, hi only)
#define BATT_SLICE2 ((size_t)32768)        // uint2 per slice

// ---------------------------------------------------------------------------
// helpers (fp16 split)
// ---------------------------------------------------------------------------
__device__ __forceinline__ unsigned hpack(float x, float y) {
    __half2 h = __floats2half2_rn(x, y);
    return *reinterpret_cast<unsigned*>(&h);
}
__device__ __forceinline__ void hsplit(float v, float& hi, float& lo) {
    __half h = __float2half_rn(v);
    hi = __half2float(h);
    lo = v - hi;
}
__device__ __forceinline__ void hpack2(float x, float y, unsigned& hi, unsigned& lo) {
    float hx, lx, hy, ly;
    hsplit(x, hx, lx); hsplit(y, hy, ly);
    hi = hpack(hx, hy); lo = hpack(lx, ly);
}
__device__ __forceinline__ void mma_f16(float* c, const uint4& a, const uint2& b) {
    asm volatile(
        "mma.sync.aligned.m16n8k16.row.col.f32.f16.f16.f32 "
        "{%0,%1,%2,%3}, {%4,%5,%6,%7}, {%8,%9}, {%0,%1,%2,%3};\n"
        : "+f"(c[0]), "+f"(c[1]), "+f"(c[2]), "+f"(c[3])
        : "r"(a.x), "r"(a.y), "r"(a.z), "r"(a.w), "r"(b.x), "r"(b.y));
}

// cp.async
__device__ __forceinline__ void cp16(uint4* smem, const uint4* gmem) {
    unsigned sa = (unsigned)__cvta_generic_to_shared(smem);
    asm volatile("cp.async.cg.shared.global [%0], [%1], 16;\n" :: "r"(sa), "l"(gmem));
}
__device__ __forceinline__ void cp16s(uint32_t saddr, const void* gmem) {
    asm volatile("cp.async.cg.shared.global [%0], [%1], 16;\n" :: "r"(saddr), "l"(gmem));
}
__device__ __forceinline__ void cp_commit() { asm volatile("cp.async.commit_group;\n" ::); }
__device__ __forceinline__ void cp_wait1()  { asm volatile("cp.async.wait_group 1;\n" ::: "memory"); }
__device__ __forceinline__ void cp_wait0()  { asm volatile("cp.async.wait_group 0;\n" ::: "memory"); }

__device__ __forceinline__ uint32_t smem_u32(const void* p) {
    return (uint32_t)__cvta_generic_to_shared(p);
}

// ldmatrix x4 transposed (b16): A-frag from [k][m] smem tile
__device__ __forceinline__ void ldsm4t(uint4& a, uint32_t addr) {
    asm volatile("ldmatrix.sync.aligned.m8n8.x4.trans.shared.b16 {%0,%1,%2,%3}, [%4];"
                 : "=r"(a.x), "=r"(a.y), "=r"(a.z), "=r"(a.w) : "r"(addr));
}

// 2-pass frag mma (128x128 core, B hi+lo)
__device__ __forceinline__ void frag_mma2(const uint4* sa, const uint2* sbp,
                                          int wm, int wn, int lane, float acc[4][4][4]) {
    uint4 a[4]; uint2 b[4][2];
    #pragma unroll
    for (int i = 0; i < 4; i++) a[i] = sa[(wm * 4 + i) * 32 + lane];
    #pragma unroll
    for (int j = 0; j < 4; j++) {
        int nf = wn * 4 + j;
        b[j][0] = sbp[(nf * 2 + 0) * 32 + lane];
        b[j][1] = sbp[(nf * 2 + 1) * 32 + lane];
    }
    #pragma unroll
    for (int i = 0; i < 4; i++)
        #pragma unroll
        for (int j = 0; j < 4; j++) {
            mma_f16(acc[i][j], a[i], b[j][0]);
            mma_f16(acc[i][j], a[i], b[j][1]);
        }
}

// store a 16(row)x16(k-pairs) accumulator block as hi/lo B-frags
__device__ __forceinline__ void store_hfrag(uint2* dst, size_t cb, int nf0, int lane,
                                            const float* a0, const float* a1) {
    unsigned h00,l00,h01,l01,h10,l10,h11,l11;
    hpack2(a0[0], a0[1], h00, l00); hpack2(a1[0], a1[1], h01, l01);
    hpack2(a0[2], a0[3], h10, l10); hpack2(a1[2], a1[3], h11, l11);
    dst[cb + (size_t)(nf0 * 2 + 0) * 32 + lane] = make_uint2(h00, h01);
    dst[cb + (size_t)(nf0 * 2 + 1) * 32 + lane] = make_uint2(l00, l01);
    dst[cb + (size_t)((nf0 + 1) * 2 + 0) * 32 + lane] = make_uint2(h10, h11);
    dst[cb + (size_t)((nf0 + 1) * 2 + 1) * 32 + lane] = make_uint2(l10, l11);
}

// hi-only variant: B-frags packed densely [nf][32]
__device__ __forceinline__ void store_hfrag_hi(uint2* dst, size_t cb, int nf0, int lane,
                                               const float* a0, const float* a1) {
    dst[cb + (size_t)(nf0 + 0) * 32 + lane] =
        make_uint2(hpack(a0[0], a0[1]), hpack(a1[0], a1[1]));
    dst[cb + (size_t)(nf0 + 1) * 32 + lane] =
        make_uint2(hpack(a0[2], a0[3]), hpack(a1[2], a1[3]));
}

// ---------------------------------------------------------------------------
// conv_A: fp32 [M,K] row-major -> A-frags hi, layout [band64][ks][mf4][32]
// ---------------------------------------------------------------------------
__global__ void conv_A(const float* __restrict__ src, int lda, int Ksteps,
                       uint4* __restrict__ dst) {
    int wg   = blockIdx.x * 8 + (threadIdx.x >> 5);
    int lane = threadIdx.x & 31;
    int ks    = wg % Ksteps;
    int row16 = wg / Ksteps;
    int band64 = row16 >> 2, mf4 = row16 & 3;
    int g = lane >> 2, tc = (lane & 3) * 2;

    const float* p = src + (size_t)(row16 * 16 + g) * lda + ks * 16 + tc;
    float2 p00 = *(const float2*)p;
    float2 p01 = *(const float2*)(p + 8);
    float2 p10 = *(const float2*)(p + (size_t)8 * lda);
    float2 p11 = *(const float2*)(p + (size_t)8 * lda + 8);

    uint4 hi;
    hi.x = hpack(p00.x, p00.y);
    hi.y = hpack(p10.x, p10.y);
    hi.z = hpack(p01.x, p01.y);
    hi.w = hpack(p11.x, p11.y);
    dst[(((size_t)band64 * Ksteps + ks) * 4 + mf4) * 32 + lane] = hi;
}

// ---------------------------------------------------------------------------
// conv_Bd: fp32 [K,N=256] row-major (per slice) -> B-frags hi+lo
// layout [ks][nf32][plane][32]
// ---------------------------------------------------------------------------
__global__ void conv_Bd(const float* __restrict__ srcbase, int ldb, int Ksteps,
                        size_t src_slice_stride,
                        uint2* __restrict__ dstbase, size_t dst_slice_stride) {
    int s = blockIdx.y;
    const float* src = srcbase + (size_t)s * src_slice_stride;
    uint2* dst = dstbase + (size_t)s * dst_slice_stride;

    int wg   = blockIdx.x * 8 + (threadIdx.x >> 5);
    int lane = threadIdx.x & 31;
    int nf   = wg & 15;
    int ks   = (wg >> 4) % Ksteps;
    int band = wg / (16 * Ksteps);
    int g = lane >> 2, tc = (lane & 3) * 2;

    int nfg = band * 16 + nf;
    int n = nfg * 8 + g;
    const float* p = src + (size_t)(ks * 16 + tc) * ldb + n;
    float v0 = p[0];
    float v1 = p[(size_t)ldb];
    float v2 = p[(size_t)8 * ldb];
    float v3 = p[(size_t)9 * ldb];

    unsigned h0, l0, h1, l1;
    hpack2(v0, v1, h0, l0);
    hpack2(v2, v3, h1, l1);

    size_t base = (((size_t)ks * 32 + nfg) * 2) * 32 + lane;
    dst[base]      = make_uint2(h0, h1);
    dst[base + 32] = make_uint2(l0, l1);
}

// ---------------------------------------------------------------------------
// 64(M)x256(N) CTA tile GEMM core, warp tile 64x32.
// LO=true: B hi+lo (2 mma/frag); LO=false: B hi only (1 mma/frag).
// ---------------------------------------------------------------------------
template<bool LO>
__device__ __forceinline__ void gemm64x256(const uint4* __restrict__ Ach,
                                           const uint4* __restrict__ Bch,
                                           int Ksteps, float acc[4][4][4]) {
    __shared__ uint4 sA[3][128];
    __shared__ uint4 sB[3][LO ? 1024 : 512];
    const int BQ = LO ? 1024 : 512;
    int tid = threadIdx.x, wid = tid >> 5, lane = tid & 31;

    auto issue = [&](int ks) {
        int st = ks % 3;
        const uint4* A = Ach + (size_t)ks * 128;
        const uint4* B = Bch + (size_t)ks * BQ;
        if (tid < 128) cp16(&sA[st][tid], A + tid);
        #pragma unroll
        for (int q = 0; q < (LO ? 4 : 2); q++)
            cp16(&sB[st][tid + q * 256], B + tid + q * 256);
        cp_commit();
    };
    issue(0);
    issue(1);

    for (int ks = 0; ks < Ksteps; ks++) {
        if (ks + 1 < Ksteps) cp_wait1(); else cp_wait0();
        __syncthreads();
        if (ks + 2 < Ksteps) issue(ks + 2);
        const uint4* sa  = &sA[ks % 3][0];
        const uint2* sbp = (const uint2*)&sB[ks % 3][0];
        uint4 a[4];
        #pragma unroll
        for (int i = 0; i < 4; i++) a[i] = sa[i * 32 + lane];
        #pragma unroll
        for (int j = 0; j < 4; j++) {
            int nf = wid * 4 + j;
            if (LO) {
                uint2 bh = sbp[(nf * 2 + 0) * 32 + lane];
                uint2 bl = sbp[(nf * 2 + 1) * 32 + lane];
                #pragma unroll
                for (int i = 0; i < 4; i++) {
                    mma_f16(acc[i][j], a[i], bh);
                    mma_f16(acc[i][j], a[i], bl);
                }
            } else {
                uint2 bh = sbp[nf * 32 + lane];
                #pragma unroll
                for (int i = 0; i < 4; i++)
                    mma_f16(acc[i][j], a[i], bh);
            }
        }
    }
}

// ---------------------------------------------------------------------------
// qkv GEMM: 24 bands of 64 rows x full t=256.
// ---------------------------------------------------------------------------
__global__ __launch_bounds__(256, 2)
void k_qkv_mma(const uint4* __restrict__ Ap, const uint4* __restrict__ Bx) {
    __shared__ float red[8][64];
    int s = blockIdx.z, band = blockIdx.y;
    const uint4* Ach = Ap + (size_t)band * 16 * 128;
    const uint4* Bch = Bx + (size_t)s * BX_SLICE4;

    float acc[4][4][4] = {};
    gemm64x256<true>(Ach, Bch, 16, acc);

    int tid = threadIdx.x, wid = tid >> 5, lane = tid & 31;
    int g = lane >> 2, tc = (lane & 3) * 2;

    const float* te = g_temb + (size_t)s * OC3 + band * 64;
    float tv[4][2];
    #pragma unroll
    for (int i = 0; i < 4; i++) {
        tv[i][0] = te[i * 16 + g];
        tv[i][1] = te[i * 16 + 8 + g];
    }
    #pragma unroll
    for (int i = 0; i < 4; i++)
        #pragma unroll
        for (int j = 0; j < 4; j++) {
            acc[i][j][0] += tv[i][0]; acc[i][j][1] += tv[i][0];
            acc[i][j][2] += tv[i][1]; acc[i][j][3] += tv[i][1];
        }

    if (band < 8) {
        __half* gq = g_q16 + (size_t)s * HID * T_;
        #pragma unroll
        for (int i = 0; i < 4; i++) {
            int d = band * 64 + i * 16 + g;
            #pragma unroll
            for (int j = 0; j < 4; j++) {
                int t = wid * 32 + j * 8 + tc;
                *(__half2*)(gq + (size_t)d * T_ + t) =
                    __floats2half2_rn(acc[i][j][0], acc[i][j][1]);
                *(__half2*)(gq + (size_t)(d + 8) * T_ + t) =
                    __floats2half2_rn(acc[i][j][2], acc[i][j][3]);
            }
        }
    } else if (band < 16) {
        int kb = band - 8, h = kb >> 1, half = kb & 1;
        float mx[4][2];
        #pragma unroll
        for (int i = 0; i < 4; i++) { mx[i][0] = -1e30f; mx[i][1] = -1e30f; }
        #pragma unroll
        for (int i = 0; i < 4; i++)
            #pragma unroll
            for (int j = 0; j < 4; j++) {
                mx[i][0] = fmaxf(mx[i][0], fmaxf(acc[i][j][0], acc[i][j][1]));
                mx[i][1] = fmaxf(mx[i][1], fmaxf(acc[i][j][2], acc[i][j][3]));
            }
        #pragma unroll
        for (int i = 0; i < 4; i++)
            #pragma unroll
            for (int hh = 0; hh < 2; hh++) {
                mx[i][hh] = fmaxf(mx[i][hh], __shfl_xor_sync(0xffffffffu, mx[i][hh], 1));
                mx[i][hh] = fmaxf(mx[i][hh], __shfl_xor_sync(0xffffffffu, mx[i][hh], 2));
            }
        if ((lane & 3) == 0) {
            #pragma unroll
            for (int i = 0; i < 4; i++) {
                red[wid][i * 16 + g]     = mx[i][0];
                red[wid][i * 16 + 8 + g] = mx[i][1];
            }
        }
        __syncthreads();
        float MX[4][2];
        #pragma unroll
        for (int i = 0; i < 4; i++)
            #pragma unroll
            for (int hh = 0; hh < 2; hh++) {
                int r = i * 16 + hh * 8 + g;
                float m0 = fmaxf(fmaxf(red[0][r], red[1][r]), fmaxf(red[2][r], red[3][r]));
                float m1 = fmaxf(fmaxf(red[4][r], red[5][r]), fmaxf(red[6][r], red[7][r]));
                MX[i][hh] = fmaxf(m0, m1);
            }
        __syncthreads();
        float sm[4][2] = {};
        #pragma unroll
        for (int i = 0; i < 4; i++)
            #pragma unroll
            for (int j = 0; j < 4; j++) {
                acc[i][j][0] = __expf(acc[i][j][0] - MX[i][0]);
                acc[i][j][1] = __expf(acc[i][j][1] - MX[i][0]);
                acc[i][j][2] = __expf(acc[i][j][2] - MX[i][1]);
                acc[i][j][3] = __expf(acc[i][j][3] - MX[i][1]);
                sm[i][0] += acc[i][j][0] + acc[i][j][1];
                sm[i][1] += acc[i][j][2] + acc[i][j][3];
            }
        #pragma unroll
        for (int i = 0; i < 4; i++)
            #pragma unroll
            for (int hh = 0; hh < 2; hh++) {
                sm[i][hh] += __shfl_xor_sync(0xffffffffu, sm[i][hh], 1);
                sm[i][hh] += __shfl_xor_sync(0xffffffffu, sm[i][hh], 2);
            }
        if ((lane & 3) == 0) {
            #pragma unroll
            for (int i = 0; i < 4; i++) {
                red[wid][i * 16 + g]     = sm[i][0];
                red[wid][i * 16 + 8 + g] = sm[i][1];
            }
        }
        __syncthreads();
        float INV[4][2];
        #pragma unroll
        for (int i = 0; i < 4; i++)
            #pragma unroll
            for (int hh = 0; hh < 2; hh++) {
                int r = i * 16 + hh * 8 + g;
                INV[i][hh] = 1.f / (red[0][r] + red[1][r] + red[2][r] + red[3][r] +
                                    red[4][r] + red[5][r] + red[6][r] + red[7][r]);
            }
        uint2* dst = g_kp + ((size_t)s * HEADS + h) * 16384;
        #pragma unroll
        for (int i = 0; i < 4; i++) {
            int nf0 = half * 8 + i * 2;
            #pragma unroll
            for (int jp = 0; jp < 2; jp++) {
                int ks = wid * 2 + jp;
                float e0[4] = { acc[i][2*jp][0] * INV[i][0], acc[i][2*jp][1] * INV[i][0],
                                acc[i][2*jp][2] * INV[i][1], acc[i][2*jp][3] * INV[i][1] };
                float e1[4] = { acc[i][2*jp+1][0] * INV[i][0], acc[i][2*jp+1][1] * INV[i][0],
                                acc[i][2*jp+1][2] * INV[i][1], acc[i][2*jp+1][3] * INV[i][1] };
                store_hfrag(dst, (size_t)ks * 1024, nf0, lane, e0, e1);
            }
        }
    } else {
        int vb = band - 16, h = vb >> 1, half = vb & 1;
        uint4* dst = g_vp + ((size_t)s * HEADS + h) * 4096;
        #pragma unroll
        for (int i = 0; i < 4; i++) {
            int mf = half * 4 + i;
            #pragma unroll
            for (int jp = 0; jp < 2; jp++) {
                int ks = wid * 2 + jp;
                uint4 hi;
                hi.x = hpack(acc[i][2*jp][0],   acc[i][2*jp][1]);
                hi.y = hpack(acc[i][2*jp][2],   acc[i][2*jp][3]);
                hi.z = hpack(acc[i][2*jp+1][0], acc[i][2*jp+1][1]);
                hi.w = hpack(acc[i][2*jp+1][2], acc[i][2*jp+1][3]);
                dst[(size_t)ks * 256 + mf * 32 + lane] = hi;
            }
        }
    }
}

// ---------------------------------------------------------------------------
// out GEMM: 64x256 core with hi-only B, Ksteps=32, bias epilogue
// ---------------------------------------------------------------------------
__global__ __launch_bounds__(256, 2)
void k_out_mma(const uint4* __restrict__ Ap, const uint4* __restrict__ Bp,
               const float* __restrict__ bias, float* __restrict__ out) {
    int s = blockIdx.z, band = blockIdx.y;
    const uint4* Ach = Ap + (size_t)band * 32 * 128;
    const uint4* Bch = Bp + (size_t)s * BATT_SLICE4;

    float acc[4][4][4] = {};
    gemm64x256<false>(Ach, Bch, 32, acc);

    int tid = threadIdx.x, wid = tid >> 5, lane = tid & 31;
    int g = lane >> 2, tc = (lane & 3) * 2;
    float* Co = out + (size_t)s * 256 * T_;

    #pragma unroll
    for (int i = 0; i < 4; i++) {
        int m = band * 64 + i * 16 + g;
        float b0 = bias[m], b1 = bias[m + 8];
        #pragma unroll
        for (int j = 0; j < 4; j++) {
            int n = wid * 32 + j * 8 + tc;
            *(float2*)(Co + (size_t)m * T_ + n) =
                make_float2(acc[i][j][0] + b0, acc[i][j][1] + b0);
            *(float2*)(Co + (size_t)(m + 8) * T_ + n) =
                make_float2(acc[i][j][2] + b1, acc[i][j][3] + b1);
        }
    }
}

// ---------------------------------------------------------------------------
// 128x128 prepacked mma core (8 warps 2x4, warp tile 64x32), 3-stage cp.async
// ---------------------------------------------------------------------------
__device__ __forceinline__ void mma_tile3(const uint4* __restrict__ Ach,
                                          const uint4* __restrict__ Bch,
                                          int Ksteps, float acc[4][4][4]) {
    __shared__ uint4 sA[3][256];
    __shared__ uint4 sB[3][512];
    int tid = threadIdx.x, wid = tid >> 5, lane = tid & 31;
    int wm = wid >> 2, wn = wid & 3;

    auto issue = [&](int ks) {
        int st = ks % 3;
        const uint4* A = Ach + (size_t)ks * 256;
        const uint4* B = Bch + (size_t)ks * 512;
        cp16(&sA[st][tid], A + tid);
        cp16(&sB[st][tid], B + tid); cp16(&sB[st][tid + 256], B + tid + 256);
        cp_commit();
    };
    issue(0);
    issue(1);

    for (int ks = 0; ks < Ksteps; ks++) {
        if (ks + 1 < Ksteps) cp_wait1(); else cp_wait0();
        __syncthreads();
        if (ks + 2 < Ksteps) issue(ks + 2);
        frag_mma2(&sA[ks % 3][0], (const uint2*)&sB[ks % 3][0], wm, wn, lane, acc);
    }
}

// ---------------------------------------------------------------------------
// ctx: ctxT[e][d] = sum_t v[e,t]*softmax(k)[d,t] — both operands prepacked
// epilogue -> g_ctxp packed B-frags (hi only)
// ---------------------------------------------------------------------------
__global__ __launch_bounds__(256, 2)
void k_ctx_mma() {
    int sb = blockIdx.x;
    const uint4* Vch = g_vp + (size_t)sb * 4096;
    const uint4* Kch = (const uint4*)(g_kp + (size_t)sb * 16384);

    float acc[4][4][4] = {};
    mma_tile3(Vch, Kch, 16, acc);

    int tid = threadIdx.x, wid = tid >> 5, lane = tid & 31;
    int wm = wid >> 2, wn = wid & 3;

    uint2* dst = g_ctxp + (size_t)sb * 4096;
    #pragma unroll
    for (int i = 0; i < 4; i++) {
        int nf0 = wm * 8 + 2 * i;
        #pragma unroll
        for (int jp = 0; jp < 2; jp++) {
            int ks = wn * 2 + jp;
            store_hfrag_hi(dst, (size_t)ks * 512, nf0, lane, acc[i][2 * jp], acc[i][2 * jp + 1]);
        }
    }
}

// ---------------------------------------------------------------------------
// applyT: attT[t][e] = sum_d q[d,t]*ctxT[e,d]
// A = q staged via cp.async + swizzled ldmatrix.trans; B = ctx frags hi-only.
// Epilogue -> gB_att packed B-frags (hi only)
// ---------------------------------------------------------------------------
__global__ __launch_bounds__(256, 2)
void k_applyT_mma() {
    __shared__ uint4 sB[3][256];     // ctx frags hi, 4KB/stage
    __shared__ uint4 sQ[3][256];     // q tiles,      4KB/stage
    int sb = blockIdx.z, s = sb >> 2, h = sb & 3;
    int mband = blockIdx.x;
    int tid = threadIdx.x, wid = tid >> 5, lane = tid & 31;
    int wm = wid >> 2, wn = wid & 3;

    const __half* qb = g_q16 + (size_t)s * HID * T_ + (size_t)(h * C_) * T_
                       + mband * 128;
    const uint4* Bch = (const uint4*)(g_ctxp + (size_t)sb * 4096);

    int qrow = tid >> 4;          // 0..15 (k within tile)
    int qseg = tid & 15;          // 16B segment within 256B row
    uint32_t qdst_off = (uint32_t)(qrow * 256 + ((qseg ^ (qrow & 7)) << 4));

    auto issue = [&](int ks) {
        int st = ks % 3;
        cp16(&sB[st][tid], Bch + (size_t)ks * 256 + tid);
        cp16s(smem_u32(&sQ[st][0]) + qdst_off,
              qb + (size_t)(ks * 16 + qrow) * T_ + qseg * 8);
        cp_commit();
    };
    issue(0); issue(1);

    float acc[4][4][4] = {};
    for (int ks = 0; ks < 8; ks++) {
        if (ks + 1 < 8) cp_wait1(); else cp_wait0();
        __syncthreads();
        if (ks + 2 < 8) issue(ks + 2);

        uint32_t qt = smem_u32(&sQ[ks % 3][0]);
        uint4 a[4];
        #pragma unroll
        for (int i = 0; i < 4; i++) {
            int m0 = (wm * 4 + i) * 16;
            int r = (lane & 7) + ((lane & 16) ? 8 : 0);
            int c = m0 + ((lane & 8) ? 8 : 0);
            ldsm4t(a[i], qt + r * 256 + (((c >> 3) ^ (r & 7)) << 4));
        }
        const uint2* sbp = (const uint2*)&sB[ks % 3][0];
        #pragma unroll
        for (int j = 0; j < 4; j++) {
            uint2 bh = sbp[(wn * 4 + j) * 32 + lane];
            #pragma unroll
            for (int i = 0; i < 4; i++)
                mma_f16(acc[i][j], a[i], bh);
        }
    }

    uint2* dst = gB_att + (size_t)s * BATT_SLICE2;
    #pragma unroll
    for (int i = 0; i < 4; i++) {
        int nf0 = mband * 16 + wm * 8 + 2 * i;
        #pragma unroll
        for (int jp = 0; jp < 2; jp++) {
            int ks = h * 8 + wn * 2 + jp;
            store_hfrag_hi(dst, (size_t)ks * 1024, nf0, lane, acc[i][2 * jp], acc[i][2 * jp + 1]);
        }
    }
}

// ---------------------------------------------------------------------------
// temb
// ---------------------------------------------------------------------------
__global__ void k_temb(const float* __restrict__ time_in,
                       const float* __restrict__ w_time,
                       const float* __restrict__ b_time) {
    int s = blockIdx.x;
    int t = threadIdx.x;
    __shared__ float m[256];
    float v = time_in[(size_t)s * 256 + t];
    float sp = (v > 20.f) ? v : log1pf(__expf(v));
    m[t] = v * tanhf(sp);
    __syncthreads();

    int warp = t >> 5, lane = t & 31;
    for (int o = warp; o < OC3; o += 8) {
        const float* w = w_time + (size_t)o * 256;
        float acc = 0.f;
        #pragma unroll 4
        for (int e = lane; e < 256; e += 32) acc += m[e] * w[e];
        #pragma unroll
        for (int off = 16; off; off >>= 1) acc += __shfl_down_sync(0xffffffffu, acc, off);
        if (lane == 0) g_temb[(size_t)s * OC3 + o] = acc + b_time[o];
    }
}

// ---------------------------------------------------------------------------
extern "C" void kernel_launch(void* const* d_in, const int* in_sizes, int n_in,
                              void* d_out, int out_size) {
    (void)in_sizes; (void)n_in; (void)out_size;
    const float* x       = (const float*)d_in[0];
    const float* time_in = (const float*)d_in[1];
    const float* w_qkv   = (const float*)d_in[2];
    const float* w_time  = (const float*)d_in[3];
    const float* b_time  = (const float*)d_in[4];
    const float* w_out   = (const float*)d_in[5];
    const float* b_out   = (const float*)d_in[6];
    float* out = (float*)d_out;

    uint4* pA_qkv; cudaGetSymbolAddress((void**)&pA_qkv, gA_qkv);
    uint4* pA_out; cudaGetSymbolAddress((void**)&pA_out, gA_out);
    uint2* pB_x;   cudaGetSymbolAddress((void**)&pB_x,   gB_x);
    uint2* pB_att; cudaGetSymbolAddress((void**)&pB_att, gB_att);

    k_temb<<<S_, 256>>>(time_in, w_time, b_time);

    conv_A<<<192, 256>>>(w_qkv, F_, 16, pA_qkv);      // 96 row16-bands x 16 ks
    conv_A<<<64, 256>>>(w_out, HID, 32, pA_out);      // 16 row16-bands x 32 ks
    conv_Bd<<<dim3(64, S_), 256>>>(x, T_, 16, (size_t)F_ * T_, pB_x, (size_t)16 * 2048);

    k_qkv_mma<<<dim3(1, 24, S_), 256>>>(pA_qkv, (const uint4*)pB_x);

    k_ctx_mma<<<S_ * HEADS, 256>>>();
    k_applyT_mma<<<dim3(2, 1, S_ * HEADS), 256>>>();

    k_out_mma<<<dim3(1, 4, S_), 256>>>(pA_out, (const uint4*)pB_att, b_out, out);
}

// round 15
// speedup vs baseline: 1.6727x; 1.1662x over previous
#include <cuda_runtime.h>
#include <cuda_fp16.h>
#include <cstdint>
#include <math.h>

// Problem constants
#define B_   64
#define A_   8
#define S_   512
#define F_   256
#define T_   256
#define HID  512
#define OC3  1536
#define HEADS 4
#define C_   128

// ---------------------------------------------------------------------------
// Scratch
// ---------------------------------------------------------------------------
__device__ float  g_temb[(size_t)S_ * OC3];
__device__ __half g_q16 [(size_t)S_ * HID * T_];                 // q fp16 [s][d][t]
__device__ uint4  g_vp  [(size_t)S_ * HEADS * 4096];             // v packed A-frags (hi)
__device__ uint2  g_kp  [(size_t)S_ * HEADS * 16384];            // softmax(k) packed B-frags hi+lo
__device__ uint2  g_ctxp[(size_t)S_ * HEADS * 4096];             // ctx packed B-frags (hi only)

// prepacked operands
__device__ uint4 gA_qkv[(size_t)24 * 16 * 4 * 32];               // weights hi, [band64][ks][mf4][32]
__device__ uint4 gA_out[(size_t)4 * 32 * 4 * 32];
__device__ uint2 gB_x  [(size_t)S_ * 16 * 32 * 32];              // hi only [s][ks][nf32][32]
__device__ uint2 gB_att[(size_t)S_ * 32 * 32 * 32];              // hi only, written by applyT

#define BX_SLICE4   ((size_t)16 * 512)     // uint4 per slice (x frags, hi only)
#define BATT_SLICE4 ((size_t)16384)        // uint4 per slice (att frags, hi only)
#define BATT_SLICE2 ((size_t)32768)        // uint2 per slice

// ---------------------------------------------------------------------------
// helpers (fp16 split)
// ---------------------------------------------------------------------------
__device__ __forceinline__ unsigned hpack(float x, float y) {
    __half2 h = __floats2half2_rn(x, y);
    return *reinterpret_cast<unsigned*>(&h);
}
__device__ __forceinline__ void hsplit(float v, float& hi, float& lo) {
    __half h = __float2half_rn(v);
    hi = __half2float(h);
    lo = v - hi;
}
__device__ __forceinline__ void hpack2(float x, float y, unsigned& hi, unsigned& lo) {
    float hx, lx, hy, ly;
    hsplit(x, hx, lx); hsplit(y, hy, ly);
    hi = hpack(hx, hy); lo = hpack(lx, ly);
}
__device__ __forceinline__ void mma_f16(float* c, const uint4& a, const uint2& b) {
    asm volatile(
        "mma.sync.aligned.m16n8k16.row.col.f32.f16.f16.f32 "
        "{%0,%1,%2,%3}, {%4,%5,%6,%7}, {%8,%9}, {%0,%1,%2,%3};\n"
        : "+f"(c[0]), "+f"(c[1]), "+f"(c[2]), "+f"(c[3])
        : "r"(a.x), "r"(a.y), "r"(a.z), "r"(a.w), "r"(b.x), "r"(b.y));
}

// cp.async
__device__ __forceinline__ void cp16(uint4* smem, const uint4* gmem) {
    unsigned sa = (unsigned)__cvta_generic_to_shared(smem);
    asm volatile("cp.async.cg.shared.global [%0], [%1], 16;\n" :: "r"(sa), "l"(gmem));
}
__device__ __forceinline__ void cp16s(uint32_t saddr, const void* gmem) {
    asm volatile("cp.async.cg.shared.global [%0], [%1], 16;\n" :: "r"(saddr), "l"(gmem));
}
__device__ __forceinline__ void cp_commit() { asm volatile("cp.async.commit_group;\n" ::); }
__device__ __forceinline__ void cp_wait1()  { asm volatile("cp.async.wait_group 1;\n" ::: "memory"); }
__device__ __forceinline__ void cp_wait0()  { asm volatile("cp.async.wait_group 0;\n" ::: "memory"); }

__device__ __forceinline__ uint32_t smem_u32(const void* p) {
    return (uint32_t)__cvta_generic_to_shared(p);
}

// ldmatrix x4 transposed (b16): A-frag from [k][m] smem tile
__device__ __forceinline__ void ldsm4t(uint4& a, uint32_t addr) {
    asm volatile("ldmatrix.sync.aligned.m8n8.x4.trans.shared.b16 {%0,%1,%2,%3}, [%4];"
                 : "=r"(a.x), "=r"(a.y), "=r"(a.z), "=r"(a.w) : "r"(addr));
}

// 2-pass frag mma (128x128 core, B hi+lo)
__device__ __forceinline__ void frag_mma2(const uint4* sa, const uint2* sbp,
                                          int wm, int wn, int lane, float acc[4][4][4]) {
    uint4 a[4]; uint2 b[4][2];
    #pragma unroll
    for (int i = 0; i < 4; i++) a[i] = sa[(wm * 4 + i) * 32 + lane];
    #pragma unroll
    for (int j = 0; j < 4; j++) {
        int nf = wn * 4 + j;
        b[j][0] = sbp[(nf * 2 + 0) * 32 + lane];
        b[j][1] = sbp[(nf * 2 + 1) * 32 + lane];
    }
    #pragma unroll
    for (int i = 0; i < 4; i++)
        #pragma unroll
        for (int j = 0; j < 4; j++) {
            mma_f16(acc[i][j], a[i], b[j][0]);
            mma_f16(acc[i][j], a[i], b[j][1]);
        }
}

// store a 16(row)x16(k-pairs) accumulator block as hi/lo B-frags
__device__ __forceinline__ void store_hfrag(uint2* dst, size_t cb, int nf0, int lane,
                                            const float* a0, const float* a1) {
    unsigned h00,l00,h01,l01,h10,l10,h11,l11;
    hpack2(a0[0], a0[1], h00, l00); hpack2(a1[0], a1[1], h01, l01);
    hpack2(a0[2], a0[3], h10, l10); hpack2(a1[2], a1[3], h11, l11);
    dst[cb + (size_t)(nf0 * 2 + 0) * 32 + lane] = make_uint2(h00, h01);
    dst[cb + (size_t)(nf0 * 2 + 1) * 32 + lane] = make_uint2(l00, l01);
    dst[cb + (size_t)((nf0 + 1) * 2 + 0) * 32 + lane] = make_uint2(h10, h11);
    dst[cb + (size_t)((nf0 + 1) * 2 + 1) * 32 + lane] = make_uint2(l10, l11);
}

// hi-only variant: B-frags packed densely [nf][32]
__device__ __forceinline__ void store_hfrag_hi(uint2* dst, size_t cb, int nf0, int lane,
                                               const float* a0, const float* a1) {
    dst[cb + (size_t)(nf0 + 0) * 32 + lane] =
        make_uint2(hpack(a0[0], a0[1]), hpack(a1[0], a1[1]));
    dst[cb + (size_t)(nf0 + 1) * 32 + lane] =
        make_uint2(hpack(a0[2], a0[3]), hpack(a1[2], a1[3]));
}

// ---------------------------------------------------------------------------
// conv_A: fp32 [M,K] row-major -> A-frags hi, layout [band64][ks][mf4][32]
// ---------------------------------------------------------------------------
__global__ void conv_A(const float* __restrict__ src, int lda, int Ksteps,
                       uint4* __restrict__ dst) {
    int wg   = blockIdx.x * 8 + (threadIdx.x >> 5);
    int lane = threadIdx.x & 31;
    int ks    = wg % Ksteps;
    int row16 = wg / Ksteps;
    int band64 = row16 >> 2, mf4 = row16 & 3;
    int g = lane >> 2, tc = (lane & 3) * 2;

    const float* p = src + (size_t)(row16 * 16 + g) * lda + ks * 16 + tc;
    float2 p00 = *(const float2*)p;
    float2 p01 = *(const float2*)(p + 8);
    float2 p10 = *(const float2*)(p + (size_t)8 * lda);
    float2 p11 = *(const float2*)(p + (size_t)8 * lda + 8);

    uint4 hi;
    hi.x = hpack(p00.x, p00.y);
    hi.y = hpack(p10.x, p10.y);
    hi.z = hpack(p01.x, p01.y);
    hi.w = hpack(p11.x, p11.y);
    dst[(((size_t)band64 * Ksteps + ks) * 4 + mf4) * 32 + lane] = hi;
}

// ---------------------------------------------------------------------------
// conv_Bd: fp32 [K,N=256] row-major (per slice) -> B-frags HI ONLY
// layout [ks][nf32][32]
// ---------------------------------------------------------------------------
__global__ void conv_Bd(const float* __restrict__ srcbase, int ldb, int Ksteps,
                        size_t src_slice_stride,
                        uint2* __restrict__ dstbase, size_t dst_slice_stride) {
    int s = blockIdx.y;
    const float* src = srcbase + (size_t)s * src_slice_stride;
    uint2* dst = dstbase + (size_t)s * dst_slice_stride;

    int wg   = blockIdx.x * 8 + (threadIdx.x >> 5);
    int lane = threadIdx.x & 31;
    int nf   = wg & 15;
    int ks   = (wg >> 4) % Ksteps;
    int band = wg / (16 * Ksteps);
    int g = lane >> 2, tc = (lane & 3) * 2;

    int nfg = band * 16 + nf;
    int n = nfg * 8 + g;
    const float* p = src + (size_t)(ks * 16 + tc) * ldb + n;
    float v0 = p[0];
    float v1 = p[(size_t)ldb];
    float v2 = p[(size_t)8 * ldb];
    float v3 = p[(size_t)9 * ldb];

    dst[((size_t)ks * 32 + nfg) * 32 + lane] =
        make_uint2(hpack(v0, v1), hpack(v2, v3));
}

// ---------------------------------------------------------------------------
// 64(M)x256(N) CTA tile GEMM core, warp tile 64x32.
// LO=true: B hi+lo (2 mma/frag); LO=false: B hi only (1 mma/frag).
// ---------------------------------------------------------------------------
template<bool LO>
__device__ __forceinline__ void gemm64x256(const uint4* __restrict__ Ach,
                                           const uint4* __restrict__ Bch,
                                           int Ksteps, float acc[4][4][4]) {
    __shared__ uint4 sA[3][128];
    __shared__ uint4 sB[3][LO ? 1024 : 512];
    const int BQ = LO ? 1024 : 512;
    int tid = threadIdx.x, wid = tid >> 5, lane = tid & 31;

    auto issue = [&](int ks) {
        int st = ks % 3;
        const uint4* A = Ach + (size_t)ks * 128;
        const uint4* B = Bch + (size_t)ks * BQ;
        if (tid < 128) cp16(&sA[st][tid], A + tid);
        #pragma unroll
        for (int q = 0; q < (LO ? 4 : 2); q++)
            cp16(&sB[st][tid + q * 256], B + tid + q * 256);
        cp_commit();
    };
    issue(0);
    issue(1);

    for (int ks = 0; ks < Ksteps; ks++) {
        if (ks + 1 < Ksteps) cp_wait1(); else cp_wait0();
        __syncthreads();
        if (ks + 2 < Ksteps) issue(ks + 2);
        const uint4* sa  = &sA[ks % 3][0];
        const uint2* sbp = (const uint2*)&sB[ks % 3][0];
        uint4 a[4];
        #pragma unroll
        for (int i = 0; i < 4; i++) a[i] = sa[i * 32 + lane];
        #pragma unroll
        for (int j = 0; j < 4; j++) {
            int nf = wid * 4 + j;
            if (LO) {
                uint2 bh = sbp[(nf * 2 + 0) * 32 + lane];
                uint2 bl = sbp[(nf * 2 + 1) * 32 + lane];
                #pragma unroll
                for (int i = 0; i < 4; i++) {
                    mma_f16(acc[i][j], a[i], bh);
                    mma_f16(acc[i][j], a[i], bl);
                }
            } else {
                uint2 bh = sbp[nf * 32 + lane];
                #pragma unroll
                for (int i = 0; i < 4; i++)
                    mma_f16(acc[i][j], a[i], bh);
            }
        }
    }
}

// ---------------------------------------------------------------------------
// qkv GEMM: 24 bands of 64 rows x full t=256. B = x frags hi-only.
// ---------------------------------------------------------------------------
__global__ __launch_bounds__(256, 2)
void k_qkv_mma(const uint4* __restrict__ Ap, const uint4* __restrict__ Bx) {
    __shared__ float red[8][64];
    int s = blockIdx.z, band = blockIdx.y;
    const uint4* Ach = Ap + (size_t)band * 16 * 128;
    const uint4* Bch = Bx + (size_t)s * BX_SLICE4;

    float acc[4][4][4] = {};
    gemm64x256<false>(Ach, Bch, 16, acc);

    int tid = threadIdx.x, wid = tid >> 5, lane = tid & 31;
    int g = lane >> 2, tc = (lane & 3) * 2;

    const float* te = g_temb + (size_t)s * OC3 + band * 64;
    float tv[4][2];
    #pragma unroll
    for (int i = 0; i < 4; i++) {
        tv[i][0] = te[i * 16 + g];
        tv[i][1] = te[i * 16 + 8 + g];
    }
    #pragma unroll
    for (int i = 0; i < 4; i++)
        #pragma unroll
        for (int j = 0; j < 4; j++) {
            acc[i][j][0] += tv[i][0]; acc[i][j][1] += tv[i][0];
            acc[i][j][2] += tv[i][1]; acc[i][j][3] += tv[i][1];
        }

    if (band < 8) {
        __half* gq = g_q16 + (size_t)s * HID * T_;
        #pragma unroll
        for (int i = 0; i < 4; i++) {
            int d = band * 64 + i * 16 + g;
            #pragma unroll
            for (int j = 0; j < 4; j++) {
                int t = wid * 32 + j * 8 + tc;
                *(__half2*)(gq + (size_t)d * T_ + t) =
                    __floats2half2_rn(acc[i][j][0], acc[i][j][1]);
                *(__half2*)(gq + (size_t)(d + 8) * T_ + t) =
                    __floats2half2_rn(acc[i][j][2], acc[i][j][3]);
            }
        }
    } else if (band < 16) {
        int kb = band - 8, h = kb >> 1, half = kb & 1;
        float mx[4][2];
        #pragma unroll
        for (int i = 0; i < 4; i++) { mx[i][0] = -1e30f; mx[i][1] = -1e30f; }
        #pragma unroll
        for (int i = 0; i < 4; i++)
            #pragma unroll
            for (int j = 0; j < 4; j++) {
                mx[i][0] = fmaxf(mx[i][0], fmaxf(acc[i][j][0], acc[i][j][1]));
                mx[i][1] = fmaxf(mx[i][1], fmaxf(acc[i][j][2], acc[i][j][3]));
            }
        #pragma unroll
        for (int i = 0; i < 4; i++)
            #pragma unroll
            for (int hh = 0; hh < 2; hh++) {
                mx[i][hh] = fmaxf(mx[i][hh], __shfl_xor_sync(0xffffffffu, mx[i][hh], 1));
                mx[i][hh] = fmaxf(mx[i][hh], __shfl_xor_sync(0xffffffffu, mx[i][hh], 2));
            }
        if ((lane & 3) == 0) {
            #pragma unroll
            for (int i = 0; i < 4; i++) {
                red[wid][i * 16 + g]     = mx[i][0];
                red[wid][i * 16 + 8 + g] = mx[i][1];
            }
        }
        __syncthreads();
        float MX[4][2];
        #pragma unroll
        for (int i = 0; i < 4; i++)
            #pragma unroll
            for (int hh = 0; hh < 2; hh++) {
                int r = i * 16 + hh * 8 + g;
                float m0 = fmaxf(fmaxf(red[0][r], red[1][r]), fmaxf(red[2][r], red[3][r]));
                float m1 = fmaxf(fmaxf(red[4][r], red[5][r]), fmaxf(red[6][r], red[7][r]));
                MX[i][hh] = fmaxf(m0, m1);
            }
        __syncthreads();
        float sm[4][2] = {};
        #pragma unroll
        for (int i = 0; i < 4; i++)
            #pragma unroll
            for (int j = 0; j < 4; j++) {
                acc[i][j][0] = __expf(acc[i][j][0] - MX[i][0]);
                acc[i][j][1] = __expf(acc[i][j][1] - MX[i][0]);
                acc[i][j][2] = __expf(acc[i][j][2] - MX[i][1]);
                acc[i][j][3] = __expf(acc[i][j][3] - MX[i][1]);
                sm[i][0] += acc[i][j][0] + acc[i][j][1];
                sm[i][1] += acc[i][j][2] + acc[i][j][3];
            }
        #pragma unroll
        for (int i = 0; i < 4; i++)
            #pragma unroll
            for (int hh = 0; hh < 2; hh++) {
                sm[i][hh] += __shfl_xor_sync(0xffffffffu, sm[i][hh], 1);
                sm[i][hh] += __shfl_xor_sync(0xffffffffu, sm[i][hh], 2);
            }
        if ((lane & 3) == 0) {
            #pragma unroll
            for (int i = 0; i < 4; i++) {
                red[wid][i * 16 + g]     = sm[i][0];
                red[wid][i * 16 + 8 + g] = sm[i][1];
            }
        }
        __syncthreads();
        float INV[4][2];
        #pragma unroll
        for (int i = 0; i < 4; i++)
            #pragma unroll
            for (int hh = 0; hh < 2; hh++) {
                int r = i * 16 + hh * 8 + g;
                INV[i][hh] = 1.f / (red[0][r] + red[1][r] + red[2][r] + red[3][r] +
                                    red[4][r] + red[5][r] + red[6][r] + red[7][r]);
            }
        uint2* dst = g_kp + ((size_t)s * HEADS + h) * 16384;
        #pragma unroll
        for (int i = 0; i < 4; i++) {
            int nf0 = half * 8 + i * 2;
            #pragma unroll
            for (int jp = 0; jp < 2; jp++) {
                int ks = wid * 2 + jp;
                float e0[4] = { acc[i][2*jp][0] * INV[i][0], acc[i][2*jp][1] * INV[i][0],
                                acc[i][2*jp][2] * INV[i][1], acc[i][2*jp][3] * INV[i][1] };
                float e1[4] = { acc[i][2*jp+1][0] * INV[i][0], acc[i][2*jp+1][1] * INV[i][0],
                                acc[i][2*jp+1][2] * INV[i][1], acc[i][2*jp+1][3] * INV[i][1] };
                store_hfrag(dst, (size_t)ks * 1024, nf0, lane, e0, e1);
            }
        }
    } else {
        int vb = band - 16, h = vb >> 1, half = vb & 1;
        uint4* dst = g_vp + ((size_t)s * HEADS + h) * 4096;
        #pragma unroll
        for (int i = 0; i < 4; i++) {
            int mf = half * 4 + i;
            #pragma unroll
            for (int jp = 0; jp < 2; jp++) {
                int ks = wid * 2 + jp;
                uint4 hi;
                hi.x = hpack(acc[i][2*jp][0],   acc[i][2*jp][1]);
                hi.y = hpack(acc[i][2*jp][2],   acc[i][2*jp][3]);
                hi.z = hpack(acc[i][2*jp+1][0], acc[i][2*jp+1][1]);
                hi.w = hpack(acc[i][2*jp+1][2], acc[i][2*jp+1][3]);
                dst[(size_t)ks * 256 + mf * 32 + lane] = hi;
            }
        }
    }
}

// ---------------------------------------------------------------------------
// out GEMM: 64x256 core with hi-only B, Ksteps=32, bias epilogue
// ---------------------------------------------------------------------------
__global__ __launch_bounds__(256, 2)
void k_out_mma(const uint4* __restrict__ Ap, const uint4* __restrict__ Bp,
               const float* __restrict__ bias, float* __restrict__ out) {
    int s = blockIdx.z, band = blockIdx.y;
    const uint4* Ach = Ap + (size_t)band * 32 * 128;
    const uint4* Bch = Bp + (size_t)s * BATT_SLICE4;

    float acc[4][4][4] = {};
    gemm64x256<false>(Ach, Bch, 32, acc);

    int tid = threadIdx.x, wid = tid >> 5, lane = tid & 31;
    int g = lane >> 2, tc = (lane & 3) * 2;
    float* Co = out + (size_t)s * 256 * T_;

    #pragma unroll
    for (int i = 0; i < 4; i++) {
        int m = band * 64 + i * 16 + g;
        float b0 = bias[m], b1 = bias[m + 8];
        #pragma unroll
        for (int j = 0; j < 4; j++) {
            int n = wid * 32 + j * 8 + tc;
            *(float2*)(Co + (size_t)m * T_ + n) =
                make_float2(acc[i][j][0] + b0, acc[i][j][1] + b0);
            *(float2*)(Co + (size_t)(m + 8) * T_ + n) =
                make_float2(acc[i][j][2] + b1, acc[i][j][3] + b1);
        }
    }
}

// ---------------------------------------------------------------------------
// 128x128 prepacked mma core (8 warps 2x4, warp tile 64x32), 3-stage cp.async
// ---------------------------------------------------------------------------
__device__ __forceinline__ void mma_tile3(const uint4* __restrict__ Ach,
                                          const uint4* __restrict__ Bch,
                                          int Ksteps, float acc[4][4][4]) {
    __shared__ uint4 sA[3][256];
    __shared__ uint4 sB[3][512];
    int tid = threadIdx.x, wid = tid >> 5, lane = tid & 31;
    int wm = wid >> 2, wn = wid & 3;

    auto issue = [&](int ks) {
        int st = ks % 3;
        const uint4* A = Ach + (size_t)ks * 256;
        const uint4* B = Bch + (size_t)ks * 512;
        cp16(&sA[st][tid], A + tid);
        cp16(&sB[st][tid], B + tid); cp16(&sB[st][tid + 256], B + tid + 256);
        cp_commit();
    };
    issue(0);
    issue(1);

    for (int ks = 0; ks < Ksteps; ks++) {
        if (ks + 1 < Ksteps) cp_wait1(); else cp_wait0();
        __syncthreads();
        if (ks + 2 < Ksteps) issue(ks + 2);
        frag_mma2(&sA[ks % 3][0], (const uint2*)&sB[ks % 3][0], wm, wn, lane, acc);
    }
}

// ---------------------------------------------------------------------------
// ctx: ctxT[e][d] = sum_t v[e,t]*softmax(k)[d,t] — both operands prepacked
// epilogue -> g_ctxp packed B-frags (hi only)
// ---------------------------------------------------------------------------
__global__ __launch_bounds__(256, 2)
void k_ctx_mma() {
    int sb = blockIdx.x;
    const uint4* Vch = g_vp + (size_t)sb * 4096;
    const uint4* Kch = (const uint4*)(g_kp + (size_t)sb * 16384);

    float acc[4][4][4] = {};
    mma_tile3(Vch, Kch, 16, acc);

    int tid = threadIdx.x, wid = tid >> 5, lane = tid & 31;
    int wm = wid >> 2, wn = wid & 3;

    uint2* dst = g_ctxp + (size_t)sb * 4096;
    #pragma unroll
    for (int i = 0; i < 4; i++) {
        int nf0 = wm * 8 + 2 * i;
        #pragma unroll
        for (int jp = 0; jp < 2; jp++) {
            int ks = wn * 2 + jp;
            store_hfrag_hi(dst, (size_t)ks * 512, nf0, lane, acc[i][2 * jp], acc[i][2 * jp + 1]);
        }
    }
}

// ---------------------------------------------------------------------------
// applyT: attT[t][e] = sum_d q[d,t]*ctxT[e,d]
// A = q staged via cp.async + swizzled ldmatrix.trans; B = ctx frags hi-only.
// Epilogue -> gB_att packed B-frags (hi only)
// ---------------------------------------------------------------------------
__global__ __launch_bounds__(256, 2)
void k_applyT_mma() {
    __shared__ uint4 sB[3][256];     // ctx frags hi, 4KB/stage
    __shared__ uint4 sQ[3][256];     // q tiles,      4KB/stage
    int sb = blockIdx.z, s = sb >> 2, h = sb & 3;
    int mband = blockIdx.x;
    int tid = threadIdx.x, wid = tid >> 5, lane = tid & 31;
    int wm = wid >> 2, wn = wid & 3;

    const __half* qb = g_q16 + (size_t)s * HID * T_ + (size_t)(h * C_) * T_
                       + mband * 128;
    const uint4* Bch = (const uint4*)(g_ctxp + (size_t)sb * 4096);

    int qrow = tid >> 4;          // 0..15 (k within tile)
    int qseg = tid & 15;          // 16B segment within 256B row
    uint32_t qdst_off = (uint32_t)(qrow * 256 + ((qseg ^ (qrow & 7)) << 4));

    auto issue = [&](int ks) {
        int st = ks % 3;
        cp16(&sB[st][tid], Bch + (size_t)ks * 256 + tid);
        cp16s(smem_u32(&sQ[st][0]) + qdst_off,
              qb + (size_t)(ks * 16 + qrow) * T_ + qseg * 8);
        cp_commit();
    };
    issue(0); issue(1);

    float acc[4][4][4] = {};
    for (int ks = 0; ks < 8; ks++) {
        if (ks + 1 < 8) cp_wait1(); else cp_wait0();
        __syncthreads();
        if (ks + 2 < 8) issue(ks + 2);

        uint32_t qt = smem_u32(&sQ[ks % 3][0]);
        uint4 a[4];
        #pragma unroll
        for (int i = 0; i < 4; i++) {
            int m0 = (wm * 4 + i) * 16;
            int r = (lane & 7) + ((lane & 16) ? 8 : 0);
            int c = m0 + ((lane & 8) ? 8 : 0);
            ldsm4t(a[i], qt + r * 256 + (((c >> 3) ^ (r & 7)) << 4));
        }
        const uint2* sbp = (const uint2*)&sB[ks % 3][0];
        #pragma unroll
        for (int j = 0; j < 4; j++) {
            uint2 bh = sbp[(wn * 4 + j) * 32 + lane];
            #pragma unroll
            for (int i = 0; i < 4; i++)
                mma_f16(acc[i][j], a[i], bh);
        }
    }

    uint2* dst = gB_att + (size_t)s * BATT_SLICE2;
    #pragma unroll
    for (int i = 0; i < 4; i++) {
        int nf0 = mband * 16 + wm * 8 + 2 * i;
        #pragma unroll
        for (int jp = 0; jp < 2; jp++) {
            int ks = h * 8 + wn * 2 + jp;
            store_hfrag_hi(dst, (size_t)ks * 1024, nf0, lane, acc[i][2 * jp], acc[i][2 * jp + 1]);
        }
    }
}

// ---------------------------------------------------------------------------
// temb
// ---------------------------------------------------------------------------
__global__ void k_temb(const float* __restrict__ time_in,
                       const float* __restrict__ w_time,
                       const float* __restrict__ b_time) {
    int s = blockIdx.x;
    int t = threadIdx.x;
    __shared__ float m[256];
    float v = time_in[(size_t)s * 256 + t];
    float sp = (v > 20.f) ? v : log1pf(__expf(v));
    m[t] = v * tanhf(sp);
    __syncthreads();

    int warp = t >> 5, lane = t & 31;
    for (int o = warp; o < OC3; o += 8) {
        const float* w = w_time + (size_t)o * 256;
        float acc = 0.f;
        #pragma unroll 4
        for (int e = lane; e < 256; e += 32) acc += m[e] * w[e];
        #pragma unroll
        for (int off = 16; off; off >>= 1) acc += __shfl_down_sync(0xffffffffu, acc, off);
        if (lane == 0) g_temb[(size_t)s * OC3 + o] = acc + b_time[o];
    }
}

// ---------------------------------------------------------------------------
extern "C" void kernel_launch(void* const* d_in, const int* in_sizes, int n_in,
                              void* d_out, int out_size) {
    (void)in_sizes; (void)n_in; (void)out_size;
    const float* x       = (const float*)d_in[0];
    const float* time_in = (const float*)d_in[1];
    const float* w_qkv   = (const float*)d_in[2];
    const float* w_time  = (const float*)d_in[3];
    const float* b_time  = (const float*)d_in[4];
    const float* w_out   = (const float*)d_in[5];
    const float* b_out   = (const float*)d_in[6];
    float* out = (float*)d_out;

    uint4* pA_qkv; cudaGetSymbolAddress((void**)&pA_qkv, gA_qkv);
    uint4* pA_out; cudaGetSymbolAddress((void**)&pA_out, gA_out);
    uint2* pB_x;   cudaGetSymbolAddress((void**)&pB_x,   gB_x);
    uint2* pB_att; cudaGetSymbolAddress((void**)&pB_att, gB_att);

    k_temb<<<S_, 256>>>(time_in, w_time, b_time);

    conv_A<<<192, 256>>>(w_qkv, F_, 16, pA_qkv);      // 96 row16-bands x 16 ks
    conv_A<<<64, 256>>>(w_out, HID, 32, pA_out);      // 16 row16-bands x 32 ks
    conv_Bd<<<dim3(64, S_), 256>>>(x, T_, 16, (size_t)F_ * T_, pB_x, (size_t)16 * 1024);

    k_qkv_mma<<<dim3(1, 24, S_), 256>>>(pA_qkv, (const uint4*)pB_x);

    k_ctx_mma<<<S_ * HEADS, 256>>>();
    k_applyT_mma<<<dim3(2, 1, S_ * HEADS), 256>>>();

    k_out_mma<<<dim3(1, 4, S_), 256>>>(pA_out, (const uint4*)pB_att, b_out, out);
}

// round 16
// speedup vs baseline: 1.7472x; 1.0445x over previous
#include <cuda_runtime.h>
#include <cuda_fp16.h>
#include <cstdint>
#include <math.h>

// Problem constants
#define B_   64
#define A_   8
#define S_   512
#define F_   256
#define T_   256
#define HID  512
#define OC3  1536
#define HEADS 4
#define C_   128

// ---------------------------------------------------------------------------
// Scratch
// ---------------------------------------------------------------------------
__device__ float  g_temb[(size_t)S_ * OC3];
__device__ __half g_q16 [(size_t)S_ * HID * T_];                 // q fp16 [s][d][t]
__device__ uint4  g_vp  [(size_t)S_ * HEADS * 4096];             // v packed A-frags (hi)
__device__ uint2  g_kp  [(size_t)S_ * HEADS * 8192];             // softmax(k) B-frags (hi only)
__device__ uint2  g_ctxp[(size_t)S_ * HEADS * 4096];             // ctx packed B-frags (hi only)

// prepacked operands
__device__ uint4 gA_qkv[(size_t)24 * 16 * 4 * 32];               // weights hi, [band64][ks][mf4][32]
__device__ uint4 gA_out[(size_t)4 * 32 * 4 * 32];
__device__ uint2 gB_x  [(size_t)S_ * 16 * 32 * 32];              // hi only [s][ks][nf32][32]
__device__ uint2 gB_att[(size_t)S_ * 32 * 32 * 32];              // hi only, written by applyT

#define BX_SLICE4   ((size_t)16 * 512)     // uint4 per slice (x frags, hi only)
#define BATT_SLICE4 ((size_t)16384)        // uint4 per slice (att frags, hi only)
#define BATT_SLICE2 ((size_t)32768)        // uint2 per slice

// ---------------------------------------------------------------------------
// helpers (fp16)
// ---------------------------------------------------------------------------
__device__ __forceinline__ unsigned hpack(float x, float y) {
    __half2 h = __floats2half2_rn(x, y);
    return *reinterpret_cast<unsigned*>(&h);
}
__device__ __forceinline__ void mma_f16(float* c, const uint4& a, const uint2& b) {
    asm volatile(
        "mma.sync.aligned.m16n8k16.row.col.f32.f16.f16.f32 "
        "{%0,%1,%2,%3}, {%4,%5,%6,%7}, {%8,%9}, {%0,%1,%2,%3};\n"
        : "+f"(c[0]), "+f"(c[1]), "+f"(c[2]), "+f"(c[3])
        : "r"(a.x), "r"(a.y), "r"(a.z), "r"(a.w), "r"(b.x), "r"(b.y));
}

// cp.async
__device__ __forceinline__ void cp16(uint4* smem, const uint4* gmem) {
    unsigned sa = (unsigned)__cvta_generic_to_shared(smem);
    asm volatile("cp.async.cg.shared.global [%0], [%1], 16;\n" :: "r"(sa), "l"(gmem));
}
__device__ __forceinline__ void cp16s(uint32_t saddr, const void* gmem) {
    asm volatile("cp.async.cg.shared.global [%0], [%1], 16;\n" :: "r"(saddr), "l"(gmem));
}
__device__ __forceinline__ void cp_commit() { asm volatile("cp.async.commit_group;\n" ::); }
__device__ __forceinline__ void cp_wait1()  { asm volatile("cp.async.wait_group 1;\n" ::: "memory"); }
__device__ __forceinline__ void cp_wait0()  { asm volatile("cp.async.wait_group 0;\n" ::: "memory"); }

__device__ __forceinline__ uint32_t smem_u32(const void* p) {
    return (uint32_t)__cvta_generic_to_shared(p);
}

// ldmatrix x4 transposed (b16): A-frag from [k][m] smem tile
__device__ __forceinline__ void ldsm4t(uint4& a, uint32_t addr) {
    asm volatile("ldmatrix.sync.aligned.m8n8.x4.trans.shared.b16 {%0,%1,%2,%3}, [%4];"
                 : "=r"(a.x), "=r"(a.y), "=r"(a.z), "=r"(a.w) : "r"(addr));
}

// hi-only store: B-frags packed densely [nf][32]
__device__ __forceinline__ void store_hfrag_hi(uint2* dst, size_t cb, int nf0, int lane,
                                               const float* a0, const float* a1) {
    dst[cb + (size_t)(nf0 + 0) * 32 + lane] =
        make_uint2(hpack(a0[0], a0[1]), hpack(a1[0], a1[1]));
    dst[cb + (size_t)(nf0 + 1) * 32 + lane] =
        make_uint2(hpack(a0[2], a0[3]), hpack(a1[2], a1[3]));
}

// ---------------------------------------------------------------------------
// conv_A: fp32 [M,K] row-major -> A-frags hi, layout [band64][ks][mf4][32]
// ---------------------------------------------------------------------------
__global__ void conv_A(const float* __restrict__ src, int lda, int Ksteps,
                       uint4* __restrict__ dst) {
    int wg   = blockIdx.x * 8 + (threadIdx.x >> 5);
    int lane = threadIdx.x & 31;
    int ks    = wg % Ksteps;
    int row16 = wg / Ksteps;
    int band64 = row16 >> 2, mf4 = row16 & 3;
    int g = lane >> 2, tc = (lane & 3) * 2;

    const float* p = src + (size_t)(row16 * 16 + g) * lda + ks * 16 + tc;
    float2 p00 = *(const float2*)p;
    float2 p01 = *(const float2*)(p + 8);
    float2 p10 = *(const float2*)(p + (size_t)8 * lda);
    float2 p11 = *(const float2*)(p + (size_t)8 * lda + 8);

    uint4 hi;
    hi.x = hpack(p00.x, p00.y);
    hi.y = hpack(p10.x, p10.y);
    hi.z = hpack(p01.x, p01.y);
    hi.w = hpack(p11.x, p11.y);
    dst[(((size_t)band64 * Ksteps + ks) * 4 + mf4) * 32 + lane] = hi;
}

// ---------------------------------------------------------------------------
// conv_Bd: fp32 [K,N=256] row-major (per slice) -> B-frags HI ONLY
// layout [ks][nf32][32]
// ---------------------------------------------------------------------------
__global__ void conv_Bd(const float* __restrict__ srcbase, int ldb, int Ksteps,
                        size_t src_slice_stride,
                        uint2* __restrict__ dstbase, size_t dst_slice_stride) {
    int s = blockIdx.y;
    const float* src = srcbase + (size_t)s * src_slice_stride;
    uint2* dst = dstbase + (size_t)s * dst_slice_stride;

    int wg   = blockIdx.x * 8 + (threadIdx.x >> 5);
    int lane = threadIdx.x & 31;
    int nf   = wg & 15;
    int ks   = (wg >> 4) % Ksteps;
    int band = wg / (16 * Ksteps);
    int g = lane >> 2, tc = (lane & 3) * 2;

    int nfg = band * 16 + nf;
    int n = nfg * 8 + g;
    const float* p = src + (size_t)(ks * 16 + tc) * ldb + n;
    float v0 = p[0];
    float v1 = p[(size_t)ldb];
    float v2 = p[(size_t)8 * ldb];
    float v3 = p[(size_t)9 * ldb];

    dst[((size_t)ks * 32 + nfg) * 32 + lane] =
        make_uint2(hpack(v0, v1), hpack(v2, v3));
}

// ---------------------------------------------------------------------------
// 64(M)x256(N) CTA tile GEMM core, warp tile 64x32, B hi-only (1 mma/frag)
// ---------------------------------------------------------------------------
__device__ __forceinline__ void gemm64x256(const uint4* __restrict__ Ach,
                                           const uint4* __restrict__ Bch,
                                           int Ksteps, float acc[4][4][4]) {
    __shared__ uint4 sA[3][128];
    __shared__ uint4 sB[3][512];
    int tid = threadIdx.x, wid = tid >> 5, lane = tid & 31;

    auto issue = [&](int ks) {
        int st = ks % 3;
        const uint4* A = Ach + (size_t)ks * 128;
        const uint4* B = Bch + (size_t)ks * 512;
        if (tid < 128) cp16(&sA[st][tid], A + tid);
        #pragma unroll
        for (int q = 0; q < 2; q++)
            cp16(&sB[st][tid + q * 256], B + tid + q * 256);
        cp_commit();
    };
    issue(0);
    issue(1);

    for (int ks = 0; ks < Ksteps; ks++) {
        if (ks + 1 < Ksteps) cp_wait1(); else cp_wait0();
        __syncthreads();
        if (ks + 2 < Ksteps) issue(ks + 2);
        const uint4* sa  = &sA[ks % 3][0];
        const uint2* sbp = (const uint2*)&sB[ks % 3][0];
        uint4 a[4];
        #pragma unroll
        for (int i = 0; i < 4; i++) a[i] = sa[i * 32 + lane];
        #pragma unroll
        for (int j = 0; j < 4; j++) {
            uint2 bh = sbp[(wid * 4 + j) * 32 + lane];
            #pragma unroll
            for (int i = 0; i < 4; i++)
                mma_f16(acc[i][j], a[i], bh);
        }
    }
}

// ---------------------------------------------------------------------------
// qkv GEMM: 24 bands of 64 rows x full t=256. B = x frags hi-only.
// ---------------------------------------------------------------------------
__global__ __launch_bounds__(256, 2)
void k_qkv_mma(const uint4* __restrict__ Ap, const uint4* __restrict__ Bx) {
    __shared__ float red[8][64];
    int s = blockIdx.z, band = blockIdx.y;
    const uint4* Ach = Ap + (size_t)band * 16 * 128;
    const uint4* Bch = Bx + (size_t)s * BX_SLICE4;

    float acc[4][4][4] = {};
    gemm64x256(Ach, Bch, 16, acc);

    int tid = threadIdx.x, wid = tid >> 5, lane = tid & 31;
    int g = lane >> 2, tc = (lane & 3) * 2;

    const float* te = g_temb + (size_t)s * OC3 + band * 64;
    float tv[4][2];
    #pragma unroll
    for (int i = 0; i < 4; i++) {
        tv[i][0] = te[i * 16 + g];
        tv[i][1] = te[i * 16 + 8 + g];
    }
    #pragma unroll
    for (int i = 0; i < 4; i++)
        #pragma unroll
        for (int j = 0; j < 4; j++) {
            acc[i][j][0] += tv[i][0]; acc[i][j][1] += tv[i][0];
            acc[i][j][2] += tv[i][1]; acc[i][j][3] += tv[i][1];
        }

    if (band < 8) {
        __half* gq = g_q16 + (size_t)s * HID * T_;
        #pragma unroll
        for (int i = 0; i < 4; i++) {
            int d = band * 64 + i * 16 + g;
            #pragma unroll
            for (int j = 0; j < 4; j++) {
                int t = wid * 32 + j * 8 + tc;
                *(__half2*)(gq + (size_t)d * T_ + t) =
                    __floats2half2_rn(acc[i][j][0], acc[i][j][1]);
                *(__half2*)(gq + (size_t)(d + 8) * T_ + t) =
                    __floats2half2_rn(acc[i][j][2], acc[i][j][3]);
            }
        }
    } else if (band < 16) {
        int kb = band - 8, h = kb >> 1, half = kb & 1;
        float mx[4][2];
        #pragma unroll
        for (int i = 0; i < 4; i++) { mx[i][0] = -1e30f; mx[i][1] = -1e30f; }
        #pragma unroll
        for (int i = 0; i < 4; i++)
            #pragma unroll
            for (int j = 0; j < 4; j++) {
                mx[i][0] = fmaxf(mx[i][0], fmaxf(acc[i][j][0], acc[i][j][1]));
                mx[i][1] = fmaxf(mx[i][1], fmaxf(acc[i][j][2], acc[i][j][3]));
            }
        #pragma unroll
        for (int i = 0; i < 4; i++)
            #pragma unroll
            for (int hh = 0; hh < 2; hh++) {
                mx[i][hh] = fmaxf(mx[i][hh], __shfl_xor_sync(0xffffffffu, mx[i][hh], 1));
                mx[i][hh] = fmaxf(mx[i][hh], __shfl_xor_sync(0xffffffffu, mx[i][hh], 2));
            }
        if ((lane & 3) == 0) {
            #pragma unroll
            for (int i = 0; i < 4; i++) {
                red[wid][i * 16 + g]     = mx[i][0];
                red[wid][i * 16 + 8 + g] = mx[i][1];
            }
        }
        __syncthreads();
        float MX[4][2];
        #pragma unroll
        for (int i = 0; i < 4; i++)
            #pragma unroll
            for (int hh = 0; hh < 2; hh++) {
                int r = i * 16 + hh * 8 + g;
                float m0 = fmaxf(fmaxf(red[0][r], red[1][r]), fmaxf(red[2][r], red[3][r]));
                float m1 = fmaxf(fmaxf(red[4][r], red[5][r]), fmaxf(red[6][r], red[7][r]));
                MX[i][hh] = fmaxf(m0, m1);
            }
        __syncthreads();
        float sm[4][2] = {};
        #pragma unroll
        for (int i = 0; i < 4; i++)
            #pragma unroll
            for (int j = 0; j < 4; j++) {
                acc[i][j][0] = __expf(acc[i][j][0] - MX[i][0]);
                acc[i][j][1] = __expf(acc[i][j][1] - MX[i][0]);
                acc[i][j][2] = __expf(acc[i][j][2] - MX[i][1]);
                acc[i][j][3] = __expf(acc[i][j][3] - MX[i][1]);
                sm[i][0] += acc[i][j][0] + acc[i][j][1];
                sm[i][1] += acc[i][j][2] + acc[i][j][3];
            }
        #pragma unroll
        for (int i = 0; i < 4; i++)
            #pragma unroll
            for (int hh = 0; hh < 2; hh++) {
                sm[i][hh] += __shfl_xor_sync(0xffffffffu, sm[i][hh], 1);
                sm[i][hh] += __shfl_xor_sync(0xffffffffu, sm[i][hh], 2);
            }
        if ((lane & 3) == 0) {
            #pragma unroll
            for (int i = 0; i < 4; i++) {
                red[wid][i * 16 + g]     = sm[i][0];
                red[wid][i * 16 + 8 + g] = sm[i][1];
            }
        }
        __syncthreads();
        float INV[4][2];
        #pragma unroll
        for (int i = 0; i < 4; i++)
            #pragma unroll
            for (int hh = 0; hh < 2; hh++) {
                int r = i * 16 + hh * 8 + g;
                INV[i][hh] = 1.f / (red[0][r] + red[1][r] + red[2][r] + red[3][r] +
                                    red[4][r] + red[5][r] + red[6][r] + red[7][r]);
            }
        // pack into ctx B-frags (hi only): [ks][nf16][32]
        uint2* dst = g_kp + ((size_t)s * HEADS + h) * 8192;
        #pragma unroll
        for (int i = 0; i < 4; i++) {
            int nf0 = half * 8 + i * 2;
            #pragma unroll
            for (int jp = 0; jp < 2; jp++) {
                int ks = wid * 2 + jp;
                float e0[4] = { acc[i][2*jp][0] * INV[i][0], acc[i][2*jp][1] * INV[i][0],
                                acc[i][2*jp][2] * INV[i][1], acc[i][2*jp][3] * INV[i][1] };
                float e1[4] = { acc[i][2*jp+1][0] * INV[i][0], acc[i][2*jp+1][1] * INV[i][0],
                                acc[i][2*jp+1][2] * INV[i][1], acc[i][2*jp+1][3] * INV[i][1] };
                store_hfrag_hi(dst, (size_t)ks * 512, nf0, lane, e0, e1);
            }
        }
    } else {
        int vb = band - 16, h = vb >> 1, half = vb & 1;
        uint4* dst = g_vp + ((size_t)s * HEADS + h) * 4096;
        #pragma unroll
        for (int i = 0; i < 4; i++) {
            int mf = half * 4 + i;
            #pragma unroll
            for (int jp = 0; jp < 2; jp++) {
                int ks = wid * 2 + jp;
                uint4 hi;
                hi.x = hpack(acc[i][2*jp][0],   acc[i][2*jp][1]);
                hi.y = hpack(acc[i][2*jp][2],   acc[i][2*jp][3]);
                hi.z = hpack(acc[i][2*jp+1][0], acc[i][2*jp+1][1]);
                hi.w = hpack(acc[i][2*jp+1][2], acc[i][2*jp+1][3]);
                dst[(size_t)ks * 256 + mf * 32 + lane] = hi;
            }
        }
    }
}

// ---------------------------------------------------------------------------
// out GEMM: 64x256 core (hi-only B), Ksteps=32, bias epilogue
// ---------------------------------------------------------------------------
__global__ __launch_bounds__(256, 2)
void k_out_mma(const uint4* __restrict__ Ap, const uint4* __restrict__ Bp,
               const float* __restrict__ bias, float* __restrict__ out) {
    int s = blockIdx.z, band = blockIdx.y;
    const uint4* Ach = Ap + (size_t)band * 32 * 128;
    const uint4* Bch = Bp + (size_t)s * BATT_SLICE4;

    float acc[4][4][4] = {};
    gemm64x256(Ach, Bch, 32, acc);

    int tid = threadIdx.x, wid = tid >> 5, lane = tid & 31;
    int g = lane >> 2, tc = (lane & 3) * 2;
    float* Co = out + (size_t)s * 256 * T_;

    #pragma unroll
    for (int i = 0; i < 4; i++) {
        int m = band * 64 + i * 16 + g;
        float b0 = bias[m], b1 = bias[m + 8];
        #pragma unroll
        for (int j = 0; j < 4; j++) {
            int n = wid * 32 + j * 8 + tc;
            *(float2*)(Co + (size_t)m * T_ + n) =
                make_float2(acc[i][j][0] + b0, acc[i][j][1] + b0);
            *(float2*)(Co + (size_t)(m + 8) * T_ + n) =
                make_float2(acc[i][j][2] + b1, acc[i][j][3] + b1);
        }
    }
}

// ---------------------------------------------------------------------------
// 128x128 prepacked mma core (8 warps 2x4, warp tile 64x32), B hi-only,
// 3-stage cp.async. A 256 uint4/kstep, B 256 uint4/kstep.
// ---------------------------------------------------------------------------
__device__ __forceinline__ void mma_tile3(const uint4* __restrict__ Ach,
                                          const uint4* __restrict__ Bch,
                                          int Ksteps, float acc[4][4][4]) {
    __shared__ uint4 sA[3][256];
    __shared__ uint4 sB[3][256];
    int tid = threadIdx.x, wid = tid >> 5, lane = tid & 31;
    int wm = wid >> 2, wn = wid & 3;

    auto issue = [&](int ks) {
        int st = ks % 3;
        cp16(&sA[st][tid], Ach + (size_t)ks * 256 + tid);
        cp16(&sB[st][tid], Bch + (size_t)ks * 256 + tid);
        cp_commit();
    };
    issue(0);
    issue(1);

    for (int ks = 0; ks < Ksteps; ks++) {
        if (ks + 1 < Ksteps) cp_wait1(); else cp_wait0();
        __syncthreads();
        if (ks + 2 < Ksteps) issue(ks + 2);
        const uint4* sa  = &sA[ks % 3][0];
        const uint2* sbp = (const uint2*)&sB[ks % 3][0];
        uint4 a[4];
        #pragma unroll
        for (int i = 0; i < 4; i++) a[i] = sa[(wm * 4 + i) * 32 + lane];
        #pragma unroll
        for (int j = 0; j < 4; j++) {
            uint2 bh = sbp[(wn * 4 + j) * 32 + lane];
            #pragma unroll
            for (int i = 0; i < 4; i++)
                mma_f16(acc[i][j], a[i], bh);
        }
    }
}

// ---------------------------------------------------------------------------
// ctx: ctxT[e][d] = sum_t v[e,t]*softmax(k)[d,t] — both operands prepacked hi
// epilogue -> g_ctxp packed B-frags (hi only)
// ---------------------------------------------------------------------------
__global__ __launch_bounds__(256, 2)
void k_ctx_mma() {
    int sb = blockIdx.x;
    const uint4* Vch = g_vp + (size_t)sb * 4096;
    const uint4* Kch = (const uint4*)(g_kp + (size_t)sb * 8192);

    float acc[4][4][4] = {};
    mma_tile3(Vch, Kch, 16, acc);

    int tid = threadIdx.x, wid = tid >> 5, lane = tid & 31;
    int wm = wid >> 2, wn = wid & 3;

    uint2* dst = g_ctxp + (size_t)sb * 4096;
    #pragma unroll
    for (int i = 0; i < 4; i++) {
        int nf0 = wm * 8 + 2 * i;
        #pragma unroll
        for (int jp = 0; jp < 2; jp++) {
            int ks = wn * 2 + jp;
            store_hfrag_hi(dst, (size_t)ks * 512, nf0, lane, acc[i][2 * jp], acc[i][2 * jp + 1]);
        }
    }
}

// ---------------------------------------------------------------------------
// applyT: attT[t][e] = sum_d q[d,t]*ctxT[e,d]
// A = q staged via cp.async + swizzled ldmatrix.trans; B = ctx frags hi-only.
// Epilogue -> gB_att packed B-frags (hi only)
// ---------------------------------------------------------------------------
__global__ __launch_bounds__(256, 2)
void k_applyT_mma() {
    __shared__ uint4 sB[3][256];     // ctx frags hi, 4KB/stage
    __shared__ uint4 sQ[3][256];     // q tiles,      4KB/stage
    int sb = blockIdx.z, s = sb >> 2, h = sb & 3;
    int mband = blockIdx.x;
    int tid = threadIdx.x, wid = tid >> 5, lane = tid & 31;
    int wm = wid >> 2, wn = wid & 3;

    const __half* qb = g_q16 + (size_t)s * HID * T_ + (size_t)(h * C_) * T_
                       + mband * 128;
    const uint4* Bch = (const uint4*)(g_ctxp + (size_t)sb * 4096);

    int qrow = tid >> 4;          // 0..15 (k within tile)
    int qseg = tid & 15;          // 16B segment within 256B row
    uint32_t qdst_off = (uint32_t)(qrow * 256 + ((qseg ^ (qrow & 7)) << 4));

    auto issue = [&](int ks) {
        int st = ks % 3;
        cp16(&sB[st][tid], Bch + (size_t)ks * 256 + tid);
        cp16s(smem_u32(&sQ[st][0]) + qdst_off,
              qb + (size_t)(ks * 16 + qrow) * T_ + qseg * 8);
        cp_commit();
    };
    issue(0); issue(1);

    float acc[4][4][4] = {};
    for (int ks = 0; ks < 8; ks++) {
        if (ks + 1 < 8) cp_wait1(); else cp_wait0();
        __syncthreads();
        if (ks + 2 < 8) issue(ks + 2);

        uint32_t qt = smem_u32(&sQ[ks % 3][0]);
        uint4 a[4];
        #pragma unroll
        for (int i = 0; i < 4; i++) {
            int m0 = (wm * 4 + i) * 16;
            int r = (lane & 7) + ((lane & 16) ? 8 : 0);
            int c = m0 + ((lane & 8) ? 8 : 0);
            ldsm4t(a[i], qt + r * 256 + (((c >> 3) ^ (r & 7)) << 4));
        }
        const uint2* sbp = (const uint2*)&sB[ks % 3][0];
        #pragma unroll
        for (int j = 0; j < 4; j++) {
            uint2 bh = sbp[(wn * 4 + j) * 32 + lane];
            #pragma unroll
            for (int i = 0; i < 4; i++)
                mma_f16(acc[i][j], a[i], bh);
        }
    }

    uint2* dst = gB_att + (size_t)s * BATT_SLICE2;
    #pragma unroll
    for (int i = 0; i < 4; i++) {
        int nf0 = mband * 16 + wm * 8 + 2 * i;
        #pragma unroll
        for (int jp = 0; jp < 2; jp++) {
            int ks = h * 8 + wn * 2 + jp;
            store_hfrag_hi(dst, (size_t)ks * 1024, nf0, lane, acc[i][2 * jp], acc[i][2 * jp + 1]);
        }
    }
}

// ---------------------------------------------------------------------------
// temb
// ---------------------------------------------------------------------------
__global__ void k_temb(const float* __restrict__ time_in,
                       const float* __restrict__ w_time,
                       const float* __restrict__ b_time) {
    int s = blockIdx.x;
    int t = threadIdx.x;
    __shared__ float m[256];
    float v = time_in[(size_t)s * 256 + t];
    float sp = (v > 20.f) ? v : log1pf(__expf(v));
    m[t] = v * tanhf(sp);
    __syncthreads();

    int warp = t >> 5, lane = t & 31;
    for (int o = warp; o < OC3; o += 8) {
        const float* w = w_time + (size_t)o * 256;
        float acc = 0.f;
        #pragma unroll 4
        for (int e = lane; e < 256; e += 32) acc += m[e] * w[e];
        #pragma unroll
        for (int off = 16; off; off >>= 1) acc += __shfl_down_sync(0xffffffffu, acc, off);
        if (lane == 0) g_temb[(size_t)s * OC3 + o] = acc + b_time[o];
    }
}

// ---------------------------------------------------------------------------
extern "C" void kernel_launch(void* const* d_in, const int* in_sizes, int n_in,
                              void* d_out, int out_size) {
    (void)in_sizes; (void)n_in; (void)out_size;
    const float* x       = (const float*)d_in[0];
    const float* time_in = (const float*)d_in[1];
    const float* w_qkv   = (const float*)d_in[2];
    const float* w_time  = (const float*)d_in[3];
    const float* b_time  = (const float*)d_in[4];
    const float* w_out   = (const float*)d_in[5];
    const float* b_out   = (const float*)d_in[6];
    float* out = (float*)d_out;

    uint4* pA_qkv; cudaGetSymbolAddress((void**)&pA_qkv, gA_qkv);
    uint4* pA_out; cudaGetSymbolAddress((void**)&pA_out, gA_out);
    uint2* pB_x;   cudaGetSymbolAddress((void**)&pB_x,   gB_x);
    uint2* pB_att; cudaGetSymbolAddress((void**)&pB_att, gB_att);

    k_temb<<<S_, 256>>>(time_in, w_time, b_time);

    conv_A<<<192, 256>>>(w_qkv, F_, 16, pA_qkv);      // 96 row16-bands x 16 ks
    conv_A<<<64, 256>>>(w_out, HID, 32, pA_out);      // 16 row16-bands x 32 ks
    conv_Bd<<<dim3(64, S_), 256>>>(x, T_, 16, (size_t)F_ * T_, pB_x, (size_t)16 * 1024);

    k_qkv_mma<<<dim3(1, 24, S_), 256>>>(pA_qkv, (const uint4*)pB_x);

    k_ctx_mma<<<S_ * HEADS, 256>>>();
    k_applyT_mma<<<dim3(2, 1, S_ * HEADS), 256>>>();

    k_out_mma<<<dim3(1, 4, S_), 256>>>(pA_out, (const uint4*)pB_att, b_out, out);
}

// round 17
// speedup vs baseline: 1.8556x; 1.0621x over previous
#include <cuda_runtime.h>
#include <cuda_fp16.h>
#include <cstdint>
#include <math.h>

// Problem constants
#define B_   64
#define A_   8
#define S_   512
#define F_   256
#define T_   256
#define HID  512
#define OC3  1536
#define HEADS 4
#define C_   128

// ---------------------------------------------------------------------------
// Scratch
// ---------------------------------------------------------------------------
__device__ float  g_temb[(size_t)S_ * OC3];
__device__ __half g_q16 [(size_t)S_ * HID * T_];                 // q fp16 [s][d][t]
__device__ uint4  g_vp  [(size_t)S_ * HEADS * 4096];             // v packed A-frags (hi)
__device__ uint2  g_kp  [(size_t)S_ * HEADS * 8192];             // softmax(k) B-frags (hi only)
__device__ uint2  g_ctxp[(size_t)S_ * HEADS * 4096];             // ctx packed B-frags (hi only)

// prepacked operands
__device__ uint4 gA_qkv[(size_t)24 * 16 * 4 * 32];               // weights hi, [band64][ks][mf4][32]
__device__ uint4 gA_out[(size_t)4 * 32 * 4 * 32];
__device__ uint2 gB_x  [(size_t)S_ * 16 * 32 * 32];              // hi only [s][ks][nf32][32]
__device__ uint2 gB_att[(size_t)S_ * 32 * 32 * 32];              // hi only, written by applyT

#define BX_SLICE4   ((size_t)16 * 512)     // uint4 per slice (x frags, hi only)
#define BATT_SLICE4 ((size_t)16384)        // uint4 per slice (att frags, hi only)
#define BATT_SLICE2 ((size_t)32768)        // uint2 per slice

#define GEMM_SMEM 61440                    // 3 stages x (4KB A + 16KB B)

// ---------------------------------------------------------------------------
// helpers (fp16)
// ---------------------------------------------------------------------------
__device__ __forceinline__ unsigned hpack(float x, float y) {
    __half2 h = __floats2half2_rn(x, y);
    return *reinterpret_cast<unsigned*>(&h);
}
__device__ __forceinline__ void mma_f16(float* c, const uint4& a, const uint2& b) {
    asm volatile(
        "mma.sync.aligned.m16n8k16.row.col.f32.f16.f16.f32 "
        "{%0,%1,%2,%3}, {%4,%5,%6,%7}, {%8,%9}, {%0,%1,%2,%3};\n"
        : "+f"(c[0]), "+f"(c[1]), "+f"(c[2]), "+f"(c[3])
        : "r"(a.x), "r"(a.y), "r"(a.z), "r"(a.w), "r"(b.x), "r"(b.y));
}

// cp.async
__device__ __forceinline__ void cp16(uint4* smem, const uint4* gmem) {
    unsigned sa = (unsigned)__cvta_generic_to_shared(smem);
    asm volatile("cp.async.cg.shared.global [%0], [%1], 16;\n" :: "r"(sa), "l"(gmem));
}
__device__ __forceinline__ void cp16s(uint32_t saddr, const void* gmem) {
    asm volatile("cp.async.cg.shared.global [%0], [%1], 16;\n" :: "r"(saddr), "l"(gmem));
}
__device__ __forceinline__ void cp_commit() { asm volatile("cp.async.commit_group;\n" ::); }
__device__ __forceinline__ void cp_wait1()  { asm volatile("cp.async.wait_group 1;\n" ::: "memory"); }
__device__ __forceinline__ void cp_wait0()  { asm volatile("cp.async.wait_group 0;\n" ::: "memory"); }

__device__ __forceinline__ uint32_t smem_u32(const void* p) {
    return (uint32_t)__cvta_generic_to_shared(p);
}

// ldmatrix x4 transposed (b16): A-frag from [k][m] smem tile
__device__ __forceinline__ void ldsm4t(uint4& a, uint32_t addr) {
    asm volatile("ldmatrix.sync.aligned.m8n8.x4.trans.shared.b16 {%0,%1,%2,%3}, [%4];"
                 : "=r"(a.x), "=r"(a.y), "=r"(a.z), "=r"(a.w) : "r"(addr));
}

// hi-only store: B-frags packed densely [nf][32]
__device__ __forceinline__ void store_hfrag_hi(uint2* dst, size_t cb, int nf0, int lane,
                                               const float* a0, const float* a1) {
    dst[cb + (size_t)(nf0 + 0) * 32 + lane] =
        make_uint2(hpack(a0[0], a0[1]), hpack(a1[0], a1[1]));
    dst[cb + (size_t)(nf0 + 1) * 32 + lane] =
        make_uint2(hpack(a0[2], a0[3]), hpack(a1[2], a1[3]));
}

// ---------------------------------------------------------------------------
// conv_A: fp32 [M,K] row-major -> A-frags hi, layout [band64][ks][mf4][32]
// ---------------------------------------------------------------------------
__global__ void conv_A(const float* __restrict__ src, int lda, int Ksteps,
                       uint4* __restrict__ dst) {
    int wg   = blockIdx.x * 8 + (threadIdx.x >> 5);
    int lane = threadIdx.x & 31;
    int ks    = wg % Ksteps;
    int row16 = wg / Ksteps;
    int band64 = row16 >> 2, mf4 = row16 & 3;
    int g = lane >> 2, tc = (lane & 3) * 2;

    const float* p = src + (size_t)(row16 * 16 + g) * lda + ks * 16 + tc;
    float2 p00 = *(const float2*)p;
    float2 p01 = *(const float2*)(p + 8);
    float2 p10 = *(const float2*)(p + (size_t)8 * lda);
    float2 p11 = *(const float2*)(p + (size_t)8 * lda + 8);

    uint4 hi;
    hi.x = hpack(p00.x, p00.y);
    hi.y = hpack(p10.x, p10.y);
    hi.z = hpack(p01.x, p01.y);
    hi.w = hpack(p11.x, p11.y);
    dst[(((size_t)band64 * Ksteps + ks) * 4 + mf4) * 32 + lane] = hi;
}

// ---------------------------------------------------------------------------
// conv_Bd: fp32 [K,N=256] row-major (per slice) -> B-frags HI ONLY
// layout [ks][nf32][32]
// ---------------------------------------------------------------------------
__global__ void conv_Bd(const float* __restrict__ srcbase, int ldb, int Ksteps,
                        size_t src_slice_stride,
                        uint2* __restrict__ dstbase, size_t dst_slice_stride) {
    int s = blockIdx.y;
    const float* src = srcbase + (size_t)s * src_slice_stride;
    uint2* dst = dstbase + (size_t)s * dst_slice_stride;

    int wg   = blockIdx.x * 8 + (threadIdx.x >> 5);
    int lane = threadIdx.x & 31;
    int nf   = wg & 15;
    int ks   = (wg >> 4) % Ksteps;
    int band = wg / (16 * Ksteps);
    int g = lane >> 2, tc = (lane & 3) * 2;

    int nfg = band * 16 + nf;
    int n = nfg * 8 + g;
    const float* p = src + (size_t)(ks * 16 + tc) * ldb + n;
    float v0 = p[0];
    float v1 = p[(size_t)ldb];
    float v2 = p[(size_t)8 * ldb];
    float v3 = p[(size_t)9 * ldb];

    dst[((size_t)ks * 32 + nfg) * 32 + lane] =
        make_uint2(hpack(v0, v1), hpack(v2, v3));
}

// ---------------------------------------------------------------------------
// 64(M)x256(N) CTA tile GEMM core, warp tile 64x32, B hi-only.
// 3-stage cp.async pipeline, 2 ksteps per stage (dynamic smem, 60KB).
// ---------------------------------------------------------------------------
__device__ __forceinline__ void gemm64x256(char* dsm,
                                           const uint4* __restrict__ Ach,
                                           const uint4* __restrict__ Bch,
                                           int Kpairs, float acc[4][4][4]) {
    uint4* sA = (uint4*)dsm;                 // 3 * 256 uint4 (2 ksteps/stage)
    uint4* sB = (uint4*)(dsm + 12288);       // 3 * 1024 uint4
    int tid = threadIdx.x, wid = tid >> 5, lane = tid & 31;

    auto issue = [&](int p) {
        int st = p % 3;
        cp16(&sA[st * 256 + tid], Ach + (size_t)p * 256 + tid);
        const uint4* B = Bch + (size_t)p * 1024;
        #pragma unroll
        for (int q = 0; q < 4; q++)
            cp16(&sB[st * 1024 + tid + q * 256], B + tid + q * 256);
        cp_commit();
    };
    issue(0);
    issue(1);

    for (int p = 0; p < Kpairs; p++) {
        if (p + 1 < Kpairs) cp_wait1(); else cp_wait0();
        __syncthreads();
        if (p + 2 < Kpairs) issue(p + 2);
        int st = p % 3;
        #pragma unroll
        for (int sub = 0; sub < 2; sub++) {
            const uint4* sa  = &sA[st * 256 + sub * 128];
            const uint2* sbp = (const uint2*)&sB[st * 1024 + sub * 512];
            uint4 a[4];
            #pragma unroll
            for (int i = 0; i < 4; i++) a[i] = sa[i * 32 + lane];
            #pragma unroll
            for (int j = 0; j < 4; j++) {
                uint2 bh = sbp[(wid * 4 + j) * 32 + lane];
                #pragma unroll
                for (int i = 0; i < 4; i++)
                    mma_f16(acc[i][j], a[i], bh);
            }
        }
    }
}

// ---------------------------------------------------------------------------
// qkv GEMM: 24 bands of 64 rows x full t=256. B = x frags hi-only.
// ---------------------------------------------------------------------------
__global__ __launch_bounds__(256, 2)
void k_qkv_mma(const uint4* __restrict__ Ap, const uint4* __restrict__ Bx) {
    extern __shared__ char dsm[];
    __shared__ float red[8][64];
    int s = blockIdx.z, band = blockIdx.y;
    const uint4* Ach = Ap + (size_t)band * 16 * 128;
    const uint4* Bch = Bx + (size_t)s * BX_SLICE4;

    float acc[4][4][4] = {};
    gemm64x256(dsm, Ach, Bch, 8, acc);

    int tid = threadIdx.x, wid = tid >> 5, lane = tid & 31;
    int g = lane >> 2, tc = (lane & 3) * 2;

    const float* te = g_temb + (size_t)s * OC3 + band * 64;
    float tv[4][2];
    #pragma unroll
    for (int i = 0; i < 4; i++) {
        tv[i][0] = te[i * 16 + g];
        tv[i][1] = te[i * 16 + 8 + g];
    }
    #pragma unroll
    for (int i = 0; i < 4; i++)
        #pragma unroll
        for (int j = 0; j < 4; j++) {
            acc[i][j][0] += tv[i][0]; acc[i][j][1] += tv[i][0];
            acc[i][j][2] += tv[i][1]; acc[i][j][3] += tv[i][1];
        }

    if (band < 8) {
        __half* gq = g_q16 + (size_t)s * HID * T_;
        #pragma unroll
        for (int i = 0; i < 4; i++) {
            int d = band * 64 + i * 16 + g;
            #pragma unroll
            for (int j = 0; j < 4; j++) {
                int t = wid * 32 + j * 8 + tc;
                *(__half2*)(gq + (size_t)d * T_ + t) =
                    __floats2half2_rn(acc[i][j][0], acc[i][j][1]);
                *(__half2*)(gq + (size_t)(d + 8) * T_ + t) =
                    __floats2half2_rn(acc[i][j][2], acc[i][j][3]);
            }
        }
    } else if (band < 16) {
        int kb = band - 8, h = kb >> 1, half = kb & 1;
        float mx[4][2];
        #pragma unroll
        for (int i = 0; i < 4; i++) { mx[i][0] = -1e30f; mx[i][1] = -1e30f; }
        #pragma unroll
        for (int i = 0; i < 4; i++)
            #pragma unroll
            for (int j = 0; j < 4; j++) {
                mx[i][0] = fmaxf(mx[i][0], fmaxf(acc[i][j][0], acc[i][j][1]));
                mx[i][1] = fmaxf(mx[i][1], fmaxf(acc[i][j][2], acc[i][j][3]));
            }
        #pragma unroll
        for (int i = 0; i < 4; i++)
            #pragma unroll
            for (int hh = 0; hh < 2; hh++) {
                mx[i][hh] = fmaxf(mx[i][hh], __shfl_xor_sync(0xffffffffu, mx[i][hh], 1));
                mx[i][hh] = fmaxf(mx[i][hh], __shfl_xor_sync(0xffffffffu, mx[i][hh], 2));
            }
        if ((lane & 3) == 0) {
            #pragma unroll
            for (int i = 0; i < 4; i++) {
                red[wid][i * 16 + g]     = mx[i][0];
                red[wid][i * 16 + 8 + g] = mx[i][1];
            }
        }
        __syncthreads();
        float MX[4][2];
        #pragma unroll
        for (int i = 0; i < 4; i++)
            #pragma unroll
            for (int hh = 0; hh < 2; hh++) {
                int r = i * 16 + hh * 8 + g;
                float m0 = fmaxf(fmaxf(red[0][r], red[1][r]), fmaxf(red[2][r], red[3][r]));
                float m1 = fmaxf(fmaxf(red[4][r], red[5][r]), fmaxf(red[6][r], red[7][r]));
                MX[i][hh] = fmaxf(m0, m1);
            }
        __syncthreads();
        float sm[4][2] = {};
        #pragma unroll
        for (int i = 0; i < 4; i++)
            #pragma unroll
            for (int j = 0; j < 4; j++) {
                acc[i][j][0] = __expf(acc[i][j][0] - MX[i][0]);
                acc[i][j][1] = __expf(acc[i][j][1] - MX[i][0]);
                acc[i][j][2] = __expf(acc[i][j][2] - MX[i][1]);
                acc[i][j][3] = __expf(acc[i][j][3] - MX[i][1]);
                sm[i][0] += acc[i][j][0] + acc[i][j][1];
                sm[i][1] += acc[i][j][2] + acc[i][j][3];
            }
        #pragma unroll
        for (int i = 0; i < 4; i++)
            #pragma unroll
            for (int hh = 0; hh < 2; hh++) {
                sm[i][hh] += __shfl_xor_sync(0xffffffffu, sm[i][hh], 1);
                sm[i][hh] += __shfl_xor_sync(0xffffffffu, sm[i][hh], 2);
            }
        if ((lane & 3) == 0) {
            #pragma unroll
            for (int i = 0; i < 4; i++) {
                red[wid][i * 16 + g]     = sm[i][0];
                red[wid][i * 16 + 8 + g] = sm[i][1];
            }
        }
        __syncthreads();
        float INV[4][2];
        #pragma unroll
        for (int i = 0; i < 4; i++)
            #pragma unroll
            for (int hh = 0; hh < 2; hh++) {
                int r = i * 16 + hh * 8 + g;
                INV[i][hh] = 1.f / (red[0][r] + red[1][r] + red[2][r] + red[3][r] +
                                    red[4][r] + red[5][r] + red[6][r] + red[7][r]);
            }
        uint2* dst = g_kp + ((size_t)s * HEADS + h) * 8192;
        #pragma unroll
        for (int i = 0; i < 4; i++) {
            int nf0 = half * 8 + i * 2;
            #pragma unroll
            for (int jp = 0; jp < 2; jp++) {
                int ks = wid * 2 + jp;
                float e0[4] = { acc[i][2*jp][0] * INV[i][0], acc[i][2*jp][1] * INV[i][0],
                                acc[i][2*jp][2] * INV[i][1], acc[i][2*jp][3] * INV[i][1] };
                float e1[4] = { acc[i][2*jp+1][0] * INV[i][0], acc[i][2*jp+1][1] * INV[i][0],
                                acc[i][2*jp+1][2] * INV[i][1], acc[i][2*jp+1][3] * INV[i][1] };
                store_hfrag_hi(dst, (size_t)ks * 512, nf0, lane, e0, e1);
            }
        }
    } else {
        int vb = band - 16, h = vb >> 1, half = vb & 1;
        uint4* dst = g_vp + ((size_t)s * HEADS + h) * 4096;
        #pragma unroll
        for (int i = 0; i < 4; i++) {
            int mf = half * 4 + i;
            #pragma unroll
            for (int jp = 0; jp < 2; jp++) {
                int ks = wid * 2 + jp;
                uint4 hi;
                hi.x = hpack(acc[i][2*jp][0],   acc[i][2*jp][1]);
                hi.y = hpack(acc[i][2*jp][2],   acc[i][2*jp][3]);
                hi.z = hpack(acc[i][2*jp+1][0], acc[i][2*jp+1][1]);
                hi.w = hpack(acc[i][2*jp+1][2], acc[i][2*jp+1][3]);
                dst[(size_t)ks * 256 + mf * 32 + lane] = hi;
            }
        }
    }
}

// ---------------------------------------------------------------------------
// out GEMM: 64x256 core (hi-only B), 16 kstep-pairs, bias epilogue
// ---------------------------------------------------------------------------
__global__ __launch_bounds__(256, 2)
void k_out_mma(const uint4* __restrict__ Ap, const uint4* __restrict__ Bp,
               const float* __restrict__ bias, float* __restrict__ out) {
    extern __shared__ char dsm[];
    int s = blockIdx.z, band = blockIdx.y;
    const uint4* Ach = Ap + (size_t)band * 32 * 128;
    const uint4* Bch = Bp + (size_t)s * BATT_SLICE4;

    float acc[4][4][4] = {};
    gemm64x256(dsm, Ach, Bch, 16, acc);

    int tid = threadIdx.x, wid = tid >> 5, lane = tid & 31;
    int g = lane >> 2, tc = (lane & 3) * 2;
    float* Co = out + (size_t)s * 256 * T_;

    #pragma unroll
    for (int i = 0; i < 4; i++) {
        int m = band * 64 + i * 16 + g;
        float b0 = bias[m], b1 = bias[m + 8];
        #pragma unroll
        for (int j = 0; j < 4; j++) {
            int n = wid * 32 + j * 8 + tc;
            *(float2*)(Co + (size_t)m * T_ + n) =
                make_float2(acc[i][j][0] + b0, acc[i][j][1] + b0);
            *(float2*)(Co + (size_t)(m + 8) * T_ + n) =
                make_float2(acc[i][j][2] + b1, acc[i][j][3] + b1);
        }
    }
}

// ---------------------------------------------------------------------------
// 128x128 prepacked mma core (8 warps 2x4, warp tile 64x32), B hi-only,
// 3-stage cp.async. A 256 uint4/kstep, B 256 uint4/kstep.
// ---------------------------------------------------------------------------
__device__ __forceinline__ void mma_tile3(const uint4* __restrict__ Ach,
                                          const uint4* __restrict__ Bch,
                                          int Ksteps, float acc[4][4][4]) {
    __shared__ uint4 sA[3][256];
    __shared__ uint4 sB[3][256];
    int tid = threadIdx.x, wid = tid >> 5, lane = tid & 31;
    int wm = wid >> 2, wn = wid & 3;

    auto issue = [&](int ks) {
        int st = ks % 3;
        cp16(&sA[st][tid], Ach + (size_t)ks * 256 + tid);
        cp16(&sB[st][tid], Bch + (size_t)ks * 256 + tid);
        cp_commit();
    };
    issue(0);
    issue(1);

    for (int ks = 0; ks < Ksteps; ks++) {
        if (ks + 1 < Ksteps) cp_wait1(); else cp_wait0();
        __syncthreads();
        if (ks + 2 < Ksteps) issue(ks + 2);
        const uint4* sa  = &sA[ks % 3][0];
        const uint2* sbp = (const uint2*)&sB[ks % 3][0];
        uint4 a[4];
        #pragma unroll
        for (int i = 0; i < 4; i++) a[i] = sa[(wm * 4 + i) * 32 + lane];
        #pragma unroll
        for (int j = 0; j < 4; j++) {
            uint2 bh = sbp[(wn * 4 + j) * 32 + lane];
            #pragma unroll
            for (int i = 0; i < 4; i++)
                mma_f16(acc[i][j], a[i], bh);
        }
    }
}

// ---------------------------------------------------------------------------
// ctx: ctxT[e][d] = sum_t v[e,t]*softmax(k)[d,t] — both operands prepacked hi
// epilogue -> g_ctxp packed B-frags (hi only)
// ---------------------------------------------------------------------------
__global__ __launch_bounds__(256, 2)
void k_ctx_mma() {
    int sb = blockIdx.x;
    const uint4* Vch = g_vp + (size_t)sb * 4096;
    const uint4* Kch = (const uint4*)(g_kp + (size_t)sb * 8192);

    float acc[4][4][4] = {};
    mma_tile3(Vch, Kch, 16, acc);

    int tid = threadIdx.x, wid = tid >> 5, lane = tid & 31;
    int wm = wid >> 2, wn = wid & 3;

    uint2* dst = g_ctxp + (size_t)sb * 4096;
    #pragma unroll
    for (int i = 0; i < 4; i++) {
        int nf0 = wm * 8 + 2 * i;
        #pragma unroll
        for (int jp = 0; jp < 2; jp++) {
            int ks = wn * 2 + jp;
            store_hfrag_hi(dst, (size_t)ks * 512, nf0, lane, acc[i][2 * jp], acc[i][2 * jp + 1]);
        }
    }
}

// ---------------------------------------------------------------------------
// applyT: attT[t][e] = sum_d q[d,t]*ctxT[e,d]
// A = q staged via cp.async + swizzled ldmatrix.trans; B = ctx frags hi-only.
// Epilogue -> gB_att packed B-frags (hi only)
// ---------------------------------------------------------------------------
__global__ __launch_bounds__(256, 2)
void k_applyT_mma() {
    __shared__ uint4 sB[3][256];     // ctx frags hi, 4KB/stage
    __shared__ uint4 sQ[3][256];     // q tiles,      4KB/stage
    int sb = blockIdx.z, s = sb >> 2, h = sb & 3;
    int mband = blockIdx.x;
    int tid = threadIdx.x, wid = tid >> 5, lane = tid & 31;
    int wm = wid >> 2, wn = wid & 3;

    const __half* qb = g_q16 + (size_t)s * HID * T_ + (size_t)(h * C_) * T_
                       + mband * 128;
    const uint4* Bch = (const uint4*)(g_ctxp + (size_t)sb * 4096);

    int qrow = tid >> 4;          // 0..15 (k within tile)
    int qseg = tid & 15;          // 16B segment within 256B row
    uint32_t qdst_off = (uint32_t)(qrow * 256 + ((qseg ^ (qrow & 7)) << 4));

    auto issue = [&](int ks) {
        int st = ks % 3;
        cp16(&sB[st][tid], Bch + (size_t)ks * 256 + tid);
        cp16s(smem_u32(&sQ[st][0]) + qdst_off,
              qb + (size_t)(ks * 16 + qrow) * T_ + qseg * 8);
        cp_commit();
    };
    issue(0); issue(1);

    float acc[4][4][4] = {};
    for (int ks = 0; ks < 8; ks++) {
        if (ks + 1 < 8) cp_wait1(); else cp_wait0();
        __syncthreads();
        if (ks + 2 < 8) issue(ks + 2);

        uint32_t qt = smem_u32(&sQ[ks % 3][0]);
        uint4 a[4];
        #pragma unroll
        for (int i = 0; i < 4; i++) {
            int m0 = (wm * 4 + i) * 16;
            int r = (lane & 7) + ((lane & 16) ? 8 : 0);
            int c = m0 + ((lane & 8) ? 8 : 0);
            ldsm4t(a[i], qt + r * 256 + (((c >> 3) ^ (r & 7)) << 4));
        }
        const uint2* sbp = (const uint2*)&sB[ks % 3][0];
        #pragma unroll
        for (int j = 0; j < 4; j++) {
            uint2 bh = sbp[(wn * 4 + j) * 32 + lane];
            #pragma unroll
            for (int i = 0; i < 4; i++)
                mma_f16(acc[i][j], a[i], bh);
        }
    }

    uint2* dst = gB_att + (size_t)s * BATT_SLICE2;
    #pragma unroll
    for (int i = 0; i < 4; i++) {
        int nf0 = mband * 16 + wm * 8 + 2 * i;
        #pragma unroll
        for (int jp = 0; jp < 2; jp++) {
            int ks = h * 8 + wn * 2 + jp;
            store_hfrag_hi(dst, (size_t)ks * 1024, nf0, lane, acc[i][2 * jp], acc[i][2 * jp + 1]);
        }
    }
}

// ---------------------------------------------------------------------------
// temb
// ---------------------------------------------------------------------------
__global__ void k_temb(const float* __restrict__ time_in,
                       const float* __restrict__ w_time,
                       const float* __restrict__ b_time) {
    int s = blockIdx.x;
    int t = threadIdx.x;
    __shared__ float m[256];
    float v = time_in[(size_t)s * 256 + t];
    float sp = (v > 20.f) ? v : log1pf(__expf(v));
    m[t] = v * tanhf(sp);
    __syncthreads();

    int warp = t >> 5, lane = t & 31;
    for (int o = warp; o < OC3; o += 8) {
        const float* w = w_time + (size_t)o * 256;
        float acc = 0.f;
        #pragma unroll 4
        for (int e = lane; e < 256; e += 32) acc += m[e] * w[e];
        #pragma unroll
        for (int off = 16; off; off >>= 1) acc += __shfl_down_sync(0xffffffffu, acc, off);
        if (lane == 0) g_temb[(size_t)s * OC3 + o] = acc + b_time[o];
    }
}

// ---------------------------------------------------------------------------
extern "C" void kernel_launch(void* const* d_in, const int* in_sizes, int n_in,
                              void* d_out, int out_size) {
    (void)in_sizes; (void)n_in; (void)out_size;
    const float* x       = (const float*)d_in[0];
    const float* time_in = (const float*)d_in[1];
    const float* w_qkv   = (const float*)d_in[2];
    const float* w_time  = (const float*)d_in[3];
    const float* b_time  = (const float*)d_in[4];
    const float* w_out   = (const float*)d_in[5];
    const float* b_out   = (const float*)d_in[6];
    float* out = (float*)d_out;

    uint4* pA_qkv; cudaGetSymbolAddress((void**)&pA_qkv, gA_qkv);
    uint4* pA_out; cudaGetSymbolAddress((void**)&pA_out, gA_out);
    uint2* pB_x;   cudaGetSymbolAddress((void**)&pB_x,   gB_x);
    uint2* pB_att; cudaGetSymbolAddress((void**)&pB_att, gB_att);

    cudaFuncSetAttribute(k_qkv_mma, cudaFuncAttributeMaxDynamicSharedMemorySize, GEMM_SMEM);
    cudaFuncSetAttribute(k_out_mma, cudaFuncAttributeMaxDynamicSharedMemorySize, GEMM_SMEM);

    k_temb<<<S_, 256>>>(time_in, w_time, b_time);

    conv_A<<<192, 256>>>(w_qkv, F_, 16, pA_qkv);      // 96 row16-bands x 16 ks
    conv_A<<<64, 256>>>(w_out, HID, 32, pA_out);      // 16 row16-bands x 32 ks
    conv_Bd<<<dim3(64, S_), 256>>>(x, T_, 16, (size_t)F_ * T_, pB_x, (size_t)16 * 1024);

    k_qkv_mma<<<dim3(1, 24, S_), 256, GEMM_SMEM>>>(pA_qkv, (const uint4*)pB_x);

    k_ctx_mma<<<S_ * HEADS, 256>>>();
    k_applyT_mma<<<dim3(2, 1, S_ * HEADS), 256>>>();

    k_out_mma<<<dim3(1, 4, S_), 256, GEMM_SMEM>>>(pA_out, (const uint4*)pB_att, b_out, out);
}